// round 9
// baseline (speedup 1.0000x reference)
#include <cuda_runtime.h>
#include <cuda_bf16.h>
#include <math.h>
#include <stdint.h>

// ---------------------------------------------------------------- constants
#define B_    2
#define S_    2048
#define H_    32
#define D_    128
#define DIM_  4096
#define ADL_  10
#define MROWS (B_ * S_)
#define NELEM ((size_t)MROWS * DIM_)

// ---------------------------------------------------------------- scratch
__device__ float g_aK[ADL_ * DIM_];
__device__ float g_aV[ADL_ * DIM_];

__device__ __nv_bfloat16 g_xh[NELEM],  g_xl[NELEM];
__device__ __nv_bfloat16 g_wqh[NELEM], g_wql[NELEM];
__device__ __nv_bfloat16 g_wkh[NELEM], g_wkl[NELEM];
__device__ __nv_bfloat16 g_wvh[NELEM], g_wvl[NELEM];
__device__ __nv_bfloat16 g_woh[NELEM], g_wol[NELEM];
__device__ __nv_bfloat16 g_qh[NELEM],  g_ql[NELEM];
__device__ __nv_bfloat16 g_kh[NELEM],  g_kl[NELEM];
__device__ __nv_bfloat16 g_vh[NELEM],  g_vl[NELEM];
__device__ __nv_bfloat16 g_oh[NELEM],  g_ol[NELEM];

// ---------------------------------------------------------------- PTX utils
__device__ __forceinline__ uint32_t smem_u32(const void* p) {
    uint32_t a;
    asm("{ .reg .u64 t; cvta.to.shared.u64 t, %1; cvt.u32.u64 %0, t; }"
        : "=r"(a) : "l"(p));
    return a;
}
#define CP_ASYNC16(dst, src) \
    asm volatile("cp.async.cg.shared.global [%0], [%1], 16;" \
                 :: "r"(dst), "l"(src) : "memory")
#define CP_COMMIT() asm volatile("cp.async.commit_group;" ::: "memory")
#define CP_WAIT(n)  asm volatile("cp.async.wait_group %0;" :: "n"(n) : "memory")

#define LDSM_X4(r0, r1, r2, r3, addr) \
    asm volatile("ldmatrix.sync.aligned.m8n8.x4.shared.b16 {%0,%1,%2,%3}, [%4];" \
                 : "=r"(r0), "=r"(r1), "=r"(r2), "=r"(r3) : "r"(addr))
#define LDSM_X4_T(r0, r1, r2, r3, addr) \
    asm volatile("ldmatrix.sync.aligned.m8n8.x4.trans.shared.b16 {%0,%1,%2,%3}, [%4];" \
                 : "=r"(r0), "=r"(r1), "=r"(r2), "=r"(r3) : "r"(addr))

#define MMA16816(c, a, b) \
    asm volatile("mma.sync.aligned.m16n8k16.row.col.f32.bf16.bf16.f32 " \
                 "{%0,%1,%2,%3}, {%4,%5,%6,%7}, {%8,%9}, {%0,%1,%2,%3};" \
                 : "+f"((c)[0]), "+f"((c)[1]), "+f"((c)[2]), "+f"((c)[3]) \
                 : "r"((a)[0]), "r"((a)[1]), "r"((a)[2]), "r"((a)[3]), \
                   "r"((b)[0]), "r"((b)[1]))

__device__ __forceinline__ uint32_t pack_bf16x2(float lo, float hi) {
    __nv_bfloat162 t = __floats2bfloat162_rn(lo, hi);
    return *(uint32_t*)&t;
}
__device__ __forceinline__ void split_store(__nv_bfloat16* Xh, __nv_bfloat16* Xl,
                                            size_t off, float v0, float v1) {
    __nv_bfloat16 h0 = __float2bfloat16(v0);
    __nv_bfloat16 h1 = __float2bfloat16(v1);
    __nv_bfloat16 l0 = __float2bfloat16(v0 - __bfloat162float(h0));
    __nv_bfloat16 l1 = __float2bfloat16(v1 - __bfloat162float(h1));
    *(__nv_bfloat162*)(Xh + off) = __nv_bfloat162(h0, h1);
    *(__nv_bfloat162*)(Xl + off) = __nv_bfloat162(l0, l1);
}

// ============================================================================
// GEMM core: bf16x3 HMMA, CTA tile 128x256, warp tile 64x64, BK=32,
// 3-stage cp.async, occ 1 (smem 162 KB). Row layout [hi 64B | lo 64B | pad16],
// stride 144 (9 phases mod 8 -> conflict-free ldmatrix).
// ============================================================================
#define GK_BM      128
#define GK_BN      256
#define GK_BK      32
#define GK_AREG    (GK_BM * 144)              // 18432
#define GK_BREG    (GK_BN * 144)              // 36864
#define GK_STAGE_B (GK_AREG + GK_BREG)        // 55296
#define GK_STAGES  3
#define GK_SMEM    (GK_STAGES * GK_STAGE_B)   // 165888
#define GK_NIT     (DIM_ / GK_BK)             // 128

__device__ __forceinline__ void gk_fill(uint32_t sbase,
    const __nv_bfloat16* __restrict__ Ah, const __nv_bfloat16* __restrict__ Al,
    const __nv_bfloat16* __restrict__ Bh, const __nv_bfloat16* __restrict__ Bl,
    int rowBase, int colBase, int k0)
{
    const int tid = threadIdx.x;
#pragma unroll
    for (int i = 0; i < 4; i++) {                 // A: 128 rows x 8 chunks
        int idx = tid + i * 256;
        int row = idx >> 3;
        int ch  = idx & 7;
        CP_ASYNC16(sbase + (uint32_t)(row * 144 + ch * 16),
                   ((ch < 4) ? Ah : Al) +
                   (size_t)(rowBase + row) * DIM_ + k0 + (ch & 3) * 8);
    }
#pragma unroll
    for (int i = 0; i < 8; i++) {                 // B: 256 rows x 8 chunks
        int idx = tid + i * 256;
        int row = idx >> 3;
        int ch  = idx & 7;
        CP_ASYNC16(sbase + GK_AREG + (uint32_t)(row * 144 + ch * 16),
                   ((ch < 4) ? Bh : Bl) +
                   (size_t)(colBase + row) * DIM_ + k0 + (ch & 3) * 8);
    }
}

#define GK_MAINLOOP(Ah, Al, Bh, Bl)                                            \
    gk_fill(base,              Ah, Al, Bh, Bl, rowBase, colBase, 0);           \
    CP_COMMIT();                                                               \
    gk_fill(base + GK_STAGE_B, Ah, Al, Bh, Bl, rowBase, colBase, GK_BK);       \
    CP_COMMIT();                                                               \
    const uint32_t aRow = (uint32_t)(wm + (lane & 15));                        \
    const uint32_t bRow = (uint32_t)(wn + (lane & 15));                        \
    const uint32_t kHalf = (uint32_t)((lane >> 4) * 16);                       \
    uint32_t stg = 0;                                                          \
    for (int it = 0; it < GK_NIT; it++) {                                      \
        CP_WAIT(1);                                                            \
        __syncthreads();                                                       \
        if (it + 2 < GK_NIT) {                                                 \
            uint32_t fs = stg + 2 * GK_STAGE_B;                                \
            if (fs >= GK_SMEM) fs -= GK_SMEM;                                  \
            gk_fill(base + fs, Ah, Al, Bh, Bl, rowBase, colBase,               \
                    (it + 2) * GK_BK);                                         \
        }                                                                      \
        CP_COMMIT();                                                           \
        const uint32_t sb = base + stg;                                        \
        stg += GK_STAGE_B; if (stg >= GK_SMEM) stg = 0;                        \
        _Pragma("unroll")                                                      \
        for (int ks = 0; ks < 2; ks++) {                                       \
            const uint32_t kcol = (uint32_t)(ks * 32) + kHalf;                 \
            uint32_t ah[4][4], al[4][4];                                       \
            _Pragma("unroll")                                                  \
            for (int mi = 0; mi < 4; mi++) {                                   \
                uint32_t off = (aRow + mi * 16) * 144 + kcol;                  \
                LDSM_X4(ah[mi][0], ah[mi][1], ah[mi][2], ah[mi][3], sb + off); \
                LDSM_X4(al[mi][0], al[mi][1], al[mi][2], al[mi][3],            \
                        sb + off + 64);                                        \
            }                                                                  \
            _Pragma("unroll")                                                  \
            for (int np = 0; np < 4; np++) {                                   \
                uint32_t off = GK_AREG + (bRow + np * 16) * 144 + kcol;        \
                uint32_t r0, r1, r2, r3;                                       \
                uint32_t bh0[2], bh1[2], bl0[2], bl1[2];                       \
                LDSM_X4(r0, r1, r2, r3, sb + off);                             \
                bh0[0] = r0; bh0[1] = r2; bh1[0] = r1; bh1[1] = r3;            \
                LDSM_X4(r0, r1, r2, r3, sb + off + 64);                        \
                bl0[0] = r0; bl0[1] = r2; bl1[0] = r1; bl1[1] = r3;            \
                _Pragma("unroll")                                              \
                for (int mi = 0; mi < 4; mi++) {                               \
                    MMA16816(acc[mi][2 * np],     ah[mi], bh0);                \
                    MMA16816(acc[mi][2 * np],     ah[mi], bl0);                \
                    MMA16816(acc[mi][2 * np],     al[mi], bh0);                \
                    MMA16816(acc[mi][2 * np + 1], ah[mi], bh1);                \
                    MMA16816(acc[mi][2 * np + 1], ah[mi], bl1);                \
                    MMA16816(acc[mi][2 * np + 1], al[mi], bh1);                \
                }                                                              \
            }                                                                  \
        }                                                                      \
    }

// --------- final output GEMM: fp32 C ---------
__global__ __launch_bounds__(256, 1)
void mma_gemm(const __nv_bfloat16* __restrict__ Ah, const __nv_bfloat16* __restrict__ Al,
              const __nv_bfloat16* __restrict__ Bh, const __nv_bfloat16* __restrict__ Bl,
              float* __restrict__ C)
{
    extern __shared__ char sm[];
    const uint32_t base = smem_u32(sm);
    const int lane = threadIdx.x & 31;
    const int wid  = threadIdx.x >> 5;
    const int rowBase = blockIdx.y * GK_BM;
    const int colBase = blockIdx.x * GK_BN;
    const int wm = (wid & 1) * 64;
    const int wn = (wid >> 1) * 64;

    float acc[4][8][4];
#pragma unroll
    for (int mi = 0; mi < 4; mi++)
#pragma unroll
        for (int ni = 0; ni < 8; ni++)
#pragma unroll
            for (int q = 0; q < 4; q++) acc[mi][ni][q] = 0.f;

    GK_MAINLOOP(Ah, Al, Bh, Bl)

    const int r0 = rowBase + wm + (lane >> 2);
    const int c0 = colBase + wn + (lane & 3) * 2;
#pragma unroll
    for (int mi = 0; mi < 4; mi++)
#pragma unroll
        for (int ni = 0; ni < 8; ni++) {
            float* p = C + (size_t)(r0 + mi * 16) * DIM_ + c0 + ni * 8;
            *(float2*)p = make_float2(acc[mi][ni][0], acc[mi][ni][1]);
            *(float2*)(p + 8 * DIM_) = make_float2(acc[mi][ni][2], acc[mi][ni][3]);
        }
}

// --------- QKV GEMM: z selects weights/output; rope fused for z<2 ---------
__global__ __launch_bounds__(256, 1)
void qkv_gemm(const __nv_bfloat16* __restrict__ Ah, const __nv_bfloat16* __restrict__ Al,
              const __nv_bfloat16* __restrict__ Bqh, const __nv_bfloat16* __restrict__ Bql,
              const __nv_bfloat16* __restrict__ Bkh, const __nv_bfloat16* __restrict__ Bkl,
              const __nv_bfloat16* __restrict__ Bvh, const __nv_bfloat16* __restrict__ Bvl,
              __nv_bfloat16* __restrict__ Qh, __nv_bfloat16* __restrict__ Ql,
              __nv_bfloat16* __restrict__ Kh, __nv_bfloat16* __restrict__ Kl,
              __nv_bfloat16* __restrict__ Vh, __nv_bfloat16* __restrict__ Vl,
              const float* __restrict__ fcos, const float* __restrict__ fsin)
{
    extern __shared__ char sm[];
    const uint32_t base = smem_u32(sm);
    const int lane = threadIdx.x & 31;
    const int wid  = threadIdx.x >> 5;
    const int rowBase = blockIdx.y * GK_BM;
    const int colBase = blockIdx.x * GK_BN;
    const int wm = (wid & 1) * 64;
    const int wn = (wid >> 1) * 64;
    const int z = blockIdx.z;

    const __nv_bfloat16* Bh = (z == 0) ? Bqh : (z == 1) ? Bkh : Bvh;
    const __nv_bfloat16* Bl = (z == 0) ? Bql : (z == 1) ? Bkl : Bvl;
    __nv_bfloat16* Xh = (z == 0) ? Qh : (z == 1) ? Kh : Vh;
    __nv_bfloat16* Xl = (z == 0) ? Ql : (z == 1) ? Kl : Vl;
    const bool dorope = (z < 2);

    float acc[4][8][4];
#pragma unroll
    for (int mi = 0; mi < 4; mi++)
#pragma unroll
        for (int ni = 0; ni < 8; ni++)
#pragma unroll
            for (int q = 0; q < 4; q++) acc[mi][ni][q] = 0.f;

    GK_MAINLOOP(Ah, Al, Bh, Bl)

    const int r0 = rowBase + wm + (lane >> 2);
    const int c0 = colBase + wn + (lane & 3) * 2;
#pragma unroll
    for (int mi = 0; mi < 4; mi++) {
        int r  = r0 + mi * 16;
        int s1 = r & (S_ - 1);
        int s2 = (r + 8) & (S_ - 1);
#pragma unroll
        for (int ni = 0; ni < 8; ni++) {
            int c = c0 + ni * 8;
            float v0 = acc[mi][ni][0], v1 = acc[mi][ni][1];
            float v2 = acc[mi][ni][2], v3 = acc[mi][ni][3];
            if (dorope) {
                int i = (c & (D_ - 1)) >> 1;
                float c1 = fcos[s1 * 64 + i], n1 = fsin[s1 * 64 + i];
                float c2 = fcos[s2 * 64 + i], n2 = fsin[s2 * 64 + i];
                float t;
                t = v0 * c1 - v1 * n1; v1 = v0 * n1 + v1 * c1; v0 = t;
                t = v2 * c2 - v3 * n2; v3 = v2 * n2 + v3 * c2; v2 = t;
            }
            split_store(Xh, Xl, (size_t)r * DIM_ + c, v0, v1);
            split_store(Xh, Xl, (size_t)(r + 8) * DIM_ + c, v2, v3);
        }
    }
}

// ============================================================================
// split5: one launch splits x, wq, wk, wv, wo
// ============================================================================
__global__ void split5(const float* __restrict__ x,  const float* __restrict__ wq,
                       const float* __restrict__ wk, const float* __restrict__ wv,
                       const float* __restrict__ wo,
                       __nv_bfloat16* xh,  __nv_bfloat16* xl,
                       __nv_bfloat16* qh,  __nv_bfloat16* ql,
                       __nv_bfloat16* kh,  __nv_bfloat16* kl,
                       __nv_bfloat16* vh,  __nv_bfloat16* vl,
                       __nv_bfloat16* oh,  __nv_bfloat16* ol)
{
    const float* src; __nv_bfloat16 *hi, *lo;
    switch (blockIdx.y) {
        case 0: src = x;  hi = xh; lo = xl; break;
        case 1: src = wq; hi = qh; lo = ql; break;
        case 2: src = wk; hi = kh; lo = kl; break;
        case 3: src = wv; hi = vh; lo = vl; break;
        default: src = wo; hi = oh; lo = ol; break;
    }
    size_t i = (size_t)blockIdx.x * blockDim.x + threadIdx.x;
    float4 v = ((const float4*)src)[i];
    __nv_bfloat16 h0 = __float2bfloat16(v.x);
    __nv_bfloat16 h1 = __float2bfloat16(v.y);
    __nv_bfloat16 h2 = __float2bfloat16(v.z);
    __nv_bfloat16 h3 = __float2bfloat16(v.w);
    ((__nv_bfloat162*)hi)[2 * i]     = __nv_bfloat162(h0, h1);
    ((__nv_bfloat162*)hi)[2 * i + 1] = __nv_bfloat162(h2, h3);
    ((__nv_bfloat162*)lo)[2 * i] = __nv_bfloat162(
        __float2bfloat16(v.x - __bfloat162float(h0)),
        __float2bfloat16(v.y - __bfloat162float(h1)));
    ((__nv_bfloat162*)lo)[2 * i + 1] = __nv_bfloat162(
        __float2bfloat16(v.z - __bfloat162float(h2)),
        __float2bfloat16(v.w - __bfloat162float(h3)));
}

// ============================================================================
// adapter GEMV (fp32)
// ============================================================================
__global__ __launch_bounds__(256)
void adapter_gemv(const float* __restrict__ A, const float* __restrict__ W,
                  float* __restrict__ out)
{
    int warp = (blockIdx.x * blockDim.x + threadIdx.x) >> 5;
    int lane = threadIdx.x & 31;
    int e0 = warp * 4;

    float acc[ADL_][4];
#pragma unroll
    for (int l = 0; l < ADL_; l++)
#pragma unroll
        for (int j = 0; j < 4; j++) acc[l][j] = 0.f;

    for (int d = lane * 4; d < DIM_; d += 128) {
        float4 w4[4];
#pragma unroll
        for (int j = 0; j < 4; j++)
            w4[j] = *(const float4*)(W + (size_t)(e0 + j) * DIM_ + d);
#pragma unroll
        for (int l = 0; l < ADL_; l++) {
            float4 a4 = *(const float4*)(A + (size_t)l * DIM_ + d);
#pragma unroll
            for (int j = 0; j < 4; j++) {
                acc[l][j] = fmaf(a4.x, w4[j].x, acc[l][j]);
                acc[l][j] = fmaf(a4.y, w4[j].y, acc[l][j]);
                acc[l][j] = fmaf(a4.z, w4[j].z, acc[l][j]);
                acc[l][j] = fmaf(a4.w, w4[j].w, acc[l][j]);
            }
        }
    }
#pragma unroll
    for (int l = 0; l < ADL_; l++)
#pragma unroll
        for (int j = 0; j < 4; j++) {
            float v = acc[l][j];
#pragma unroll
            for (int off = 16; off; off >>= 1)
                v += __shfl_xor_sync(0xffffffffu, v, off);
            if (lane == 0) out[l * DIM_ + e0 + j] = v;
        }
}

// ============================================================================
// Flash attention (HMMA bf16x3) + fused adapter attention + bf16-split output
// ============================================================================
#define FRSTR   272
#define FQ_TILE (128 * FRSTR)
#define FK_TILE (64 * FRSTR)
#define FSTAGE  (4 * FK_TILE)
#define FAK_OFF (2 * FQ_TILE + 2 * FSTAGE)
#define FLASH_SMEM (FAK_OFF + 2 * ADL_ * D_ * 4)

__device__ __forceinline__ void fkv_fill(uint32_t sdst,
    const __nv_bfloat16* __restrict__ Kh, const __nv_bfloat16* __restrict__ Kl,
    const __nv_bfloat16* __restrict__ Vh, const __nv_bfloat16* __restrict__ Vl,
    int b, int h, int kv0)
{
    const int tid = threadIdx.x;
    const size_t gbase = ((size_t)(b * S_) + kv0) * DIM_ + h * D_;
#pragma unroll
    for (int i = 0; i < 16; i++) {
        int idx = tid + i * 256;
        int arr = idx >> 10;
        int rem = idx & 1023;
        int row = rem >> 4;
        int ch  = rem & 15;
        const __nv_bfloat16* src =
            (arr == 0) ? Kh : (arr == 1) ? Kl : (arr == 2) ? Vh : Vl;
        CP_ASYNC16(sdst + arr * FK_TILE + row * FRSTR + ch * 16,
                   src + gbase + (size_t)row * DIM_ + ch * 8);
    }
}

__global__ __launch_bounds__(256, 1)
void flash_mma(const __nv_bfloat16* __restrict__ Qh_g, const __nv_bfloat16* __restrict__ Ql_g,
               const __nv_bfloat16* __restrict__ Kh_g, const __nv_bfloat16* __restrict__ Kl_g,
               const __nv_bfloat16* __restrict__ Vh_g, const __nv_bfloat16* __restrict__ Vl_g,
               const float* __restrict__ aK, const float* __restrict__ aV,
               const float* __restrict__ gate,
               __nv_bfloat16* __restrict__ Oh, __nv_bfloat16* __restrict__ Ol)
{
    extern __shared__ char sm[];
    const uint32_t base = smem_u32(sm);
    const int tid  = threadIdx.x;
    const int wid  = tid >> 5;
    const int lane = tid & 31;
    const int qt = blockIdx.x, h = blockIdx.y, b = blockIdx.z;
    const int nkt = 2 * qt + 2;

    const uint32_t sQh = base;
    const uint32_t sKV = base + 2 * FQ_TILE;
    float* aKs = (float*)(sm + FAK_OFF);
    float* aVs = aKs + ADL_ * D_;

    {
        size_t gq = ((size_t)(b * S_) + qt * 128) * DIM_ + h * D_;
#pragma unroll
        for (int i = 0; i < 8; i++) {
            int idx = tid + i * 256;
            int row = idx >> 4, ch = idx & 15;
            uint32_t d = row * FRSTR + ch * 16;
            size_t src = gq + (size_t)row * DIM_ + ch * 8;
            CP_ASYNC16(sQh + d,           Qh_g + src);
            CP_ASYNC16(sQh + FQ_TILE + d, Ql_g + src);
        }
        for (int idx = tid; idx < ADL_ * D_; idx += 256) {
            int t = idx >> 7, cc = idx & (D_ - 1);
            aKs[idx] = aK[t * DIM_ + h * D_ + cc];
            aVs[idx] = aV[t * DIM_ + h * D_ + cc];
        }
    }
    fkv_fill(sKV, Kh_g, Kl_g, Vh_g, Vl_g, b, h, 0);
    CP_COMMIT();

    const int q0  = qt * 128 + wid * 16;
    const int qg0 = q0 + (lane >> 2);
    const int qg1 = qg0 + 8;
    const float scl = 0.08838834764831845f;

    float m0 = -1e30f, m1 = -1e30f, l0 = 0.f, l1 = 0.f;
    float o[16][4];
#pragma unroll
    for (int d = 0; d < 16; d++)
#pragma unroll
        for (int q = 0; q < 4; q++) o[d][q] = 0.f;

    const uint32_t kh16 = (uint32_t)((lane >> 4) * 16);

    for (int kt = 0; kt < nkt; kt++) {
        if (kt + 1 < nkt)
            fkv_fill(sKV + ((kt + 1) & 1) * FSTAGE,
                     Kh_g, Kl_g, Vh_g, Vl_g, b, h, (kt + 1) * 64);
        CP_COMMIT();
        CP_WAIT(1);
        __syncthreads();

        const uint32_t st = sKV + (uint32_t)(kt & 1) * FSTAGE;
        const int kv0 = kt * 64;

        if (kv0 <= q0 + 15) {
            float sa[8][4];
#pragma unroll
            for (int n8 = 0; n8 < 8; n8++)
#pragma unroll
                for (int q = 0; q < 4; q++) sa[n8][q] = 0.f;

            const uint32_t qrow = (uint32_t)(wid * 16 + (lane & 15));
            const uint32_t klrow = (uint32_t)(lane & 15);

#pragma unroll
            for (int ch = 0; ch < 8; ch++) {
                uint32_t qa = sQh + qrow * FRSTR + ch * 32 + kh16;
                uint32_t qh[4], ql[4];
                LDSM_X4(qh[0], qh[1], qh[2], qh[3], qa);
                LDSM_X4(ql[0], ql[1], ql[2], ql[3], qa + FQ_TILE);
#pragma unroll
                for (int nb = 0; nb < 4; nb++) {
                    uint32_t ka = st + (klrow + nb * 16) * FRSTR + ch * 32 + kh16;
                    uint32_t r0, r1, r2, r3, t0, t1, t2, t3;
                    LDSM_X4(r0, r1, r2, r3, ka);
                    LDSM_X4(t0, t1, t2, t3, ka + FK_TILE);
                    uint32_t kb0[2] = {r0, r2}, kb1[2] = {r1, r3};
                    uint32_t lb0[2] = {t0, t2}, lb1[2] = {t1, t3};
                    MMA16816(sa[2 * nb],     qh, kb0);
                    MMA16816(sa[2 * nb],     qh, lb0);
                    MMA16816(sa[2 * nb],     ql, kb0);
                    MMA16816(sa[2 * nb + 1], qh, kb1);
                    MMA16816(sa[2 * nb + 1], qh, lb1);
                    MMA16816(sa[2 * nb + 1], ql, kb1);
                }
            }

            float rmax0 = -1e30f, rmax1 = -1e30f;
            const int kvb = kv0 + (lane & 3) * 2;
#pragma unroll
            for (int n8 = 0; n8 < 8; n8++) {
                int kvc = kvb + n8 * 8;
                float s0 = sa[n8][0] * scl, s1 = sa[n8][1] * scl;
                float s2 = sa[n8][2] * scl, s3 = sa[n8][3] * scl;
                if (kvc     > qg0) s0 = -1e30f;
                if (kvc + 1 > qg0) s1 = -1e30f;
                if (kvc     > qg1) s2 = -1e30f;
                if (kvc + 1 > qg1) s3 = -1e30f;
                sa[n8][0] = s0; sa[n8][1] = s1; sa[n8][2] = s2; sa[n8][3] = s3;
                rmax0 = fmaxf(rmax0, fmaxf(s0, s1));
                rmax1 = fmaxf(rmax1, fmaxf(s2, s3));
            }
            rmax0 = fmaxf(rmax0, __shfl_xor_sync(0xffffffffu, rmax0, 1));
            rmax0 = fmaxf(rmax0, __shfl_xor_sync(0xffffffffu, rmax0, 2));
            rmax1 = fmaxf(rmax1, __shfl_xor_sync(0xffffffffu, rmax1, 1));
            rmax1 = fmaxf(rmax1, __shfl_xor_sync(0xffffffffu, rmax1, 2));

            float mn0 = fmaxf(m0, rmax0), mn1 = fmaxf(m1, rmax1);
            float sc0 = __expf(m0 - mn0), sc1 = __expf(m1 - mn1);
            m0 = mn0; m1 = mn1;

            uint32_t ph[16], pl[16];
            float rs0 = 0.f, rs1 = 0.f;
#pragma unroll
            for (int n8 = 0; n8 < 8; n8++) {
                float p0 = __expf(sa[n8][0] - mn0);
                float p1 = __expf(sa[n8][1] - mn0);
                float p2 = __expf(sa[n8][2] - mn1);
                float p3 = __expf(sa[n8][3] - mn1);
                rs0 += p0 + p1; rs1 += p2 + p3;
                float h0 = __bfloat162float(__float2bfloat16(p0));
                float h1 = __bfloat162float(__float2bfloat16(p1));
                float h2 = __bfloat162float(__float2bfloat16(p2));
                float h3 = __bfloat162float(__float2bfloat16(p3));
                ph[2 * n8]     = pack_bf16x2(h0, h1);
                ph[2 * n8 + 1] = pack_bf16x2(h2, h3);
                pl[2 * n8]     = pack_bf16x2(p0 - h0, p1 - h1);
                pl[2 * n8 + 1] = pack_bf16x2(p2 - h2, p3 - h3);
            }
            rs0 += __shfl_xor_sync(0xffffffffu, rs0, 1);
            rs0 += __shfl_xor_sync(0xffffffffu, rs0, 2);
            rs1 += __shfl_xor_sync(0xffffffffu, rs1, 1);
            rs1 += __shfl_xor_sync(0xffffffffu, rs1, 2);
            l0 = l0 * sc0 + rs0;
            l1 = l1 * sc1 + rs1;

#pragma unroll
            for (int d = 0; d < 16; d++) {
                o[d][0] *= sc0; o[d][1] *= sc0;
                o[d][2] *= sc1; o[d][3] *= sc1;
            }

#pragma unroll
            for (int j = 0; j < 4; j++) {
                uint32_t ah[4] = {ph[4*j], ph[4*j+1], ph[4*j+2], ph[4*j+3]};
                uint32_t al[4] = {pl[4*j], pl[4*j+1], pl[4*j+2], pl[4*j+3]};
#pragma unroll
                for (int nb = 0; nb < 8; nb++) {
                    uint32_t va = st + 2 * FK_TILE +
                                  (uint32_t)(j * 16 + (lane & 15)) * FRSTR +
                                  nb * 32 + kh16;
                    uint32_t r0, r1, r2, r3, t0, t1, t2, t3;
                    LDSM_X4_T(r0, r1, r2, r3, va);
                    LDSM_X4_T(t0, t1, t2, t3, va + FK_TILE);
                    uint32_t vh0[2] = {r0, r1}, vh1[2] = {r2, r3};
                    uint32_t vl0[2] = {t0, t1}, vl1[2] = {t2, t3};
                    MMA16816(o[2 * nb],     ah, vh0);
                    MMA16816(o[2 * nb],     ah, vl0);
                    MMA16816(o[2 * nb],     al, vh0);
                    MMA16816(o[2 * nb + 1], ah, vh1);
                    MMA16816(o[2 * nb + 1], ah, vl1);
                    MMA16816(o[2 * nb + 1], al, vh1);
                }
            }
        }
        __syncthreads();
    }

    // ---- epilogue: fused adapter attention + bf16 split store ----
    const float g = tanhf(gate[h]);
    const float inv0 = 1.0f / l0, inv1 = 1.0f / l1;
    const int ccb = (lane & 3) * 2;

#pragma unroll
    for (int rr = 0; rr < 2; rr++) {
        const int lr = wid * 16 + (lane >> 2) + rr * 8;
        const float inv = rr ? inv1 : inv0;
        const size_t rowg = (size_t)(b * S_) + qt * 128 + lr;

        float qv[32];
#pragma unroll
        for (int d = 0; d < 16; d++) {
            int cc = d * 8 + ccb;
            __nv_bfloat162 hh = *(__nv_bfloat162*)(sm + lr * FRSTR + cc * 2);
            __nv_bfloat162 ll = *(__nv_bfloat162*)(sm + FQ_TILE + lr * FRSTR + cc * 2);
            qv[2 * d]     = __bfloat162float(hh.x) + __bfloat162float(ll.x);
            qv[2 * d + 1] = __bfloat162float(hh.y) + __bfloat162float(ll.y);
        }
        float sc[ADL_];
#pragma unroll
        for (int t = 0; t < ADL_; t++) {
            float p = 0.f;
#pragma unroll
            for (int d = 0; d < 16; d++) {
                int cc = d * 8 + ccb;
                p = fmaf(qv[2 * d],     aKs[t * D_ + cc],     p);
                p = fmaf(qv[2 * d + 1], aKs[t * D_ + cc + 1], p);
            }
            p += __shfl_xor_sync(0xffffffffu, p, 1);
            p += __shfl_xor_sync(0xffffffffu, p, 2);
            sc[t] = p * scl;
        }
        float mx = sc[0];
#pragma unroll
        for (int t = 1; t < ADL_; t++) mx = fmaxf(mx, sc[t]);
        float sum = 0.f;
#pragma unroll
        for (int t = 0; t < ADL_; t++) { sc[t] = __expf(sc[t] - mx); sum += sc[t]; }
        float isum = g / sum;
#pragma unroll
        for (int t = 0; t < ADL_; t++) sc[t] *= isum;

#pragma unroll
        for (int d = 0; d < 16; d++) {
            int cc = d * 8 + ccb;
            float a0 = 0.f, a1 = 0.f;
#pragma unroll
            for (int t = 0; t < ADL_; t++) {
                a0 = fmaf(sc[t], aVs[t * D_ + cc],     a0);
                a1 = fmaf(sc[t], aVs[t * D_ + cc + 1], a1);
            }
            float o0 = o[d][rr * 2]     * inv + a0;
            float o1 = o[d][rr * 2 + 1] * inv + a1;
            split_store(Oh, Ol, rowg * DIM_ + h * D_ + cc, o0, o1);
        }
    }
}

// ============================================================================
// launch
// ============================================================================
extern "C" void kernel_launch(void* const* d_in, const int* in_sizes, int n_in,
                              void* d_out, int out_size)
{
    const float* x       = (const float*)d_in[0];
    const float* wq      = (const float*)d_in[1];
    const float* wk      = (const float*)d_in[2];
    const float* wv      = (const float*)d_in[3];
    const float* wo      = (const float*)d_in[4];
    const float* gate    = (const float*)d_in[5];
    const float* adapter = (const float*)d_in[6];
    const float* fcos    = (const float*)d_in[7];
    const float* fsin    = (const float*)d_in[8];
    float* out = (float*)d_out;

    float *aKp, *aVp;
    cudaGetSymbolAddress((void**)&aKp, g_aK);
    cudaGetSymbolAddress((void**)&aVp, g_aV);

    __nv_bfloat16 *xh, *xl, *wqh, *wql, *wkh, *wkl, *wvh, *wvl, *woh, *wol;
    __nv_bfloat16 *qh, *ql, *kh, *kl, *vh, *vl, *oh, *ol;
    cudaGetSymbolAddress((void**)&xh,  g_xh);  cudaGetSymbolAddress((void**)&xl,  g_xl);
    cudaGetSymbolAddress((void**)&wqh, g_wqh); cudaGetSymbolAddress((void**)&wql, g_wql);
    cudaGetSymbolAddress((void**)&wkh, g_wkh); cudaGetSymbolAddress((void**)&wkl, g_wkl);
    cudaGetSymbolAddress((void**)&wvh, g_wvh); cudaGetSymbolAddress((void**)&wvl, g_wvl);
    cudaGetSymbolAddress((void**)&woh, g_woh); cudaGetSymbolAddress((void**)&wol, g_wol);
    cudaGetSymbolAddress((void**)&qh,  g_qh);  cudaGetSymbolAddress((void**)&ql,  g_ql);
    cudaGetSymbolAddress((void**)&kh,  g_kh);  cudaGetSymbolAddress((void**)&kl,  g_kl);
    cudaGetSymbolAddress((void**)&vh,  g_vh);  cudaGetSymbolAddress((void**)&vl,  g_vl);
    cudaGetSymbolAddress((void**)&oh,  g_oh);  cudaGetSymbolAddress((void**)&ol,  g_ol);

    cudaFuncSetAttribute(mma_gemm,
                         cudaFuncAttributeMaxDynamicSharedMemorySize, GK_SMEM);
    cudaFuncSetAttribute(qkv_gemm,
                         cudaFuncAttributeMaxDynamicSharedMemorySize, GK_SMEM);
    cudaFuncSetAttribute(flash_mma,
                         cudaFuncAttributeMaxDynamicSharedMemorySize, FLASH_SMEM);

    split5<<<dim3(NELEM / 4 / 256, 5), 256>>>(x, wq, wk, wv, wo,
        xh, xl, wqh, wql, wkh, wkl, wvh, wvl, woh, wol);

    adapter_gemv<<<128, 256>>>(adapter, wk, aKp);
    adapter_gemv<<<128, 256>>>(adapter, wv, aVp);

    qkv_gemm<<<dim3(DIM_ / GK_BN, MROWS / GK_BM, 3), 256, GK_SMEM>>>(
        xh, xl, wqh, wql, wkh, wkl, wvh, wvl,
        qh, ql, kh, kl, vh, vl, fcos, fsin);

    flash_mma<<<dim3(S_ / 128, H_, B_), 256, FLASH_SMEM>>>(
        qh, ql, kh, kl, vh, vl, aKp, aVp, gate, oh, ol);

    mma_gemm<<<dim3(DIM_ / GK_BN, MROWS / GK_BM), 256, GK_SMEM>>>(
        oh, ol, woh, wol, out);
}

// round 10
// speedup vs baseline: 1.0938x; 1.0938x over previous
#include <cuda_runtime.h>
#include <cuda_bf16.h>
#include <math.h>
#include <stdint.h>

// ---------------------------------------------------------------- constants
#define B_    2
#define S_    2048
#define H_    32
#define D_    128
#define DIM_  4096
#define ADL_  10
#define MROWS (B_ * S_)
#define NELEM ((size_t)MROWS * DIM_)

// ---------------------------------------------------------------- scratch
__device__ float g_aK[ADL_ * DIM_];
__device__ float g_aV[ADL_ * DIM_];

__device__ __nv_bfloat16 g_xh[NELEM],  g_xl[NELEM];
__device__ __nv_bfloat16 g_wqh[NELEM], g_wql[NELEM];
__device__ __nv_bfloat16 g_wkh[NELEM], g_wkl[NELEM];
__device__ __nv_bfloat16 g_wvh[NELEM], g_wvl[NELEM];
__device__ __nv_bfloat16 g_woh[NELEM], g_wol[NELEM];
__device__ __nv_bfloat16 g_qh[NELEM],  g_ql[NELEM];
__device__ __nv_bfloat16 g_kh[NELEM],  g_kl[NELEM];
__device__ __nv_bfloat16 g_vh[NELEM],  g_vl[NELEM];
__device__ __nv_bfloat16 g_oh[NELEM],  g_ol[NELEM];

// ---------------------------------------------------------------- PTX utils
__device__ __forceinline__ uint32_t smem_u32(const void* p) {
    uint32_t a;
    asm("{ .reg .u64 t; cvta.to.shared.u64 t, %1; cvt.u32.u64 %0, t; }"
        : "=r"(a) : "l"(p));
    return a;
}
#define CP_ASYNC16(dst, src) \
    asm volatile("cp.async.cg.shared.global [%0], [%1], 16;" \
                 :: "r"(dst), "l"(src) : "memory")
#define CP_COMMIT() asm volatile("cp.async.commit_group;" ::: "memory")
#define CP_WAIT(n)  asm volatile("cp.async.wait_group %0;" :: "n"(n) : "memory")

#define LDSM_X4(r0, r1, r2, r3, addr) \
    asm volatile("ldmatrix.sync.aligned.m8n8.x4.shared.b16 {%0,%1,%2,%3}, [%4];" \
                 : "=r"(r0), "=r"(r1), "=r"(r2), "=r"(r3) : "r"(addr))
#define LDSM_X4_T(r0, r1, r2, r3, addr) \
    asm volatile("ldmatrix.sync.aligned.m8n8.x4.trans.shared.b16 {%0,%1,%2,%3}, [%4];" \
                 : "=r"(r0), "=r"(r1), "=r"(r2), "=r"(r3) : "r"(addr))

#define MMA16816(c, a, b) \
    asm volatile("mma.sync.aligned.m16n8k16.row.col.f32.bf16.bf16.f32 " \
                 "{%0,%1,%2,%3}, {%4,%5,%6,%7}, {%8,%9}, {%0,%1,%2,%3};" \
                 : "+f"((c)[0]), "+f"((c)[1]), "+f"((c)[2]), "+f"((c)[3]) \
                 : "r"((a)[0]), "r"((a)[1]), "r"((a)[2]), "r"((a)[3]), \
                   "r"((b)[0]), "r"((b)[1]))

__device__ __forceinline__ uint32_t pack_bf16x2(float lo, float hi) {
    __nv_bfloat162 t = __floats2bfloat162_rn(lo, hi);
    return *(uint32_t*)&t;
}
__device__ __forceinline__ void split_store(__nv_bfloat16* Xh, __nv_bfloat16* Xl,
                                            size_t off, float v0, float v1) {
    __nv_bfloat16 h0 = __float2bfloat16(v0);
    __nv_bfloat16 h1 = __float2bfloat16(v1);
    __nv_bfloat16 l0 = __float2bfloat16(v0 - __bfloat162float(h0));
    __nv_bfloat16 l1 = __float2bfloat16(v1 - __bfloat162float(h1));
    *(__nv_bfloat162*)(Xh + off) = __nv_bfloat162(h0, h1);
    *(__nv_bfloat162*)(Xl + off) = __nv_bfloat162(l0, l1);
}

// ============================================================================
// GEMM core: bf16x3 HMMA, 128x128 CTA tile, BK=32, 2-stage cp.async, 2 CTA/SM
// (R7 config) with dependency-chain-breaking MMA ordering: the three bf16x3
// products are issued as three full passes over all 16 accumulators.
// ============================================================================
#define GK_BK      32
#define GK_TILE_B  10240
#define GK_STAGE_B (4 * GK_TILE_B)
#define GK_STAGES  2
#define GK_SMEM    (GK_STAGES * GK_STAGE_B)    // 81920 -> 2 CTAs/SM
#define GK_NIT     (DIM_ / GK_BK)

__device__ __forceinline__ void gk_fill(uint32_t sbase,
    const __nv_bfloat16* __restrict__ Ah, const __nv_bfloat16* __restrict__ Al,
    const __nv_bfloat16* __restrict__ Bh, const __nv_bfloat16* __restrict__ Bl,
    int rowBase, int colBase, int k0)
{
    const int tid = threadIdx.x;
#pragma unroll
    for (int i = 0; i < 2; i++) {
        int idx = tid + i * 256;
        int row = idx >> 2;
        int cg  = (idx & 3) * 8;
        uint32_t doff = (uint32_t)(row * 80 + (idx & 3) * 16);
        size_t ga = (size_t)(rowBase + row) * DIM_ + k0 + cg;
        size_t gb = (size_t)(colBase + row) * DIM_ + k0 + cg;
        CP_ASYNC16(sbase + doff,                 Ah + ga);
        CP_ASYNC16(sbase + GK_TILE_B + doff,     Al + ga);
        CP_ASYNC16(sbase + 2 * GK_TILE_B + doff, Bh + gb);
        CP_ASYNC16(sbase + 3 * GK_TILE_B + doff, Bl + gb);
    }
}

#define GK_MAINLOOP(Ah, Al, Bh, Bl)                                            \
    gk_fill(base, Ah, Al, Bh, Bl, rowBase, colBase, 0);                        \
    CP_COMMIT();                                                               \
    const uint32_t aRow = (uint32_t)(wm + (lane & 15));                        \
    const uint32_t bRow = (uint32_t)(wn + (lane & 15));                        \
    const uint32_t kHalf = (uint32_t)((lane >> 4) * 16);                       \
    for (int it = 0; it < GK_NIT; it++) {                                      \
        CP_WAIT(0);                                                            \
        __syncthreads();                                                       \
        if (it + 1 < GK_NIT)                                                   \
            gk_fill(base + (uint32_t)((it + 1) & 1) * GK_STAGE_B,              \
                    Ah, Al, Bh, Bl, rowBase, colBase, (it + 1) * GK_BK);       \
        CP_COMMIT();                                                           \
        const uint32_t sb = base + (uint32_t)(it & 1) * GK_STAGE_B;            \
        _Pragma("unroll")                                                      \
        for (int ks = 0; ks < 2; ks++) {                                       \
            const uint32_t kcol = (uint32_t)(ks * 32) + kHalf;                 \
            uint32_t ah[4][4], al[4][4], bh[4][2], bl[4][2];                   \
            _Pragma("unroll")                                                  \
            for (int mi = 0; mi < 4; mi++) {                                   \
                uint32_t off = (aRow + mi * 16) * 80 + kcol;                   \
                LDSM_X4(ah[mi][0], ah[mi][1], ah[mi][2], ah[mi][3], sb + off); \
                LDSM_X4(al[mi][0], al[mi][1], al[mi][2], al[mi][3],            \
                        sb + GK_TILE_B + off);                                 \
            }                                                                  \
            _Pragma("unroll")                                                  \
            for (int np = 0; np < 2; np++) {                                   \
                uint32_t off = (bRow + np * 16) * 80 + kcol;                   \
                uint32_t r0, r1, r2, r3;                                       \
                LDSM_X4(r0, r1, r2, r3, sb + 2 * GK_TILE_B + off);             \
                bh[2 * np][0] = r0; bh[2 * np][1] = r2;                        \
                bh[2 * np + 1][0] = r1; bh[2 * np + 1][1] = r3;                \
                LDSM_X4(r0, r1, r2, r3, sb + 3 * GK_TILE_B + off);             \
                bl[2 * np][0] = r0; bl[2 * np][1] = r2;                        \
                bl[2 * np + 1][0] = r1; bl[2 * np + 1][1] = r3;                \
            }                                                                  \
            _Pragma("unroll")                                                  \
            for (int mi = 0; mi < 4; mi++)                                     \
                _Pragma("unroll")                                              \
                for (int ni = 0; ni < 4; ni++)                                 \
                    MMA16816(acc[mi][ni], ah[mi], bh[ni]);                     \
            _Pragma("unroll")                                                  \
            for (int mi = 0; mi < 4; mi++)                                     \
                _Pragma("unroll")                                              \
                for (int ni = 0; ni < 4; ni++)                                 \
                    MMA16816(acc[mi][ni], ah[mi], bl[ni]);                     \
            _Pragma("unroll")                                                  \
            for (int mi = 0; mi < 4; mi++)                                     \
                _Pragma("unroll")                                              \
                for (int ni = 0; ni < 4; ni++)                                 \
                    MMA16816(acc[mi][ni], al[mi], bh[ni]);                     \
        }                                                                      \
    }

// --------- final output GEMM: fp32 C ---------
__global__ __launch_bounds__(256, 2)
void mma_gemm(const __nv_bfloat16* __restrict__ Ah, const __nv_bfloat16* __restrict__ Al,
              const __nv_bfloat16* __restrict__ Bh, const __nv_bfloat16* __restrict__ Bl,
              float* __restrict__ C)
{
    extern __shared__ char sm[];
    const uint32_t base = smem_u32(sm);
    const int lane = threadIdx.x & 31;
    const int wid  = threadIdx.x >> 5;
    const int rowBase = blockIdx.y * 128;
    const int colBase = blockIdx.x * 128;
    const int wm = (wid & 1) * 64;
    const int wn = (wid >> 1) * 32;

    float acc[4][4][4];
#pragma unroll
    for (int mi = 0; mi < 4; mi++)
#pragma unroll
        for (int ni = 0; ni < 4; ni++)
#pragma unroll
            for (int q = 0; q < 4; q++) acc[mi][ni][q] = 0.f;

    GK_MAINLOOP(Ah, Al, Bh, Bl)

    const int r0 = rowBase + wm + (lane >> 2);
    const int c0 = colBase + wn + (lane & 3) * 2;
#pragma unroll
    for (int mi = 0; mi < 4; mi++)
#pragma unroll
        for (int ni = 0; ni < 4; ni++) {
            float* p = C + (size_t)(r0 + mi * 16) * DIM_ + c0 + ni * 8;
            *(float2*)p = make_float2(acc[mi][ni][0], acc[mi][ni][1]);
            *(float2*)(p + 8 * DIM_) = make_float2(acc[mi][ni][2], acc[mi][ni][3]);
        }
}

// --------- QKV GEMM: z selects weights/output; rope fused for z<2 ---------
__global__ __launch_bounds__(256, 2)
void qkv_gemm(const __nv_bfloat16* __restrict__ Ah, const __nv_bfloat16* __restrict__ Al,
              const __nv_bfloat16* __restrict__ Bqh, const __nv_bfloat16* __restrict__ Bql,
              const __nv_bfloat16* __restrict__ Bkh, const __nv_bfloat16* __restrict__ Bkl,
              const __nv_bfloat16* __restrict__ Bvh, const __nv_bfloat16* __restrict__ Bvl,
              __nv_bfloat16* __restrict__ Qh, __nv_bfloat16* __restrict__ Ql,
              __nv_bfloat16* __restrict__ Kh, __nv_bfloat16* __restrict__ Kl,
              __nv_bfloat16* __restrict__ Vh, __nv_bfloat16* __restrict__ Vl,
              const float* __restrict__ fcos, const float* __restrict__ fsin)
{
    extern __shared__ char sm[];
    const uint32_t base = smem_u32(sm);
    const int lane = threadIdx.x & 31;
    const int wid  = threadIdx.x >> 5;
    const int rowBase = blockIdx.y * 128;
    const int colBase = blockIdx.x * 128;
    const int wm = (wid & 1) * 64;
    const int wn = (wid >> 1) * 32;
    const int z = blockIdx.z;

    const __nv_bfloat16* Bh = (z == 0) ? Bqh : (z == 1) ? Bkh : Bvh;
    const __nv_bfloat16* Bl = (z == 0) ? Bql : (z == 1) ? Bkl : Bvl;
    __nv_bfloat16* Xh = (z == 0) ? Qh : (z == 1) ? Kh : Vh;
    __nv_bfloat16* Xl = (z == 0) ? Ql : (z == 1) ? Kl : Vl;
    const bool dorope = (z < 2);

    float acc[4][4][4];
#pragma unroll
    for (int mi = 0; mi < 4; mi++)
#pragma unroll
        for (int ni = 0; ni < 4; ni++)
#pragma unroll
            for (int q = 0; q < 4; q++) acc[mi][ni][q] = 0.f;

    GK_MAINLOOP(Ah, Al, Bh, Bl)

    const int r0 = rowBase + wm + (lane >> 2);
    const int c0 = colBase + wn + (lane & 3) * 2;
#pragma unroll
    for (int mi = 0; mi < 4; mi++) {
        int r  = r0 + mi * 16;
        int s1 = r & (S_ - 1);
        int s2 = (r + 8) & (S_ - 1);
#pragma unroll
        for (int ni = 0; ni < 4; ni++) {
            int c = c0 + ni * 8;
            float v0 = acc[mi][ni][0], v1 = acc[mi][ni][1];
            float v2 = acc[mi][ni][2], v3 = acc[mi][ni][3];
            if (dorope) {
                int i = (c & (D_ - 1)) >> 1;
                float c1 = fcos[s1 * 64 + i], n1 = fsin[s1 * 64 + i];
                float c2 = fcos[s2 * 64 + i], n2 = fsin[s2 * 64 + i];
                float t;
                t = v0 * c1 - v1 * n1; v1 = v0 * n1 + v1 * c1; v0 = t;
                t = v2 * c2 - v3 * n2; v3 = v2 * n2 + v3 * c2; v2 = t;
            }
            split_store(Xh, Xl, (size_t)r * DIM_ + c, v0, v1);
            split_store(Xh, Xl, (size_t)(r + 8) * DIM_ + c, v2, v3);
        }
    }
}

// ============================================================================
// split5: one launch splits x, wq, wk, wv, wo
// ============================================================================
__global__ void split5(const float* __restrict__ x,  const float* __restrict__ wq,
                       const float* __restrict__ wk, const float* __restrict__ wv,
                       const float* __restrict__ wo,
                       __nv_bfloat16* xh,  __nv_bfloat16* xl,
                       __nv_bfloat16* qh,  __nv_bfloat16* ql,
                       __nv_bfloat16* kh,  __nv_bfloat16* kl,
                       __nv_bfloat16* vh,  __nv_bfloat16* vl,
                       __nv_bfloat16* oh,  __nv_bfloat16* ol)
{
    const float* src; __nv_bfloat16 *hi, *lo;
    switch (blockIdx.y) {
        case 0: src = x;  hi = xh; lo = xl; break;
        case 1: src = wq; hi = qh; lo = ql; break;
        case 2: src = wk; hi = kh; lo = kl; break;
        case 3: src = wv; hi = vh; lo = vl; break;
        default: src = wo; hi = oh; lo = ol; break;
    }
    size_t i = (size_t)blockIdx.x * blockDim.x + threadIdx.x;
    float4 v = ((const float4*)src)[i];
    __nv_bfloat16 h0 = __float2bfloat16(v.x);
    __nv_bfloat16 h1 = __float2bfloat16(v.y);
    __nv_bfloat16 h2 = __float2bfloat16(v.z);
    __nv_bfloat16 h3 = __float2bfloat16(v.w);
    ((__nv_bfloat162*)hi)[2 * i]     = __nv_bfloat162(h0, h1);
    ((__nv_bfloat162*)hi)[2 * i + 1] = __nv_bfloat162(h2, h3);
    ((__nv_bfloat162*)lo)[2 * i] = __nv_bfloat162(
        __float2bfloat16(v.x - __bfloat162float(h0)),
        __float2bfloat16(v.y - __bfloat162float(h1)));
    ((__nv_bfloat162*)lo)[2 * i + 1] = __nv_bfloat162(
        __float2bfloat16(v.z - __bfloat162float(h2)),
        __float2bfloat16(v.w - __bfloat162float(h3)));
}

// ============================================================================
// adapter GEMV (fp32)
// ============================================================================
__global__ __launch_bounds__(256)
void adapter_gemv(const float* __restrict__ A, const float* __restrict__ W,
                  float* __restrict__ out)
{
    int warp = (blockIdx.x * blockDim.x + threadIdx.x) >> 5;
    int lane = threadIdx.x & 31;
    int e0 = warp * 4;

    float acc[ADL_][4];
#pragma unroll
    for (int l = 0; l < ADL_; l++)
#pragma unroll
        for (int j = 0; j < 4; j++) acc[l][j] = 0.f;

    for (int d = lane * 4; d < DIM_; d += 128) {
        float4 w4[4];
#pragma unroll
        for (int j = 0; j < 4; j++)
            w4[j] = *(const float4*)(W + (size_t)(e0 + j) * DIM_ + d);
#pragma unroll
        for (int l = 0; l < ADL_; l++) {
            float4 a4 = *(const float4*)(A + (size_t)l * DIM_ + d);
#pragma unroll
            for (int j = 0; j < 4; j++) {
                acc[l][j] = fmaf(a4.x, w4[j].x, acc[l][j]);
                acc[l][j] = fmaf(a4.y, w4[j].y, acc[l][j]);
                acc[l][j] = fmaf(a4.z, w4[j].z, acc[l][j]);
                acc[l][j] = fmaf(a4.w, w4[j].w, acc[l][j]);
            }
        }
    }
#pragma unroll
    for (int l = 0; l < ADL_; l++)
#pragma unroll
        for (int j = 0; j < 4; j++) {
            float v = acc[l][j];
#pragma unroll
            for (int off = 16; off; off >>= 1)
                v += __shfl_xor_sync(0xffffffffu, v, off);
            if (lane == 0) out[l * DIM_ + e0 + j] = v;
        }
}

// ============================================================================
// Flash attention (HMMA bf16x3) + fused adapter attention + bf16-split output.
// Dependency-chain-breaking MMA ordering in QK and PV; heavy tiles first.
// ============================================================================
#define FRSTR   272
#define FQ_TILE (128 * FRSTR)
#define FK_TILE (64 * FRSTR)
#define FSTAGE  (4 * FK_TILE)
#define FAK_OFF (2 * FQ_TILE + 2 * FSTAGE)
#define FLASH_SMEM (FAK_OFF + 2 * ADL_ * D_ * 4)

__device__ __forceinline__ void fkv_fill(uint32_t sdst,
    const __nv_bfloat16* __restrict__ Kh, const __nv_bfloat16* __restrict__ Kl,
    const __nv_bfloat16* __restrict__ Vh, const __nv_bfloat16* __restrict__ Vl,
    int b, int h, int kv0)
{
    const int tid = threadIdx.x;
    const size_t gbase = ((size_t)(b * S_) + kv0) * DIM_ + h * D_;
#pragma unroll
    for (int i = 0; i < 16; i++) {
        int idx = tid + i * 256;
        int arr = idx >> 10;
        int rem = idx & 1023;
        int row = rem >> 4;
        int ch  = rem & 15;
        const __nv_bfloat16* src =
            (arr == 0) ? Kh : (arr == 1) ? Kl : (arr == 2) ? Vh : Vl;
        CP_ASYNC16(sdst + arr * FK_TILE + row * FRSTR + ch * 16,
                   src + gbase + (size_t)row * DIM_ + ch * 8);
    }
}

__global__ __launch_bounds__(256, 1)
void flash_mma(const __nv_bfloat16* __restrict__ Qh_g, const __nv_bfloat16* __restrict__ Ql_g,
               const __nv_bfloat16* __restrict__ Kh_g, const __nv_bfloat16* __restrict__ Kl_g,
               const __nv_bfloat16* __restrict__ Vh_g, const __nv_bfloat16* __restrict__ Vl_g,
               const float* __restrict__ aK, const float* __restrict__ aV,
               const float* __restrict__ gate,
               __nv_bfloat16* __restrict__ Oh, __nv_bfloat16* __restrict__ Ol)
{
    extern __shared__ char sm[];
    const uint32_t base = smem_u32(sm);
    const int tid  = threadIdx.x;
    const int wid  = tid >> 5;
    const int lane = tid & 31;
    // heavy tiles first: reverse qt so the longest-running CTAs launch early
    const int qt = (int)gridDim.x - 1 - (int)blockIdx.x;
    const int h = blockIdx.y, b = blockIdx.z;
    const int nkt = 2 * qt + 2;

    const uint32_t sQh = base;
    const uint32_t sKV = base + 2 * FQ_TILE;
    float* aKs = (float*)(sm + FAK_OFF);
    float* aVs = aKs + ADL_ * D_;

    {
        size_t gq = ((size_t)(b * S_) + qt * 128) * DIM_ + h * D_;
#pragma unroll
        for (int i = 0; i < 8; i++) {
            int idx = tid + i * 256;
            int row = idx >> 4, ch = idx & 15;
            uint32_t d = row * FRSTR + ch * 16;
            size_t src = gq + (size_t)row * DIM_ + ch * 8;
            CP_ASYNC16(sQh + d,           Qh_g + src);
            CP_ASYNC16(sQh + FQ_TILE + d, Ql_g + src);
        }
        for (int idx = tid; idx < ADL_ * D_; idx += 256) {
            int t = idx >> 7, cc = idx & (D_ - 1);
            aKs[idx] = aK[t * DIM_ + h * D_ + cc];
            aVs[idx] = aV[t * DIM_ + h * D_ + cc];
        }
    }
    fkv_fill(sKV, Kh_g, Kl_g, Vh_g, Vl_g, b, h, 0);
    CP_COMMIT();

    const int q0  = qt * 128 + wid * 16;
    const int qg0 = q0 + (lane >> 2);
    const int qg1 = qg0 + 8;
    const float scl = 0.08838834764831845f;

    float m0 = -1e30f, m1 = -1e30f, l0 = 0.f, l1 = 0.f;
    float o[16][4];
#pragma unroll
    for (int d = 0; d < 16; d++)
#pragma unroll
        for (int q = 0; q < 4; q++) o[d][q] = 0.f;

    const uint32_t kh16 = (uint32_t)((lane >> 4) * 16);

    for (int kt = 0; kt < nkt; kt++) {
        if (kt + 1 < nkt)
            fkv_fill(sKV + ((kt + 1) & 1) * FSTAGE,
                     Kh_g, Kl_g, Vh_g, Vl_g, b, h, (kt + 1) * 64);
        CP_COMMIT();
        CP_WAIT(1);
        __syncthreads();

        const uint32_t st = sKV + (uint32_t)(kt & 1) * FSTAGE;
        const int kv0 = kt * 64;

        if (kv0 <= q0 + 15) {
            float sa[8][4];
#pragma unroll
            for (int n8 = 0; n8 < 8; n8++)
#pragma unroll
                for (int q = 0; q < 4; q++) sa[n8][q] = 0.f;

            const uint32_t qrow = (uint32_t)(wid * 16 + (lane & 15));
            const uint32_t klrow = (uint32_t)(lane & 15);

#pragma unroll
            for (int ch = 0; ch < 8; ch++) {
                uint32_t qa = sQh + qrow * FRSTR + ch * 32 + kh16;
                uint32_t qh[4], ql[4];
                LDSM_X4(qh[0], qh[1], qh[2], qh[3], qa);
                LDSM_X4(ql[0], ql[1], ql[2], ql[3], qa + FQ_TILE);
                uint32_t kb[8][2], lb[8][2];
#pragma unroll
                for (int nb = 0; nb < 4; nb++) {
                    uint32_t ka = st + (klrow + nb * 16) * FRSTR + ch * 32 + kh16;
                    uint32_t r0, r1, r2, r3;
                    LDSM_X4(r0, r1, r2, r3, ka);
                    kb[2 * nb][0] = r0; kb[2 * nb][1] = r2;
                    kb[2 * nb + 1][0] = r1; kb[2 * nb + 1][1] = r3;
                    LDSM_X4(r0, r1, r2, r3, ka + FK_TILE);
                    lb[2 * nb][0] = r0; lb[2 * nb][1] = r2;
                    lb[2 * nb + 1][0] = r1; lb[2 * nb + 1][1] = r3;
                }
#pragma unroll
                for (int n8 = 0; n8 < 8; n8++) MMA16816(sa[n8], qh, kb[n8]);
#pragma unroll
                for (int n8 = 0; n8 < 8; n8++) MMA16816(sa[n8], qh, lb[n8]);
#pragma unroll
                for (int n8 = 0; n8 < 8; n8++) MMA16816(sa[n8], ql, kb[n8]);
            }

            float rmax0 = -1e30f, rmax1 = -1e30f;
            const int kvb = kv0 + (lane & 3) * 2;
#pragma unroll
            for (int n8 = 0; n8 < 8; n8++) {
                int kvc = kvb + n8 * 8;
                float s0 = sa[n8][0] * scl, s1 = sa[n8][1] * scl;
                float s2 = sa[n8][2] * scl, s3 = sa[n8][3] * scl;
                if (kvc     > qg0) s0 = -1e30f;
                if (kvc + 1 > qg0) s1 = -1e30f;
                if (kvc     > qg1) s2 = -1e30f;
                if (kvc + 1 > qg1) s3 = -1e30f;
                sa[n8][0] = s0; sa[n8][1] = s1; sa[n8][2] = s2; sa[n8][3] = s3;
                rmax0 = fmaxf(rmax0, fmaxf(s0, s1));
                rmax1 = fmaxf(rmax1, fmaxf(s2, s3));
            }
            rmax0 = fmaxf(rmax0, __shfl_xor_sync(0xffffffffu, rmax0, 1));
            rmax0 = fmaxf(rmax0, __shfl_xor_sync(0xffffffffu, rmax0, 2));
            rmax1 = fmaxf(rmax1, __shfl_xor_sync(0xffffffffu, rmax1, 1));
            rmax1 = fmaxf(rmax1, __shfl_xor_sync(0xffffffffu, rmax1, 2));

            float mn0 = fmaxf(m0, rmax0), mn1 = fmaxf(m1, rmax1);
            float sc0 = __expf(m0 - mn0), sc1 = __expf(m1 - mn1);
            m0 = mn0; m1 = mn1;

            uint32_t ph[16], pl[16];
            float rs0 = 0.f, rs1 = 0.f;
#pragma unroll
            for (int n8 = 0; n8 < 8; n8++) {
                float p0 = __expf(sa[n8][0] - mn0);
                float p1 = __expf(sa[n8][1] - mn0);
                float p2 = __expf(sa[n8][2] - mn1);
                float p3 = __expf(sa[n8][3] - mn1);
                rs0 += p0 + p1; rs1 += p2 + p3;
                float h0 = __bfloat162float(__float2bfloat16(p0));
                float h1 = __bfloat162float(__float2bfloat16(p1));
                float h2 = __bfloat162float(__float2bfloat16(p2));
                float h3 = __bfloat162float(__float2bfloat16(p3));
                ph[2 * n8]     = pack_bf16x2(h0, h1);
                ph[2 * n8 + 1] = pack_bf16x2(h2, h3);
                pl[2 * n8]     = pack_bf16x2(p0 - h0, p1 - h1);
                pl[2 * n8 + 1] = pack_bf16x2(p2 - h2, p3 - h3);
            }
            rs0 += __shfl_xor_sync(0xffffffffu, rs0, 1);
            rs0 += __shfl_xor_sync(0xffffffffu, rs0, 2);
            rs1 += __shfl_xor_sync(0xffffffffu, rs1, 1);
            rs1 += __shfl_xor_sync(0xffffffffu, rs1, 2);
            l0 = l0 * sc0 + rs0;
            l1 = l1 * sc1 + rs1;

#pragma unroll
            for (int d = 0; d < 16; d++) {
                o[d][0] *= sc0; o[d][1] *= sc0;
                o[d][2] *= sc1; o[d][3] *= sc1;
            }

            // ---- O += P V, chain-broken: halves of V columns, 3 passes ----
#pragma unroll
            for (int j = 0; j < 4; j++) {
                uint32_t ah[4] = {ph[4*j], ph[4*j+1], ph[4*j+2], ph[4*j+3]};
                uint32_t al[4] = {pl[4*j], pl[4*j+1], pl[4*j+2], pl[4*j+3]};
#pragma unroll
                for (int half = 0; half < 2; half++) {
                    uint32_t vh[8][2], vl[8][2];
#pragma unroll
                    for (int k = 0; k < 4; k++) {
                        int nb = half * 4 + k;
                        uint32_t va = st + 2 * FK_TILE +
                                      (uint32_t)(j * 16 + (lane & 15)) * FRSTR +
                                      nb * 32 + kh16;
                        uint32_t r0, r1, r2, r3;
                        LDSM_X4_T(r0, r1, r2, r3, va);
                        vh[2 * k][0] = r0; vh[2 * k][1] = r1;
                        vh[2 * k + 1][0] = r2; vh[2 * k + 1][1] = r3;
                        LDSM_X4_T(r0, r1, r2, r3, va + FK_TILE);
                        vl[2 * k][0] = r0; vl[2 * k][1] = r1;
                        vl[2 * k + 1][0] = r2; vl[2 * k + 1][1] = r3;
                    }
                    const int ob = half * 8;
#pragma unroll
                    for (int n = 0; n < 8; n++) MMA16816(o[ob + n], ah, vh[n]);
#pragma unroll
                    for (int n = 0; n < 8; n++) MMA16816(o[ob + n], ah, vl[n]);
#pragma unroll
                    for (int n = 0; n < 8; n++) MMA16816(o[ob + n], al, vh[n]);
                }
            }
        }
        __syncthreads();
    }

    // ---- epilogue: fused adapter attention + bf16 split store ----
    const float g = tanhf(gate[h]);
    const float inv0 = 1.0f / l0, inv1 = 1.0f / l1;
    const int ccb = (lane & 3) * 2;

#pragma unroll
    for (int rr = 0; rr < 2; rr++) {
        const int lr = wid * 16 + (lane >> 2) + rr * 8;
        const float inv = rr ? inv1 : inv0;
        const size_t rowg = (size_t)(b * S_) + qt * 128 + lr;

        float qv[32];
#pragma unroll
        for (int d = 0; d < 16; d++) {
            int cc = d * 8 + ccb;
            __nv_bfloat162 hh = *(__nv_bfloat162*)(sm + lr * FRSTR + cc * 2);
            __nv_bfloat162 ll = *(__nv_bfloat162*)(sm + FQ_TILE + lr * FRSTR + cc * 2);
            qv[2 * d]     = __bfloat162float(hh.x) + __bfloat162float(ll.x);
            qv[2 * d + 1] = __bfloat162float(hh.y) + __bfloat162float(ll.y);
        }
        float sc[ADL_];
#pragma unroll
        for (int t = 0; t < ADL_; t++) {
            float p = 0.f;
#pragma unroll
            for (int d = 0; d < 16; d++) {
                int cc = d * 8 + ccb;
                p = fmaf(qv[2 * d],     aKs[t * D_ + cc],     p);
                p = fmaf(qv[2 * d + 1], aKs[t * D_ + cc + 1], p);
            }
            p += __shfl_xor_sync(0xffffffffu, p, 1);
            p += __shfl_xor_sync(0xffffffffu, p, 2);
            sc[t] = p * scl;
        }
        float mx = sc[0];
#pragma unroll
        for (int t = 1; t < ADL_; t++) mx = fmaxf(mx, sc[t]);
        float sum = 0.f;
#pragma unroll
        for (int t = 0; t < ADL_; t++) { sc[t] = __expf(sc[t] - mx); sum += sc[t]; }
        float isum = g / sum;
#pragma unroll
        for (int t = 0; t < ADL_; t++) sc[t] *= isum;

#pragma unroll
        for (int d = 0; d < 16; d++) {
            int cc = d * 8 + ccb;
            float a0 = 0.f, a1 = 0.f;
#pragma unroll
            for (int t = 0; t < ADL_; t++) {
                a0 = fmaf(sc[t], aVs[t * D_ + cc],     a0);
                a1 = fmaf(sc[t], aVs[t * D_ + cc + 1], a1);
            }
            float o0 = o[d][rr * 2]     * inv + a0;
            float o1 = o[d][rr * 2 + 1] * inv + a1;
            split_store(Oh, Ol, rowg * DIM_ + h * D_ + cc, o0, o1);
        }
    }
}

// ============================================================================
// launch
// ============================================================================
extern "C" void kernel_launch(void* const* d_in, const int* in_sizes, int n_in,
                              void* d_out, int out_size)
{
    const float* x       = (const float*)d_in[0];
    const float* wq      = (const float*)d_in[1];
    const float* wk      = (const float*)d_in[2];
    const float* wv      = (const float*)d_in[3];
    const float* wo      = (const float*)d_in[4];
    const float* gate    = (const float*)d_in[5];
    const float* adapter = (const float*)d_in[6];
    const float* fcos    = (const float*)d_in[7];
    const float* fsin    = (const float*)d_in[8];
    float* out = (float*)d_out;

    float *aKp, *aVp;
    cudaGetSymbolAddress((void**)&aKp, g_aK);
    cudaGetSymbolAddress((void**)&aVp, g_aV);

    __nv_bfloat16 *xh, *xl, *wqh, *wql, *wkh, *wkl, *wvh, *wvl, *woh, *wol;
    __nv_bfloat16 *qh, *ql, *kh, *kl, *vh, *vl, *oh, *ol;
    cudaGetSymbolAddress((void**)&xh,  g_xh);  cudaGetSymbolAddress((void**)&xl,  g_xl);
    cudaGetSymbolAddress((void**)&wqh, g_wqh); cudaGetSymbolAddress((void**)&wql, g_wql);
    cudaGetSymbolAddress((void**)&wkh, g_wkh); cudaGetSymbolAddress((void**)&wkl, g_wkl);
    cudaGetSymbolAddress((void**)&wvh, g_wvh); cudaGetSymbolAddress((void**)&wvl, g_wvl);
    cudaGetSymbolAddress((void**)&woh, g_woh); cudaGetSymbolAddress((void**)&wol, g_wol);
    cudaGetSymbolAddress((void**)&qh,  g_qh);  cudaGetSymbolAddress((void**)&ql,  g_ql);
    cudaGetSymbolAddress((void**)&kh,  g_kh);  cudaGetSymbolAddress((void**)&kl,  g_kl);
    cudaGetSymbolAddress((void**)&vh,  g_vh);  cudaGetSymbolAddress((void**)&vl,  g_vl);
    cudaGetSymbolAddress((void**)&oh,  g_oh);  cudaGetSymbolAddress((void**)&ol,  g_ol);

    cudaFuncSetAttribute(mma_gemm,
                         cudaFuncAttributeMaxDynamicSharedMemorySize, GK_SMEM);
    cudaFuncSetAttribute(qkv_gemm,
                         cudaFuncAttributeMaxDynamicSharedMemorySize, GK_SMEM);
    cudaFuncSetAttribute(flash_mma,
                         cudaFuncAttributeMaxDynamicSharedMemorySize, FLASH_SMEM);

    split5<<<dim3(NELEM / 4 / 256, 5), 256>>>(x, wq, wk, wv, wo,
        xh, xl, wqh, wql, wkh, wkl, wvh, wvl, woh, wol);

    adapter_gemv<<<128, 256>>>(adapter, wk, aKp);
    adapter_gemv<<<128, 256>>>(adapter, wv, aVp);

    qkv_gemm<<<dim3(DIM_ / 128, MROWS / 128, 3), 256, GK_SMEM>>>(
        xh, xl, wqh, wql, wkh, wkl, wvh, wvl,
        qh, ql, kh, kl, vh, vl, fcos, fsin);

    flash_mma<<<dim3(S_ / 128, H_, B_), 256, FLASH_SMEM>>>(
        qh, ql, kh, kl, vh, vl, aKp, aVp, gate, oh, ol);

    mma_gemm<<<dim3(DIM_ / 128, MROWS / 128), 256, GK_SMEM>>>(
        oh, ol, woh, wol, out);
}

// round 11
// speedup vs baseline: 1.0968x; 1.0027x over previous
#include <cuda_runtime.h>
#include <cuda_bf16.h>
#include <math.h>
#include <stdint.h>

// ---------------------------------------------------------------- constants
#define B_    2
#define S_    2048
#define H_    32
#define D_    128
#define DIM_  4096
#define ADL_  10
#define MROWS (B_ * S_)
#define NELEM ((size_t)MROWS * DIM_)

// ---------------------------------------------------------------- scratch
__device__ float g_aK[ADL_ * DIM_];
__device__ float g_aV[ADL_ * DIM_];

__device__ __nv_bfloat16 g_xh[NELEM],  g_xl[NELEM];
__device__ __nv_bfloat16 g_wqh[NELEM], g_wql[NELEM];
__device__ __nv_bfloat16 g_wkh[NELEM], g_wkl[NELEM];
__device__ __nv_bfloat16 g_wvh[NELEM], g_wvl[NELEM];
__device__ __nv_bfloat16 g_woh[NELEM], g_wol[NELEM];
__device__ __nv_bfloat16 g_qh[NELEM],  g_ql[NELEM];
__device__ __nv_bfloat16 g_kh[NELEM],  g_kl[NELEM];
__device__ __nv_bfloat16 g_vh[NELEM],  g_vl[NELEM];
__device__ __nv_bfloat16 g_oh[NELEM],  g_ol[NELEM];

// ---------------------------------------------------------------- PTX utils
__device__ __forceinline__ uint32_t smem_u32(const void* p) {
    uint32_t a;
    asm("{ .reg .u64 t; cvta.to.shared.u64 t, %1; cvt.u32.u64 %0, t; }"
        : "=r"(a) : "l"(p));
    return a;
}
#define CP_ASYNC16(dst, src) \
    asm volatile("cp.async.cg.shared.global [%0], [%1], 16;" \
                 :: "r"(dst), "l"(src) : "memory")
#define CP_COMMIT() asm volatile("cp.async.commit_group;" ::: "memory")
#define CP_WAIT(n)  asm volatile("cp.async.wait_group %0;" :: "n"(n) : "memory")

#define LDSM_X4(r0, r1, r2, r3, addr) \
    asm volatile("ldmatrix.sync.aligned.m8n8.x4.shared.b16 {%0,%1,%2,%3}, [%4];" \
                 : "=r"(r0), "=r"(r1), "=r"(r2), "=r"(r3) : "r"(addr))
#define LDSM_X4_T(r0, r1, r2, r3, addr) \
    asm volatile("ldmatrix.sync.aligned.m8n8.x4.trans.shared.b16 {%0,%1,%2,%3}, [%4];" \
                 : "=r"(r0), "=r"(r1), "=r"(r2), "=r"(r3) : "r"(addr))

#define MMA16816(c, a, b) \
    asm volatile("mma.sync.aligned.m16n8k16.row.col.f32.bf16.bf16.f32 " \
                 "{%0,%1,%2,%3}, {%4,%5,%6,%7}, {%8,%9}, {%0,%1,%2,%3};" \
                 : "+f"((c)[0]), "+f"((c)[1]), "+f"((c)[2]), "+f"((c)[3]) \
                 : "r"((a)[0]), "r"((a)[1]), "r"((a)[2]), "r"((a)[3]), \
                   "r"((b)[0]), "r"((b)[1]))

__device__ __forceinline__ uint32_t pack_bf16x2(float lo, float hi) {
    __nv_bfloat162 t = __floats2bfloat162_rn(lo, hi);
    return *(uint32_t*)&t;
}
__device__ __forceinline__ void split_store(__nv_bfloat16* Xh, __nv_bfloat16* Xl,
                                            size_t off, float v0, float v1) {
    __nv_bfloat16 h0 = __float2bfloat16(v0);
    __nv_bfloat16 h1 = __float2bfloat16(v1);
    __nv_bfloat16 l0 = __float2bfloat16(v0 - __bfloat162float(h0));
    __nv_bfloat16 l1 = __float2bfloat16(v1 - __bfloat162float(h1));
    *(__nv_bfloat162*)(Xh + off) = __nv_bfloat162(h0, h1);
    *(__nv_bfloat162*)(Xl + off) = __nv_bfloat162(l0, l1);
}

// ============================================================================
// GEMM core: bf16x3 HMMA, 128x128 CTA tile, BK=32, 2-stage cp.async, 2 CTA/SM
// (R10 best config — unchanged)
// ============================================================================
#define GK_BK      32
#define GK_TILE_B  10240
#define GK_STAGE_B (4 * GK_TILE_B)
#define GK_STAGES  2
#define GK_SMEM    (GK_STAGES * GK_STAGE_B)
#define GK_NIT     (DIM_ / GK_BK)

__device__ __forceinline__ void gk_fill(uint32_t sbase,
    const __nv_bfloat16* __restrict__ Ah, const __nv_bfloat16* __restrict__ Al,
    const __nv_bfloat16* __restrict__ Bh, const __nv_bfloat16* __restrict__ Bl,
    int rowBase, int colBase, int k0)
{
    const int tid = threadIdx.x;
#pragma unroll
    for (int i = 0; i < 2; i++) {
        int idx = tid + i * 256;
        int row = idx >> 2;
        int cg  = (idx & 3) * 8;
        uint32_t doff = (uint32_t)(row * 80 + (idx & 3) * 16);
        size_t ga = (size_t)(rowBase + row) * DIM_ + k0 + cg;
        size_t gb = (size_t)(colBase + row) * DIM_ + k0 + cg;
        CP_ASYNC16(sbase + doff,                 Ah + ga);
        CP_ASYNC16(sbase + GK_TILE_B + doff,     Al + ga);
        CP_ASYNC16(sbase + 2 * GK_TILE_B + doff, Bh + gb);
        CP_ASYNC16(sbase + 3 * GK_TILE_B + doff, Bl + gb);
    }
}

#define GK_MAINLOOP(Ah, Al, Bh, Bl)                                            \
    gk_fill(base, Ah, Al, Bh, Bl, rowBase, colBase, 0);                        \
    CP_COMMIT();                                                               \
    const uint32_t aRow = (uint32_t)(wm + (lane & 15));                        \
    const uint32_t bRow = (uint32_t)(wn + (lane & 15));                        \
    const uint32_t kHalf = (uint32_t)((lane >> 4) * 16);                       \
    for (int it = 0; it < GK_NIT; it++) {                                      \
        CP_WAIT(0);                                                            \
        __syncthreads();                                                       \
        if (it + 1 < GK_NIT)                                                   \
            gk_fill(base + (uint32_t)((it + 1) & 1) * GK_STAGE_B,              \
                    Ah, Al, Bh, Bl, rowBase, colBase, (it + 1) * GK_BK);       \
        CP_COMMIT();                                                           \
        const uint32_t sb = base + (uint32_t)(it & 1) * GK_STAGE_B;            \
        _Pragma("unroll")                                                      \
        for (int ks = 0; ks < 2; ks++) {                                       \
            const uint32_t kcol = (uint32_t)(ks * 32) + kHalf;                 \
            uint32_t ah[4][4], al[4][4], bh[4][2], bl[4][2];                   \
            _Pragma("unroll")                                                  \
            for (int mi = 0; mi < 4; mi++) {                                   \
                uint32_t off = (aRow + mi * 16) * 80 + kcol;                   \
                LDSM_X4(ah[mi][0], ah[mi][1], ah[mi][2], ah[mi][3], sb + off); \
                LDSM_X4(al[mi][0], al[mi][1], al[mi][2], al[mi][3],            \
                        sb + GK_TILE_B + off);                                 \
            }                                                                  \
            _Pragma("unroll")                                                  \
            for (int np = 0; np < 2; np++) {                                   \
                uint32_t off = (bRow + np * 16) * 80 + kcol;                   \
                uint32_t r0, r1, r2, r3;                                       \
                LDSM_X4(r0, r1, r2, r3, sb + 2 * GK_TILE_B + off);             \
                bh[2 * np][0] = r0; bh[2 * np][1] = r2;                        \
                bh[2 * np + 1][0] = r1; bh[2 * np + 1][1] = r3;                \
                LDSM_X4(r0, r1, r2, r3, sb + 3 * GK_TILE_B + off);             \
                bl[2 * np][0] = r0; bl[2 * np][1] = r2;                        \
                bl[2 * np + 1][0] = r1; bl[2 * np + 1][1] = r3;                \
            }                                                                  \
            _Pragma("unroll")                                                  \
            for (int mi = 0; mi < 4; mi++)                                     \
                _Pragma("unroll")                                              \
                for (int ni = 0; ni < 4; ni++)                                 \
                    MMA16816(acc[mi][ni], ah[mi], bh[ni]);                     \
            _Pragma("unroll")                                                  \
            for (int mi = 0; mi < 4; mi++)                                     \
                _Pragma("unroll")                                              \
                for (int ni = 0; ni < 4; ni++)                                 \
                    MMA16816(acc[mi][ni], ah[mi], bl[ni]);                     \
            _Pragma("unroll")                                                  \
            for (int mi = 0; mi < 4; mi++)                                     \
                _Pragma("unroll")                                              \
                for (int ni = 0; ni < 4; ni++)                                 \
                    MMA16816(acc[mi][ni], al[mi], bh[ni]);                     \
        }                                                                      \
    }

// --------- final output GEMM: fp32 C ---------
__global__ __launch_bounds__(256, 2)
void mma_gemm(const __nv_bfloat16* __restrict__ Ah, const __nv_bfloat16* __restrict__ Al,
              const __nv_bfloat16* __restrict__ Bh, const __nv_bfloat16* __restrict__ Bl,
              float* __restrict__ C)
{
    extern __shared__ char sm[];
    const uint32_t base = smem_u32(sm);
    const int lane = threadIdx.x & 31;
    const int wid  = threadIdx.x >> 5;
    const int rowBase = blockIdx.y * 128;
    const int colBase = blockIdx.x * 128;
    const int wm = (wid & 1) * 64;
    const int wn = (wid >> 1) * 32;

    float acc[4][4][4];
#pragma unroll
    for (int mi = 0; mi < 4; mi++)
#pragma unroll
        for (int ni = 0; ni < 4; ni++)
#pragma unroll
            for (int q = 0; q < 4; q++) acc[mi][ni][q] = 0.f;

    GK_MAINLOOP(Ah, Al, Bh, Bl)

    const int r0 = rowBase + wm + (lane >> 2);
    const int c0 = colBase + wn + (lane & 3) * 2;
#pragma unroll
    for (int mi = 0; mi < 4; mi++)
#pragma unroll
        for (int ni = 0; ni < 4; ni++) {
            float* p = C + (size_t)(r0 + mi * 16) * DIM_ + c0 + ni * 8;
            *(float2*)p = make_float2(acc[mi][ni][0], acc[mi][ni][1]);
            *(float2*)(p + 8 * DIM_) = make_float2(acc[mi][ni][2], acc[mi][ni][3]);
        }
}

// --------- QKV GEMM: z selects weights/output; rope fused for z<2 ---------
__global__ __launch_bounds__(256, 2)
void qkv_gemm(const __nv_bfloat16* __restrict__ Ah, const __nv_bfloat16* __restrict__ Al,
              const __nv_bfloat16* __restrict__ Bqh, const __nv_bfloat16* __restrict__ Bql,
              const __nv_bfloat16* __restrict__ Bkh, const __nv_bfloat16* __restrict__ Bkl,
              const __nv_bfloat16* __restrict__ Bvh, const __nv_bfloat16* __restrict__ Bvl,
              __nv_bfloat16* __restrict__ Qh, __nv_bfloat16* __restrict__ Ql,
              __nv_bfloat16* __restrict__ Kh, __nv_bfloat16* __restrict__ Kl,
              __nv_bfloat16* __restrict__ Vh, __nv_bfloat16* __restrict__ Vl,
              const float* __restrict__ fcos, const float* __restrict__ fsin)
{
    extern __shared__ char sm[];
    const uint32_t base = smem_u32(sm);
    const int lane = threadIdx.x & 31;
    const int wid  = threadIdx.x >> 5;
    const int rowBase = blockIdx.y * 128;
    const int colBase = blockIdx.x * 128;
    const int wm = (wid & 1) * 64;
    const int wn = (wid >> 1) * 32;
    const int z = blockIdx.z;

    const __nv_bfloat16* Bh = (z == 0) ? Bqh : (z == 1) ? Bkh : Bvh;
    const __nv_bfloat16* Bl = (z == 0) ? Bql : (z == 1) ? Bkl : Bvl;
    __nv_bfloat16* Xh = (z == 0) ? Qh : (z == 1) ? Kh : Vh;
    __nv_bfloat16* Xl = (z == 0) ? Ql : (z == 1) ? Kl : Vl;
    const bool dorope = (z < 2);

    float acc[4][4][4];
#pragma unroll
    for (int mi = 0; mi < 4; mi++)
#pragma unroll
        for (int ni = 0; ni < 4; ni++)
#pragma unroll
            for (int q = 0; q < 4; q++) acc[mi][ni][q] = 0.f;

    GK_MAINLOOP(Ah, Al, Bh, Bl)

    const int r0 = rowBase + wm + (lane >> 2);
    const int c0 = colBase + wn + (lane & 3) * 2;
#pragma unroll
    for (int mi = 0; mi < 4; mi++) {
        int r  = r0 + mi * 16;
        int s1 = r & (S_ - 1);
        int s2 = (r + 8) & (S_ - 1);
#pragma unroll
        for (int ni = 0; ni < 4; ni++) {
            int c = c0 + ni * 8;
            float v0 = acc[mi][ni][0], v1 = acc[mi][ni][1];
            float v2 = acc[mi][ni][2], v3 = acc[mi][ni][3];
            if (dorope) {
                int i = (c & (D_ - 1)) >> 1;
                float c1 = fcos[s1 * 64 + i], n1 = fsin[s1 * 64 + i];
                float c2 = fcos[s2 * 64 + i], n2 = fsin[s2 * 64 + i];
                float t;
                t = v0 * c1 - v1 * n1; v1 = v0 * n1 + v1 * c1; v0 = t;
                t = v2 * c2 - v3 * n2; v3 = v2 * n2 + v3 * c2; v2 = t;
            }
            split_store(Xh, Xl, (size_t)r * DIM_ + c, v0, v1);
            split_store(Xh, Xl, (size_t)(r + 8) * DIM_ + c, v2, v3);
        }
    }
}

// ============================================================================
// split5: one launch splits x, wq, wk, wv, wo
// ============================================================================
__global__ void split5(const float* __restrict__ x,  const float* __restrict__ wq,
                       const float* __restrict__ wk, const float* __restrict__ wv,
                       const float* __restrict__ wo,
                       __nv_bfloat16* xh,  __nv_bfloat16* xl,
                       __nv_bfloat16* qh,  __nv_bfloat16* ql,
                       __nv_bfloat16* kh,  __nv_bfloat16* kl,
                       __nv_bfloat16* vh,  __nv_bfloat16* vl,
                       __nv_bfloat16* oh,  __nv_bfloat16* ol)
{
    const float* src; __nv_bfloat16 *hi, *lo;
    switch (blockIdx.y) {
        case 0: src = x;  hi = xh; lo = xl; break;
        case 1: src = wq; hi = qh; lo = ql; break;
        case 2: src = wk; hi = kh; lo = kl; break;
        case 3: src = wv; hi = vh; lo = vl; break;
        default: src = wo; hi = oh; lo = ol; break;
    }
    size_t i = (size_t)blockIdx.x * blockDim.x + threadIdx.x;
    float4 v = ((const float4*)src)[i];
    __nv_bfloat16 h0 = __float2bfloat16(v.x);
    __nv_bfloat16 h1 = __float2bfloat16(v.y);
    __nv_bfloat16 h2 = __float2bfloat16(v.z);
    __nv_bfloat16 h3 = __float2bfloat16(v.w);
    ((__nv_bfloat162*)hi)[2 * i]     = __nv_bfloat162(h0, h1);
    ((__nv_bfloat162*)hi)[2 * i + 1] = __nv_bfloat162(h2, h3);
    ((__nv_bfloat162*)lo)[2 * i] = __nv_bfloat162(
        __float2bfloat16(v.x - __bfloat162float(h0)),
        __float2bfloat16(v.y - __bfloat162float(h1)));
    ((__nv_bfloat162*)lo)[2 * i + 1] = __nv_bfloat162(
        __float2bfloat16(v.z - __bfloat162float(h2)),
        __float2bfloat16(v.w - __bfloat162float(h3)));
}

// ============================================================================
// adapter GEMV (fp32)
// ============================================================================
__global__ __launch_bounds__(256)
void adapter_gemv(const float* __restrict__ A, const float* __restrict__ W,
                  float* __restrict__ out)
{
    int warp = (blockIdx.x * blockDim.x + threadIdx.x) >> 5;
    int lane = threadIdx.x & 31;
    int e0 = warp * 4;

    float acc[ADL_][4];
#pragma unroll
    for (int l = 0; l < ADL_; l++)
#pragma unroll
        for (int j = 0; j < 4; j++) acc[l][j] = 0.f;

    for (int d = lane * 4; d < DIM_; d += 128) {
        float4 w4[4];
#pragma unroll
        for (int j = 0; j < 4; j++)
            w4[j] = *(const float4*)(W + (size_t)(e0 + j) * DIM_ + d);
#pragma unroll
        for (int l = 0; l < ADL_; l++) {
            float4 a4 = *(const float4*)(A + (size_t)l * DIM_ + d);
#pragma unroll
            for (int j = 0; j < 4; j++) {
                acc[l][j] = fmaf(a4.x, w4[j].x, acc[l][j]);
                acc[l][j] = fmaf(a4.y, w4[j].y, acc[l][j]);
                acc[l][j] = fmaf(a4.z, w4[j].z, acc[l][j]);
                acc[l][j] = fmaf(a4.w, w4[j].w, acc[l][j]);
            }
        }
    }
#pragma unroll
    for (int l = 0; l < ADL_; l++)
#pragma unroll
        for (int j = 0; j < 4; j++) {
            float v = acc[l][j];
#pragma unroll
            for (int off = 16; off; off >>= 1)
                v += __shfl_xor_sync(0xffffffffu, v, off);
            if (lane == 0) out[l * DIM_ + e0 + j] = v;
        }
}

// ============================================================================
// Flash attention (HMMA bf16x3), occ-2 redesign:
// 64 q-rows/CTA, 128 threads (4 warps x 16 rows), single-buffered 64-row KV
// tile (cross-CTA latency hiding), adapter staged into dead KV smem at
// epilogue. smem = 104448 B -> 2 CTAs/SM.
// ============================================================================
#define FRSTR   272
#define FQ_TILE (64 * FRSTR)             // 17408
#define FK_TILE (64 * FRSTR)             // 17408
#define FSTAGE  (4 * FK_TILE)            // 69632
#define FLASH_SMEM (2 * FQ_TILE + FSTAGE)    // 104448

__device__ __forceinline__ void fkv_fill(uint32_t sdst,
    const __nv_bfloat16* __restrict__ Kh, const __nv_bfloat16* __restrict__ Kl,
    const __nv_bfloat16* __restrict__ Vh, const __nv_bfloat16* __restrict__ Vl,
    int b, int h, int kv0)
{
    const int tid = threadIdx.x;
    const size_t gbase = ((size_t)(b * S_) + kv0) * DIM_ + h * D_;
#pragma unroll
    for (int i = 0; i < 32; i++) {
        int idx = tid + i * 128;              // 0..4095
        int arr = idx >> 10;                  // Kh,Kl,Vh,Vl
        int rem = idx & 1023;
        int row = rem >> 4;
        int ch  = rem & 15;
        const __nv_bfloat16* src =
            (arr == 0) ? Kh : (arr == 1) ? Kl : (arr == 2) ? Vh : Vl;
        CP_ASYNC16(sdst + arr * FK_TILE + row * FRSTR + ch * 16,
                   src + gbase + (size_t)row * DIM_ + ch * 8);
    }
}

__global__ __launch_bounds__(128, 2)
void flash_mma(const __nv_bfloat16* __restrict__ Qh_g, const __nv_bfloat16* __restrict__ Ql_g,
               const __nv_bfloat16* __restrict__ Kh_g, const __nv_bfloat16* __restrict__ Kl_g,
               const __nv_bfloat16* __restrict__ Vh_g, const __nv_bfloat16* __restrict__ Vl_g,
               const float* __restrict__ aK, const float* __restrict__ aV,
               const float* __restrict__ gate,
               __nv_bfloat16* __restrict__ Oh, __nv_bfloat16* __restrict__ Ol)
{
    extern __shared__ char sm[];
    const uint32_t base = smem_u32(sm);
    const int tid  = threadIdx.x;
    const int wid  = tid >> 5;        // 0..3
    const int lane = tid & 31;
    // heavy tiles first
    const int qt = (int)gridDim.x - 1 - (int)blockIdx.x;
    const int h = blockIdx.y, b = blockIdx.z;
    const int nkt = qt + 1;           // 64-row kv tiles

    const uint32_t sQh = base;                    // Qh: 64 x 272
    const uint32_t sKV = base + 2 * FQ_TILE;      // Kh,Kl,Vh,Vl single stage

    // Q tile fill (64 rows, hi+lo)
    {
        size_t gq = ((size_t)(b * S_) + qt * 64) * DIM_ + h * D_;
#pragma unroll
        for (int i = 0; i < 8; i++) {
            int idx = tid + i * 128;      // 0..1023
            int row = idx >> 4, ch = idx & 15;
            uint32_t d = row * FRSTR + ch * 16;
            size_t src = gq + (size_t)row * DIM_ + ch * 8;
            CP_ASYNC16(sQh + d,           Qh_g + src);
            CP_ASYNC16(sQh + FQ_TILE + d, Ql_g + src);
        }
    }
    fkv_fill(sKV, Kh_g, Kl_g, Vh_g, Vl_g, b, h, 0);
    CP_COMMIT();

    const int q0  = qt * 64 + wid * 16;
    const int qg0 = q0 + (lane >> 2);
    const int qg1 = qg0 + 8;
    const float scl = 0.08838834764831845f;

    float m0 = -1e30f, m1 = -1e30f, l0 = 0.f, l1 = 0.f;
    float o[16][4];
#pragma unroll
    for (int d = 0; d < 16; d++)
#pragma unroll
        for (int q = 0; q < 4; q++) o[d][q] = 0.f;

    const uint32_t kh16 = (uint32_t)((lane >> 4) * 16);

    for (int kt = 0; kt < nkt; kt++) {
        CP_WAIT(0);
        __syncthreads();

        const uint32_t st = sKV;
        const int kv0 = kt * 64;

        // ---- S = Q K^T (chain-broken bf16x3) ----
        float sa[8][4];
#pragma unroll
        for (int n8 = 0; n8 < 8; n8++)
#pragma unroll
            for (int q = 0; q < 4; q++) sa[n8][q] = 0.f;

        const uint32_t qrow = (uint32_t)(wid * 16 + (lane & 15));
        const uint32_t klrow = (uint32_t)(lane & 15);

#pragma unroll
        for (int ch = 0; ch < 8; ch++) {
            uint32_t qa = sQh + qrow * FRSTR + ch * 32 + kh16;
            uint32_t qh[4], ql[4];
            LDSM_X4(qh[0], qh[1], qh[2], qh[3], qa);
            LDSM_X4(ql[0], ql[1], ql[2], ql[3], qa + FQ_TILE);
            uint32_t kb[8][2], lb[8][2];
#pragma unroll
            for (int nb = 0; nb < 4; nb++) {
                uint32_t ka = st + (klrow + nb * 16) * FRSTR + ch * 32 + kh16;
                uint32_t r0, r1, r2, r3;
                LDSM_X4(r0, r1, r2, r3, ka);
                kb[2 * nb][0] = r0; kb[2 * nb][1] = r2;
                kb[2 * nb + 1][0] = r1; kb[2 * nb + 1][1] = r3;
                LDSM_X4(r0, r1, r2, r3, ka + FK_TILE);
                lb[2 * nb][0] = r0; lb[2 * nb][1] = r2;
                lb[2 * nb + 1][0] = r1; lb[2 * nb + 1][1] = r3;
            }
#pragma unroll
            for (int n8 = 0; n8 < 8; n8++) MMA16816(sa[n8], qh, kb[n8]);
#pragma unroll
            for (int n8 = 0; n8 < 8; n8++) MMA16816(sa[n8], qh, lb[n8]);
#pragma unroll
            for (int n8 = 0; n8 < 8; n8++) MMA16816(sa[n8], ql, kb[n8]);
        }

        // ---- mask + online softmax ----
        float rmax0 = -1e30f, rmax1 = -1e30f;
        const int kvb = kv0 + (lane & 3) * 2;
#pragma unroll
        for (int n8 = 0; n8 < 8; n8++) {
            int kvc = kvb + n8 * 8;
            float s0 = sa[n8][0] * scl, s1 = sa[n8][1] * scl;
            float s2 = sa[n8][2] * scl, s3 = sa[n8][3] * scl;
            if (kvc     > qg0) s0 = -1e30f;
            if (kvc + 1 > qg0) s1 = -1e30f;
            if (kvc     > qg1) s2 = -1e30f;
            if (kvc + 1 > qg1) s3 = -1e30f;
            sa[n8][0] = s0; sa[n8][1] = s1; sa[n8][2] = s2; sa[n8][3] = s3;
            rmax0 = fmaxf(rmax0, fmaxf(s0, s1));
            rmax1 = fmaxf(rmax1, fmaxf(s2, s3));
        }
        rmax0 = fmaxf(rmax0, __shfl_xor_sync(0xffffffffu, rmax0, 1));
        rmax0 = fmaxf(rmax0, __shfl_xor_sync(0xffffffffu, rmax0, 2));
        rmax1 = fmaxf(rmax1, __shfl_xor_sync(0xffffffffu, rmax1, 1));
        rmax1 = fmaxf(rmax1, __shfl_xor_sync(0xffffffffu, rmax1, 2));

        float mn0 = fmaxf(m0, rmax0), mn1 = fmaxf(m1, rmax1);
        float sc0 = __expf(m0 - mn0), sc1 = __expf(m1 - mn1);
        m0 = mn0; m1 = mn1;

        uint32_t ph[16], pl[16];
        float rs0 = 0.f, rs1 = 0.f;
#pragma unroll
        for (int n8 = 0; n8 < 8; n8++) {
            float p0 = __expf(sa[n8][0] - mn0);
            float p1 = __expf(sa[n8][1] - mn0);
            float p2 = __expf(sa[n8][2] - mn1);
            float p3 = __expf(sa[n8][3] - mn1);
            rs0 += p0 + p1; rs1 += p2 + p3;
            float h0 = __bfloat162float(__float2bfloat16(p0));
            float h1 = __bfloat162float(__float2bfloat16(p1));
            float h2 = __bfloat162float(__float2bfloat16(p2));
            float h3 = __bfloat162float(__float2bfloat16(p3));
            ph[2 * n8]     = pack_bf16x2(h0, h1);
            ph[2 * n8 + 1] = pack_bf16x2(h2, h3);
            pl[2 * n8]     = pack_bf16x2(p0 - h0, p1 - h1);
            pl[2 * n8 + 1] = pack_bf16x2(p2 - h2, p3 - h3);
        }
        rs0 += __shfl_xor_sync(0xffffffffu, rs0, 1);
        rs0 += __shfl_xor_sync(0xffffffffu, rs0, 2);
        rs1 += __shfl_xor_sync(0xffffffffu, rs1, 1);
        rs1 += __shfl_xor_sync(0xffffffffu, rs1, 2);
        l0 = l0 * sc0 + rs0;
        l1 = l1 * sc1 + rs1;

#pragma unroll
        for (int d = 0; d < 16; d++) {
            o[d][0] *= sc0; o[d][1] *= sc0;
            o[d][2] *= sc1; o[d][3] *= sc1;
        }

        // ---- O += P V (chain-broken) ----
#pragma unroll
        for (int j = 0; j < 4; j++) {
            uint32_t ah[4] = {ph[4*j], ph[4*j+1], ph[4*j+2], ph[4*j+3]};
            uint32_t al[4] = {pl[4*j], pl[4*j+1], pl[4*j+2], pl[4*j+3]};
#pragma unroll
            for (int half = 0; half < 2; half++) {
                uint32_t vh[8][2], vl[8][2];
#pragma unroll
                for (int k = 0; k < 4; k++) {
                    int nb = half * 4 + k;
                    uint32_t va = st + 2 * FK_TILE +
                                  (uint32_t)(j * 16 + (lane & 15)) * FRSTR +
                                  nb * 32 + kh16;
                    uint32_t r0, r1, r2, r3;
                    LDSM_X4_T(r0, r1, r2, r3, va);
                    vh[2 * k][0] = r0; vh[2 * k][1] = r1;
                    vh[2 * k + 1][0] = r2; vh[2 * k + 1][1] = r3;
                    LDSM_X4_T(r0, r1, r2, r3, va + FK_TILE);
                    vl[2 * k][0] = r0; vl[2 * k][1] = r1;
                    vl[2 * k + 1][0] = r2; vl[2 * k + 1][1] = r3;
                }
                const int ob = half * 8;
#pragma unroll
                for (int n = 0; n < 8; n++) MMA16816(o[ob + n], ah, vh[n]);
#pragma unroll
                for (int n = 0; n < 8; n++) MMA16816(o[ob + n], ah, vl[n]);
#pragma unroll
                for (int n = 0; n < 8; n++) MMA16816(o[ob + n], al, vh[n]);
            }
        }

        __syncthreads();   // all warps done reading the KV buffer
        if (kt + 1 < nkt) {
            fkv_fill(sKV, Kh_g, Kl_g, Vh_g, Vl_g, b, h, (kt + 1) * 64);
            CP_COMMIT();
        }
    }

    // ---- epilogue: stage adapter into dead KV smem, then fused adapter attn
    float* aKs = (float*)(sm + 2 * FQ_TILE);
    float* aVs = aKs + ADL_ * D_;
    for (int idx = tid; idx < ADL_ * D_; idx += 128) {
        int t = idx >> 7, cc = idx & (D_ - 1);
        aKs[idx] = aK[t * DIM_ + h * D_ + cc];
        aVs[idx] = aV[t * DIM_ + h * D_ + cc];
    }
    __syncthreads();

    const float g = tanhf(gate[h]);
    const float inv0 = 1.0f / l0, inv1 = 1.0f / l1;
    const int ccb = (lane & 3) * 2;

#pragma unroll
    for (int rr = 0; rr < 2; rr++) {
        const int lr = wid * 16 + (lane >> 2) + rr * 8;
        const float inv = rr ? inv1 : inv0;
        const size_t rowg = (size_t)(b * S_) + qt * 64 + lr;

        float qv[32];
#pragma unroll
        for (int d = 0; d < 16; d++) {
            int cc = d * 8 + ccb;
            __nv_bfloat162 hh = *(__nv_bfloat162*)(sm + lr * FRSTR + cc * 2);
            __nv_bfloat162 ll = *(__nv_bfloat162*)(sm + FQ_TILE + lr * FRSTR + cc * 2);
            qv[2 * d]     = __bfloat162float(hh.x) + __bfloat162float(ll.x);
            qv[2 * d + 1] = __bfloat162float(hh.y) + __bfloat162float(ll.y);
        }
        float sc[ADL_];
#pragma unroll
        for (int t = 0; t < ADL_; t++) {
            float p = 0.f;
#pragma unroll
            for (int d = 0; d < 16; d++) {
                int cc = d * 8 + ccb;
                p = fmaf(qv[2 * d],     aKs[t * D_ + cc],     p);
                p = fmaf(qv[2 * d + 1], aKs[t * D_ + cc + 1], p);
            }
            p += __shfl_xor_sync(0xffffffffu, p, 1);
            p += __shfl_xor_sync(0xffffffffu, p, 2);
            sc[t] = p * scl;
        }
        float mx = sc[0];
#pragma unroll
        for (int t = 1; t < ADL_; t++) mx = fmaxf(mx, sc[t]);
        float sum = 0.f;
#pragma unroll
        for (int t = 0; t < ADL_; t++) { sc[t] = __expf(sc[t] - mx); sum += sc[t]; }
        float isum = g / sum;
#pragma unroll
        for (int t = 0; t < ADL_; t++) sc[t] *= isum;

#pragma unroll
        for (int d = 0; d < 16; d++) {
            int cc = d * 8 + ccb;
            float a0 = 0.f, a1 = 0.f;
#pragma unroll
            for (int t = 0; t < ADL_; t++) {
                a0 = fmaf(sc[t], aVs[t * D_ + cc],     a0);
                a1 = fmaf(sc[t], aVs[t * D_ + cc + 1], a1);
            }
            float o0 = o[d][rr * 2]     * inv + a0;
            float o1 = o[d][rr * 2 + 1] * inv + a1;
            split_store(Oh, Ol, rowg * DIM_ + h * D_ + cc, o0, o1);
        }
    }
}

// ============================================================================
// launch
// ============================================================================
extern "C" void kernel_launch(void* const* d_in, const int* in_sizes, int n_in,
                              void* d_out, int out_size)
{
    const float* x       = (const float*)d_in[0];
    const float* wq      = (const float*)d_in[1];
    const float* wk      = (const float*)d_in[2];
    const float* wv      = (const float*)d_in[3];
    const float* wo      = (const float*)d_in[4];
    const float* gate    = (const float*)d_in[5];
    const float* adapter = (const float*)d_in[6];
    const float* fcos    = (const float*)d_in[7];
    const float* fsin    = (const float*)d_in[8];
    float* out = (float*)d_out;

    float *aKp, *aVp;
    cudaGetSymbolAddress((void**)&aKp, g_aK);
    cudaGetSymbolAddress((void**)&aVp, g_aV);

    __nv_bfloat16 *xh, *xl, *wqh, *wql, *wkh, *wkl, *wvh, *wvl, *woh, *wol;
    __nv_bfloat16 *qh, *ql, *kh, *kl, *vh, *vl, *oh, *ol;
    cudaGetSymbolAddress((void**)&xh,  g_xh);  cudaGetSymbolAddress((void**)&xl,  g_xl);
    cudaGetSymbolAddress((void**)&wqh, g_wqh); cudaGetSymbolAddress((void**)&wql, g_wql);
    cudaGetSymbolAddress((void**)&wkh, g_wkh); cudaGetSymbolAddress((void**)&wkl, g_wkl);
    cudaGetSymbolAddress((void**)&wvh, g_wvh); cudaGetSymbolAddress((void**)&wvl, g_wvl);
    cudaGetSymbolAddress((void**)&woh, g_woh); cudaGetSymbolAddress((void**)&wol, g_wol);
    cudaGetSymbolAddress((void**)&qh,  g_qh);  cudaGetSymbolAddress((void**)&ql,  g_ql);
    cudaGetSymbolAddress((void**)&kh,  g_kh);  cudaGetSymbolAddress((void**)&kl,  g_kl);
    cudaGetSymbolAddress((void**)&vh,  g_vh);  cudaGetSymbolAddress((void**)&vl,  g_vl);
    cudaGetSymbolAddress((void**)&oh,  g_oh);  cudaGetSymbolAddress((void**)&ol,  g_ol);

    cudaFuncSetAttribute(mma_gemm,
                         cudaFuncAttributeMaxDynamicSharedMemorySize, GK_SMEM);
    cudaFuncSetAttribute(qkv_gemm,
                         cudaFuncAttributeMaxDynamicSharedMemorySize, GK_SMEM);
    cudaFuncSetAttribute(flash_mma,
                         cudaFuncAttributeMaxDynamicSharedMemorySize, FLASH_SMEM);

    split5<<<dim3(NELEM / 4 / 256, 5), 256>>>(x, wq, wk, wv, wo,
        xh, xl, wqh, wql, wkh, wkl, wvh, wvl, woh, wol);

    adapter_gemv<<<128, 256>>>(adapter, wk, aKp);
    adapter_gemv<<<128, 256>>>(adapter, wv, aVp);

    qkv_gemm<<<dim3(DIM_ / 128, MROWS / 128, 3), 256, GK_SMEM>>>(
        xh, xl, wqh, wql, wkh, wkl, wvh, wvl,
        qh, ql, kh, kl, vh, vl, fcos, fsin);

    flash_mma<<<dim3(S_ / 64, H_, B_), 128, FLASH_SMEM>>>(
        qh, ql, kh, kl, vh, vl, aKp, aVp, gate, oh, ol);

    mma_gemm<<<dim3(DIM_ / 128, MROWS / 128), 256, GK_SMEM>>>(
        oh, ol, woh, wol, out);
}

// round 12
// speedup vs baseline: 1.2647x; 1.1531x over previous
#include <cuda_runtime.h>
#include <cuda_bf16.h>
#include <cuda_fp16.h>
#include <math.h>
#include <stdint.h>

// ---------------------------------------------------------------- constants
#define B_    2
#define S_    2048
#define H_    32
#define D_    128
#define DIM_  4096
#define ADL_  10
#define MROWS (B_ * S_)
#define NELEM ((size_t)MROWS * DIM_)

// ---------------------------------------------------------------- scratch
__device__ float g_aK[ADL_ * DIM_];
__device__ float g_aV[ADL_ * DIM_];

// bf16 path (Q/K precision-critical)
__device__ __nv_bfloat16 g_xh[NELEM],  g_xl[NELEM];
__device__ __nv_bfloat16 g_wqh[NELEM], g_wql[NELEM];
__device__ __nv_bfloat16 g_wkh[NELEM], g_wkl[NELEM];
__device__ __nv_bfloat16 g_qh[NELEM],  g_ql[NELEM];
__device__ __nv_bfloat16 g_kh[NELEM],  g_kl[NELEM];
// fp16 path (V / out, linear)
__device__ __half g_x16h[NELEM], g_x16l[NELEM];
__device__ __half g_wv16[NELEM], g_wo16[NELEM];
__device__ __half g_v16[NELEM];
__device__ __half g_o16h[NELEM], g_o16l[NELEM];

// ---------------------------------------------------------------- PTX utils
__device__ __forceinline__ uint32_t smem_u32(const void* p) {
    uint32_t a;
    asm("{ .reg .u64 t; cvta.to.shared.u64 t, %1; cvt.u32.u64 %0, t; }"
        : "=r"(a) : "l"(p));
    return a;
}
#define CP_ASYNC16(dst, src) \
    asm volatile("cp.async.cg.shared.global [%0], [%1], 16;" \
                 :: "r"(dst), "l"(src) : "memory")
#define CP_COMMIT() asm volatile("cp.async.commit_group;" ::: "memory")
#define CP_WAIT(n)  asm volatile("cp.async.wait_group %0;" :: "n"(n) : "memory")

#define LDSM_X4(r0, r1, r2, r3, addr) \
    asm volatile("ldmatrix.sync.aligned.m8n8.x4.shared.b16 {%0,%1,%2,%3}, [%4];" \
                 : "=r"(r0), "=r"(r1), "=r"(r2), "=r"(r3) : "r"(addr))
#define LDSM_X4_T(r0, r1, r2, r3, addr) \
    asm volatile("ldmatrix.sync.aligned.m8n8.x4.trans.shared.b16 {%0,%1,%2,%3}, [%4];" \
                 : "=r"(r0), "=r"(r1), "=r"(r2), "=r"(r3) : "r"(addr))

#define MMA16816(c, a, b) \
    asm volatile("mma.sync.aligned.m16n8k16.row.col.f32.bf16.bf16.f32 " \
                 "{%0,%1,%2,%3}, {%4,%5,%6,%7}, {%8,%9}, {%0,%1,%2,%3};" \
                 : "+f"((c)[0]), "+f"((c)[1]), "+f"((c)[2]), "+f"((c)[3]) \
                 : "r"((a)[0]), "r"((a)[1]), "r"((a)[2]), "r"((a)[3]), \
                   "r"((b)[0]), "r"((b)[1]))
#define MMAH16816(c, a, b) \
    asm volatile("mma.sync.aligned.m16n8k16.row.col.f32.f16.f16.f32 " \
                 "{%0,%1,%2,%3}, {%4,%5,%6,%7}, {%8,%9}, {%0,%1,%2,%3};" \
                 : "+f"((c)[0]), "+f"((c)[1]), "+f"((c)[2]), "+f"((c)[3]) \
                 : "r"((a)[0]), "r"((a)[1]), "r"((a)[2]), "r"((a)[3]), \
                   "r"((b)[0]), "r"((b)[1]))

__device__ __forceinline__ uint32_t pack_bf16x2(float lo, float hi) {
    __nv_bfloat162 t = __floats2bfloat162_rn(lo, hi);
    return *(uint32_t*)&t;
}
__device__ __forceinline__ uint32_t pack_h2(float lo, float hi) {
    __half2 t = __floats2half2_rn(lo, hi);
    return *(uint32_t*)&t;
}
__device__ __forceinline__ void split_store_bf(__nv_bfloat16* Xh, __nv_bfloat16* Xl,
                                               size_t off, float v0, float v1) {
    __nv_bfloat16 h0 = __float2bfloat16(v0);
    __nv_bfloat16 h1 = __float2bfloat16(v1);
    *(__nv_bfloat162*)(Xh + off) = __nv_bfloat162(h0, h1);
    *(__nv_bfloat162*)(Xl + off) = __nv_bfloat162(
        __float2bfloat16(v0 - __bfloat162float(h0)),
        __float2bfloat16(v1 - __bfloat162float(h1)));
}
__device__ __forceinline__ void split_store_h(__half* Xh, __half* Xl,
                                              size_t off, float v0, float v1) {
    __half h0 = __float2half_rn(v0);
    __half h1 = __float2half_rn(v1);
    *(__half2*)(Xh + off) = __half2(h0, h1);
    *(__half2*)(Xl + off) = __half2(
        __float2half_rn(v0 - __half2float(h0)),
        __float2half_rn(v1 - __half2float(h1)));
}

// ============================================================================
// bf16x3 GEMM core (R10/R11 best config): 128x128 tile, BK=32, 2-stage, occ 2
// ============================================================================
#define GK_BK      32
#define GK_TILE_B  10240
#define GK_STAGE_B (4 * GK_TILE_B)
#define GK_SMEM    (2 * GK_STAGE_B)
#define GK_NIT     (DIM_ / GK_BK)

__device__ __forceinline__ void gk_fill(uint32_t sbase,
    const __nv_bfloat16* __restrict__ Ah, const __nv_bfloat16* __restrict__ Al,
    const __nv_bfloat16* __restrict__ Bh, const __nv_bfloat16* __restrict__ Bl,
    int rowBase, int colBase, int k0)
{
    const int tid = threadIdx.x;
#pragma unroll
    for (int i = 0; i < 2; i++) {
        int idx = tid + i * 256;
        int row = idx >> 2;
        int cg  = (idx & 3) * 8;
        uint32_t doff = (uint32_t)(row * 80 + (idx & 3) * 16);
        size_t ga = (size_t)(rowBase + row) * DIM_ + k0 + cg;
        size_t gb = (size_t)(colBase + row) * DIM_ + k0 + cg;
        CP_ASYNC16(sbase + doff,                 Ah + ga);
        CP_ASYNC16(sbase + GK_TILE_B + doff,     Al + ga);
        CP_ASYNC16(sbase + 2 * GK_TILE_B + doff, Bh + gb);
        CP_ASYNC16(sbase + 3 * GK_TILE_B + doff, Bl + gb);
    }
}

#define GK_MAINLOOP(Ah, Al, Bh, Bl)                                            \
    gk_fill(base, Ah, Al, Bh, Bl, rowBase, colBase, 0);                        \
    CP_COMMIT();                                                               \
    const uint32_t aRow = (uint32_t)(wm + (lane & 15));                        \
    const uint32_t bRow = (uint32_t)(wn + (lane & 15));                        \
    const uint32_t kHalf = (uint32_t)((lane >> 4) * 16);                       \
    for (int it = 0; it < GK_NIT; it++) {                                      \
        CP_WAIT(0);                                                            \
        __syncthreads();                                                       \
        if (it + 1 < GK_NIT)                                                   \
            gk_fill(base + (uint32_t)((it + 1) & 1) * GK_STAGE_B,              \
                    Ah, Al, Bh, Bl, rowBase, colBase, (it + 1) * GK_BK);       \
        CP_COMMIT();                                                           \
        const uint32_t sb = base + (uint32_t)(it & 1) * GK_STAGE_B;            \
        _Pragma("unroll")                                                      \
        for (int ks = 0; ks < 2; ks++) {                                       \
            const uint32_t kcol = (uint32_t)(ks * 32) + kHalf;                 \
            uint32_t ah[4][4], al[4][4], bh[4][2], bl[4][2];                   \
            _Pragma("unroll")                                                  \
            for (int mi = 0; mi < 4; mi++) {                                   \
                uint32_t off = (aRow + mi * 16) * 80 + kcol;                   \
                LDSM_X4(ah[mi][0], ah[mi][1], ah[mi][2], ah[mi][3], sb + off); \
                LDSM_X4(al[mi][0], al[mi][1], al[mi][2], al[mi][3],            \
                        sb + GK_TILE_B + off);                                 \
            }                                                                  \
            _Pragma("unroll")                                                  \
            for (int np = 0; np < 2; np++) {                                   \
                uint32_t off = (bRow + np * 16) * 80 + kcol;                   \
                uint32_t r0, r1, r2, r3;                                       \
                LDSM_X4(r0, r1, r2, r3, sb + 2 * GK_TILE_B + off);             \
                bh[2 * np][0] = r0; bh[2 * np][1] = r2;                        \
                bh[2 * np + 1][0] = r1; bh[2 * np + 1][1] = r3;                \
                LDSM_X4(r0, r1, r2, r3, sb + 3 * GK_TILE_B + off);             \
                bl[2 * np][0] = r0; bl[2 * np][1] = r2;                        \
                bl[2 * np + 1][0] = r1; bl[2 * np + 1][1] = r3;                \
            }                                                                  \
            _Pragma("unroll")                                                  \
            for (int mi = 0; mi < 4; mi++)                                     \
                _Pragma("unroll")                                              \
                for (int ni = 0; ni < 4; ni++)                                 \
                    MMA16816(acc[mi][ni], ah[mi], bh[ni]);                     \
            _Pragma("unroll")                                                  \
            for (int mi = 0; mi < 4; mi++)                                     \
                _Pragma("unroll")                                              \
                for (int ni = 0; ni < 4; ni++)                                 \
                    MMA16816(acc[mi][ni], ah[mi], bl[ni]);                     \
            _Pragma("unroll")                                                  \
            for (int mi = 0; mi < 4; mi++)                                     \
                _Pragma("unroll")                                              \
                for (int ni = 0; ni < 4; ni++)                                 \
                    MMA16816(acc[mi][ni], al[mi], bh[ni]);                     \
        }                                                                      \
    }

// --------- Q/K GEMM (bf16x3) with fused rope + bf16 split output ---------
__global__ __launch_bounds__(256, 2)
void qk_gemm(const __nv_bfloat16* __restrict__ Ah, const __nv_bfloat16* __restrict__ Al,
             const __nv_bfloat16* __restrict__ Bqh, const __nv_bfloat16* __restrict__ Bql,
             const __nv_bfloat16* __restrict__ Bkh, const __nv_bfloat16* __restrict__ Bkl,
             __nv_bfloat16* __restrict__ Qh, __nv_bfloat16* __restrict__ Ql,
             __nv_bfloat16* __restrict__ Kh, __nv_bfloat16* __restrict__ Kl,
             const float* __restrict__ fcos, const float* __restrict__ fsin)
{
    extern __shared__ char sm[];
    const uint32_t base = smem_u32(sm);
    const int lane = threadIdx.x & 31;
    const int wid  = threadIdx.x >> 5;
    const int rowBase = blockIdx.y * 128;
    const int colBase = blockIdx.x * 128;
    const int wm = (wid & 1) * 64;
    const int wn = (wid >> 1) * 32;
    const int z = blockIdx.z;

    const __nv_bfloat16* Bh = (z == 0) ? Bqh : Bkh;
    const __nv_bfloat16* Bl = (z == 0) ? Bql : Bkl;
    __nv_bfloat16* Xh = (z == 0) ? Qh : Kh;
    __nv_bfloat16* Xl = (z == 0) ? Ql : Kl;

    float acc[4][4][4];
#pragma unroll
    for (int mi = 0; mi < 4; mi++)
#pragma unroll
        for (int ni = 0; ni < 4; ni++)
#pragma unroll
            for (int q = 0; q < 4; q++) acc[mi][ni][q] = 0.f;

    GK_MAINLOOP(Ah, Al, Bh, Bl)

    const int r0 = rowBase + wm + (lane >> 2);
    const int c0 = colBase + wn + (lane & 3) * 2;
#pragma unroll
    for (int mi = 0; mi < 4; mi++) {
        int r  = r0 + mi * 16;
        int s1 = r & (S_ - 1);
        int s2 = (r + 8) & (S_ - 1);
#pragma unroll
        for (int ni = 0; ni < 4; ni++) {
            int c = c0 + ni * 8;
            float v0 = acc[mi][ni][0], v1 = acc[mi][ni][1];
            float v2 = acc[mi][ni][2], v3 = acc[mi][ni][3];
            int i = (c & (D_ - 1)) >> 1;
            float c1 = fcos[s1 * 64 + i], n1 = fsin[s1 * 64 + i];
            float c2 = fcos[s2 * 64 + i], n2 = fsin[s2 * 64 + i];
            float t;
            t = v0 * c1 - v1 * n1; v1 = v0 * n1 + v1 * c1; v0 = t;
            t = v2 * c2 - v3 * n2; v3 = v2 * n2 + v3 * c2; v2 = t;
            split_store_bf(Xh, Xl, (size_t)r * DIM_ + c, v0, v1);
            split_store_bf(Xh, Xl, (size_t)(r + 8) * DIM_ + c, v2, v3);
        }
    }
}

// ============================================================================
// fp16 2-pass GEMM core: A = Ah+Al (fp16), B single fp16. 3 tiles/stage.
// ============================================================================
#define GH_STAGE_B (3 * GK_TILE_B)      // 30720
#define GH_SMEM    (2 * GH_STAGE_B)     // 61440

__device__ __forceinline__ void gh_fill(uint32_t sbase,
    const __half* __restrict__ Ah, const __half* __restrict__ Al,
    const __half* __restrict__ Bs,
    int rowBase, int colBase, int k0)
{
    const int tid = threadIdx.x;
#pragma unroll
    for (int i = 0; i < 6; i++) {
        int idx = tid + i * 256;              // 0..1535
        int arr = idx / 512;                  // 0 Ah, 1 Al, 2 B
        int rem = idx & 511;
        int row = rem >> 2;
        int ch  = rem & 3;
        uint32_t dst = sbase + (uint32_t)(arr * GK_TILE_B + row * 80 + ch * 16);
        const __half* src = (arr == 0) ? Ah : (arr == 1) ? Al : Bs;
        int grow = (arr == 2) ? (colBase + row) : (rowBase + row);
        CP_ASYNC16(dst, src + (size_t)grow * DIM_ + k0 + ch * 8);
    }
}

#define GH_MAINLOOP(Ah, Al, Bs)                                                \
    gh_fill(base, Ah, Al, Bs, rowBase, colBase, 0);                            \
    CP_COMMIT();                                                               \
    const uint32_t aRow = (uint32_t)(wm + (lane & 15));                        \
    const uint32_t bRow = (uint32_t)(wn + (lane & 15));                        \
    const uint32_t kHalf = (uint32_t)((lane >> 4) * 16);                       \
    for (int it = 0; it < GK_NIT; it++) {                                      \
        CP_WAIT(0);                                                            \
        __syncthreads();                                                       \
        if (it + 1 < GK_NIT)                                                   \
            gh_fill(base + (uint32_t)((it + 1) & 1) * GH_STAGE_B,              \
                    Ah, Al, Bs, rowBase, colBase, (it + 1) * GK_BK);           \
        CP_COMMIT();                                                           \
        const uint32_t sb = base + (uint32_t)(it & 1) * GH_STAGE_B;            \
        _Pragma("unroll")                                                      \
        for (int ks = 0; ks < 2; ks++) {                                       \
            const uint32_t kcol = (uint32_t)(ks * 32) + kHalf;                 \
            uint32_t ah[4][4], al[4][4], bb[4][2];                             \
            _Pragma("unroll")                                                  \
            for (int mi = 0; mi < 4; mi++) {                                   \
                uint32_t off = (aRow + mi * 16) * 80 + kcol;                   \
                LDSM_X4(ah[mi][0], ah[mi][1], ah[mi][2], ah[mi][3], sb + off); \
                LDSM_X4(al[mi][0], al[mi][1], al[mi][2], al[mi][3],            \
                        sb + GK_TILE_B + off);                                 \
            }                                                                  \
            _Pragma("unroll")                                                  \
            for (int np = 0; np < 2; np++) {                                   \
                uint32_t off = 2 * GK_TILE_B + (bRow + np * 16) * 80 + kcol;   \
                uint32_t r0, r1, r2, r3;                                       \
                LDSM_X4(r0, r1, r2, r3, sb + off);                             \
                bb[2 * np][0] = r0; bb[2 * np][1] = r2;                        \
                bb[2 * np + 1][0] = r1; bb[2 * np + 1][1] = r3;                \
            }                                                                  \
            _Pragma("unroll")                                                  \
            for (int mi = 0; mi < 4; mi++)                                     \
                _Pragma("unroll")                                              \
                for (int ni = 0; ni < 4; ni++)                                 \
                    MMAH16816(acc[mi][ni], ah[mi], bb[ni]);                    \
            _Pragma("unroll")                                                  \
            for (int mi = 0; mi < 4; mi++)                                     \
                _Pragma("unroll")                                              \
                for (int ni = 0; ni < 4; ni++)                                 \
                    MMAH16816(acc[mi][ni], al[mi], bb[ni]);                    \
        }                                                                      \
    }

// --------- V GEMM (fp16 2-pass): writes V single fp16 ---------
__global__ __launch_bounds__(256, 2)
void v_gemm(const __half* __restrict__ Ah, const __half* __restrict__ Al,
            const __half* __restrict__ Bs, __half* __restrict__ V)
{
    extern __shared__ char sm[];
    const uint32_t base = smem_u32(sm);
    const int lane = threadIdx.x & 31;
    const int wid  = threadIdx.x >> 5;
    const int rowBase = blockIdx.y * 128;
    const int colBase = blockIdx.x * 128;
    const int wm = (wid & 1) * 64;
    const int wn = (wid >> 1) * 32;

    float acc[4][4][4];
#pragma unroll
    for (int mi = 0; mi < 4; mi++)
#pragma unroll
        for (int ni = 0; ni < 4; ni++)
#pragma unroll
            for (int q = 0; q < 4; q++) acc[mi][ni][q] = 0.f;

    GH_MAINLOOP(Ah, Al, Bs)

    const int r0 = rowBase + wm + (lane >> 2);
    const int c0 = colBase + wn + (lane & 3) * 2;
#pragma unroll
    for (int mi = 0; mi < 4; mi++)
#pragma unroll
        for (int ni = 0; ni < 4; ni++) {
            size_t off = (size_t)(r0 + mi * 16) * DIM_ + c0 + ni * 8;
            *(__half2*)(V + off) =
                __floats2half2_rn(acc[mi][ni][0], acc[mi][ni][1]);
            *(__half2*)(V + off + 8 * DIM_) =
                __floats2half2_rn(acc[mi][ni][2], acc[mi][ni][3]);
        }
}

// --------- out GEMM (fp16 2-pass): fp32 C ---------
__global__ __launch_bounds__(256, 2)
void o_gemm(const __half* __restrict__ Ah, const __half* __restrict__ Al,
            const __half* __restrict__ Bs, float* __restrict__ C)
{
    extern __shared__ char sm[];
    const uint32_t base = smem_u32(sm);
    const int lane = threadIdx.x & 31;
    const int wid  = threadIdx.x >> 5;
    const int rowBase = blockIdx.y * 128;
    const int colBase = blockIdx.x * 128;
    const int wm = (wid & 1) * 64;
    const int wn = (wid >> 1) * 32;

    float acc[4][4][4];
#pragma unroll
    for (int mi = 0; mi < 4; mi++)
#pragma unroll
        for (int ni = 0; ni < 4; ni++)
#pragma unroll
            for (int q = 0; q < 4; q++) acc[mi][ni][q] = 0.f;

    GH_MAINLOOP(Ah, Al, Bs)

    const int r0 = rowBase + wm + (lane >> 2);
    const int c0 = colBase + wn + (lane & 3) * 2;
#pragma unroll
    for (int mi = 0; mi < 4; mi++)
#pragma unroll
        for (int ni = 0; ni < 4; ni++) {
            float* p = C + (size_t)(r0 + mi * 16) * DIM_ + c0 + ni * 8;
            *(float2*)p = make_float2(acc[mi][ni][0], acc[mi][ni][1]);
            *(float2*)(p + 8 * DIM_) = make_float2(acc[mi][ni][2], acc[mi][ni][3]);
        }
}

// ============================================================================
// split_all: y=0 x->(bf16 h/l + fp16 h/l); y=1 wq bf16; y=2 wk bf16;
//            y=3 wv fp16 single; y=4 wo fp16 single
// ============================================================================
__global__ void split_all(const float* __restrict__ x,  const float* __restrict__ wq,
                          const float* __restrict__ wk, const float* __restrict__ wv,
                          const float* __restrict__ wo,
                          __nv_bfloat16* xh,  __nv_bfloat16* xl,
                          __half* x16h, __half* x16l,
                          __nv_bfloat16* qh,  __nv_bfloat16* ql,
                          __nv_bfloat16* kh,  __nv_bfloat16* kl,
                          __half* wv16, __half* wo16)
{
    size_t i = (size_t)blockIdx.x * blockDim.x + threadIdx.x;
    const int y = blockIdx.y;

    if (y == 3 || y == 4) {
        const float* src = (y == 3) ? wv : wo;
        __half* dst = (y == 3) ? wv16 : wo16;
        float4 v = ((const float4*)src)[i];
        ((__half2*)dst)[2 * i]     = __floats2half2_rn(v.x, v.y);
        ((__half2*)dst)[2 * i + 1] = __floats2half2_rn(v.z, v.w);
        return;
    }

    const float* src = (y == 0) ? x : (y == 1) ? wq : wk;
    __nv_bfloat16* hi = (y == 0) ? xh : (y == 1) ? qh : kh;
    __nv_bfloat16* lo = (y == 0) ? xl : (y == 1) ? ql : kl;

    float4 v = ((const float4*)src)[i];
    __nv_bfloat16 h0 = __float2bfloat16(v.x);
    __nv_bfloat16 h1 = __float2bfloat16(v.y);
    __nv_bfloat16 h2 = __float2bfloat16(v.z);
    __nv_bfloat16 h3 = __float2bfloat16(v.w);
    ((__nv_bfloat162*)hi)[2 * i]     = __nv_bfloat162(h0, h1);
    ((__nv_bfloat162*)hi)[2 * i + 1] = __nv_bfloat162(h2, h3);
    ((__nv_bfloat162*)lo)[2 * i] = __nv_bfloat162(
        __float2bfloat16(v.x - __bfloat162float(h0)),
        __float2bfloat16(v.y - __bfloat162float(h1)));
    ((__nv_bfloat162*)lo)[2 * i + 1] = __nv_bfloat162(
        __float2bfloat16(v.z - __bfloat162float(h2)),
        __float2bfloat16(v.w - __bfloat162float(h3)));

    if (y == 0) {
        __half a0 = __float2half_rn(v.x), a1 = __float2half_rn(v.y);
        __half a2 = __float2half_rn(v.z), a3 = __float2half_rn(v.w);
        ((__half2*)x16h)[2 * i]     = __half2(a0, a1);
        ((__half2*)x16h)[2 * i + 1] = __half2(a2, a3);
        ((__half2*)x16l)[2 * i] = __half2(
            __float2half_rn(v.x - __half2float(a0)),
            __float2half_rn(v.y - __half2float(a1)));
        ((__half2*)x16l)[2 * i + 1] = __half2(
            __float2half_rn(v.z - __half2float(a2)),
            __float2half_rn(v.w - __half2float(a3)));
    }
}

// ============================================================================
// adapter GEMV (fp32)
// ============================================================================
__global__ __launch_bounds__(256)
void adapter_gemv(const float* __restrict__ A, const float* __restrict__ W,
                  float* __restrict__ out)
{
    int warp = (blockIdx.x * blockDim.x + threadIdx.x) >> 5;
    int lane = threadIdx.x & 31;
    int e0 = warp * 4;

    float acc[ADL_][4];
#pragma unroll
    for (int l = 0; l < ADL_; l++)
#pragma unroll
        for (int j = 0; j < 4; j++) acc[l][j] = 0.f;

    for (int d = lane * 4; d < DIM_; d += 128) {
        float4 w4[4];
#pragma unroll
        for (int j = 0; j < 4; j++)
            w4[j] = *(const float4*)(W + (size_t)(e0 + j) * DIM_ + d);
#pragma unroll
        for (int l = 0; l < ADL_; l++) {
            float4 a4 = *(const float4*)(A + (size_t)l * DIM_ + d);
#pragma unroll
            for (int j = 0; j < 4; j++) {
                acc[l][j] = fmaf(a4.x, w4[j].x, acc[l][j]);
                acc[l][j] = fmaf(a4.y, w4[j].y, acc[l][j]);
                acc[l][j] = fmaf(a4.z, w4[j].z, acc[l][j]);
                acc[l][j] = fmaf(a4.w, w4[j].w, acc[l][j]);
            }
        }
    }
#pragma unroll
    for (int l = 0; l < ADL_; l++)
#pragma unroll
        for (int j = 0; j < 4; j++) {
            float v = acc[l][j];
#pragma unroll
            for (int off = 16; off; off >>= 1)
                v += __shfl_xor_sync(0xffffffffu, v, off);
            if (lane == 0) out[l * DIM_ + e0 + j] = v;
        }
}

// ============================================================================
// Flash attention: QK bf16x3, PV fp16 2-pass (V single fp16).
// 64 q-rows/CTA, 128 threads, single-buffered KV (Kh,Kl bf16 + V fp16).
// ============================================================================
#define FRSTR   272
#define FQ_TILE (64 * FRSTR)             // 17408
#define FK_TILE (64 * FRSTR)
#define FSTAGE  (3 * FK_TILE)            // 52224
#define FLASH_SMEM (2 * FQ_TILE + FSTAGE)    // 87040

__device__ __forceinline__ void fkv_fill(uint32_t sdst,
    const __nv_bfloat16* __restrict__ Kh, const __nv_bfloat16* __restrict__ Kl,
    const __half* __restrict__ V,
    int b, int h, int kv0)
{
    const int tid = threadIdx.x;
    const size_t gbase = ((size_t)(b * S_) + kv0) * DIM_ + h * D_;
#pragma unroll
    for (int i = 0; i < 24; i++) {
        int idx = tid + i * 128;              // 0..3071
        int arr = idx >> 10;                  // 0 Kh, 1 Kl, 2 V
        int rem = idx & 1023;
        int row = rem >> 4;
        int ch  = rem & 15;
        uint32_t dst = sdst + arr * FK_TILE + row * FRSTR + ch * 16;
        size_t src = gbase + (size_t)row * DIM_ + ch * 8;
        if (arr == 0)      CP_ASYNC16(dst, Kh + src);
        else if (arr == 1) CP_ASYNC16(dst, Kl + src);
        else               CP_ASYNC16(dst, V + src);
    }
}

__global__ __launch_bounds__(128, 2)
void flash_mma(const __nv_bfloat16* __restrict__ Qh_g, const __nv_bfloat16* __restrict__ Ql_g,
               const __nv_bfloat16* __restrict__ Kh_g, const __nv_bfloat16* __restrict__ Kl_g,
               const __half* __restrict__ V_g,
               const float* __restrict__ aK, const float* __restrict__ aV,
               const float* __restrict__ gate,
               __half* __restrict__ Oh, __half* __restrict__ Ol)
{
    extern __shared__ char sm[];
    const uint32_t base = smem_u32(sm);
    const int tid  = threadIdx.x;
    const int wid  = tid >> 5;
    const int lane = tid & 31;
    const int qt = (int)gridDim.x - 1 - (int)blockIdx.x;   // heavy first
    const int h = blockIdx.y, b = blockIdx.z;
    const int nkt = qt + 1;

    const uint32_t sQh = base;
    const uint32_t sKV = base + 2 * FQ_TILE;

    {
        size_t gq = ((size_t)(b * S_) + qt * 64) * DIM_ + h * D_;
#pragma unroll
        for (int i = 0; i < 8; i++) {
            int idx = tid + i * 128;
            int row = idx >> 4, ch = idx & 15;
            uint32_t d = row * FRSTR + ch * 16;
            size_t src = gq + (size_t)row * DIM_ + ch * 8;
            CP_ASYNC16(sQh + d,           Qh_g + src);
            CP_ASYNC16(sQh + FQ_TILE + d, Ql_g + src);
        }
    }
    fkv_fill(sKV, Kh_g, Kl_g, V_g, b, h, 0);
    CP_COMMIT();

    const int q0  = qt * 64 + wid * 16;
    const int qg0 = q0 + (lane >> 2);
    const int qg1 = qg0 + 8;
    const float scl = 0.08838834764831845f;

    float m0 = -1e30f, m1 = -1e30f, l0 = 0.f, l1 = 0.f;
    float o[16][4];
#pragma unroll
    for (int d = 0; d < 16; d++)
#pragma unroll
        for (int q = 0; q < 4; q++) o[d][q] = 0.f;

    const uint32_t kh16 = (uint32_t)((lane >> 4) * 16);

    for (int kt = 0; kt < nkt; kt++) {
        CP_WAIT(0);
        __syncthreads();

        const uint32_t st = sKV;
        const int kv0 = kt * 64;

        // ---- S = Q K^T (bf16x3) ----
        float sa[8][4];
#pragma unroll
        for (int n8 = 0; n8 < 8; n8++)
#pragma unroll
            for (int q = 0; q < 4; q++) sa[n8][q] = 0.f;

        const uint32_t qrow = (uint32_t)(wid * 16 + (lane & 15));
        const uint32_t klrow = (uint32_t)(lane & 15);

#pragma unroll
        for (int ch = 0; ch < 8; ch++) {
            uint32_t qa = sQh + qrow * FRSTR + ch * 32 + kh16;
            uint32_t qh[4], ql[4];
            LDSM_X4(qh[0], qh[1], qh[2], qh[3], qa);
            LDSM_X4(ql[0], ql[1], ql[2], ql[3], qa + FQ_TILE);
            uint32_t kb[8][2], lb[8][2];
#pragma unroll
            for (int nb = 0; nb < 4; nb++) {
                uint32_t ka = st + (klrow + nb * 16) * FRSTR + ch * 32 + kh16;
                uint32_t r0, r1, r2, r3;
                LDSM_X4(r0, r1, r2, r3, ka);
                kb[2 * nb][0] = r0; kb[2 * nb][1] = r2;
                kb[2 * nb + 1][0] = r1; kb[2 * nb + 1][1] = r3;
                LDSM_X4(r0, r1, r2, r3, ka + FK_TILE);
                lb[2 * nb][0] = r0; lb[2 * nb][1] = r2;
                lb[2 * nb + 1][0] = r1; lb[2 * nb + 1][1] = r3;
            }
#pragma unroll
            for (int n8 = 0; n8 < 8; n8++) MMA16816(sa[n8], qh, kb[n8]);
#pragma unroll
            for (int n8 = 0; n8 < 8; n8++) MMA16816(sa[n8], qh, lb[n8]);
#pragma unroll
            for (int n8 = 0; n8 < 8; n8++) MMA16816(sa[n8], ql, kb[n8]);
        }

        // ---- mask + online softmax ----
        float rmax0 = -1e30f, rmax1 = -1e30f;
        const int kvb = kv0 + (lane & 3) * 2;
#pragma unroll
        for (int n8 = 0; n8 < 8; n8++) {
            int kvc = kvb + n8 * 8;
            float s0 = sa[n8][0] * scl, s1 = sa[n8][1] * scl;
            float s2 = sa[n8][2] * scl, s3 = sa[n8][3] * scl;
            if (kvc     > qg0) s0 = -1e30f;
            if (kvc + 1 > qg0) s1 = -1e30f;
            if (kvc     > qg1) s2 = -1e30f;
            if (kvc + 1 > qg1) s3 = -1e30f;
            sa[n8][0] = s0; sa[n8][1] = s1; sa[n8][2] = s2; sa[n8][3] = s3;
            rmax0 = fmaxf(rmax0, fmaxf(s0, s1));
            rmax1 = fmaxf(rmax1, fmaxf(s2, s3));
        }
        rmax0 = fmaxf(rmax0, __shfl_xor_sync(0xffffffffu, rmax0, 1));
        rmax0 = fmaxf(rmax0, __shfl_xor_sync(0xffffffffu, rmax0, 2));
        rmax1 = fmaxf(rmax1, __shfl_xor_sync(0xffffffffu, rmax1, 1));
        rmax1 = fmaxf(rmax1, __shfl_xor_sync(0xffffffffu, rmax1, 2));

        float mn0 = fmaxf(m0, rmax0), mn1 = fmaxf(m1, rmax1);
        float sc0 = __expf(m0 - mn0), sc1 = __expf(m1 - mn1);
        m0 = mn0; m1 = mn1;

        uint32_t ph[16], pl[16];
        float rs0 = 0.f, rs1 = 0.f;
#pragma unroll
        for (int n8 = 0; n8 < 8; n8++) {
            float p0 = __expf(sa[n8][0] - mn0);
            float p1 = __expf(sa[n8][1] - mn0);
            float p2 = __expf(sa[n8][2] - mn1);
            float p3 = __expf(sa[n8][3] - mn1);
            rs0 += p0 + p1; rs1 += p2 + p3;
            float h0 = __half2float(__float2half_rn(p0));
            float h1 = __half2float(__float2half_rn(p1));
            float h2 = __half2float(__float2half_rn(p2));
            float h3 = __half2float(__float2half_rn(p3));
            ph[2 * n8]     = pack_h2(h0, h1);
            ph[2 * n8 + 1] = pack_h2(h2, h3);
            pl[2 * n8]     = pack_h2(p0 - h0, p1 - h1);
            pl[2 * n8 + 1] = pack_h2(p2 - h2, p3 - h3);
        }
        rs0 += __shfl_xor_sync(0xffffffffu, rs0, 1);
        rs0 += __shfl_xor_sync(0xffffffffu, rs0, 2);
        rs1 += __shfl_xor_sync(0xffffffffu, rs1, 1);
        rs1 += __shfl_xor_sync(0xffffffffu, rs1, 2);
        l0 = l0 * sc0 + rs0;
        l1 = l1 * sc1 + rs1;

#pragma unroll
        for (int d = 0; d < 16; d++) {
            o[d][0] *= sc0; o[d][1] *= sc0;
            o[d][2] *= sc1; o[d][3] *= sc1;
        }

        // ---- O += P V  (fp16 2-pass, V single) ----
#pragma unroll
        for (int j = 0; j < 4; j++) {
            uint32_t ah[4] = {ph[4*j], ph[4*j+1], ph[4*j+2], ph[4*j+3]};
            uint32_t al[4] = {pl[4*j], pl[4*j+1], pl[4*j+2], pl[4*j+3]};
#pragma unroll
            for (int half = 0; half < 2; half++) {
                uint32_t vv[8][2];
#pragma unroll
                for (int k = 0; k < 4; k++) {
                    int nb = half * 4 + k;
                    uint32_t va = st + 2 * FK_TILE +
                                  (uint32_t)(j * 16 + (lane & 15)) * FRSTR +
                                  nb * 32 + kh16;
                    uint32_t r0, r1, r2, r3;
                    LDSM_X4_T(r0, r1, r2, r3, va);
                    vv[2 * k][0] = r0; vv[2 * k][1] = r1;
                    vv[2 * k + 1][0] = r2; vv[2 * k + 1][1] = r3;
                }
                const int ob = half * 8;
#pragma unroll
                for (int n = 0; n < 8; n++) MMAH16816(o[ob + n], ah, vv[n]);
#pragma unroll
                for (int n = 0; n < 8; n++) MMAH16816(o[ob + n], al, vv[n]);
            }
        }

        __syncthreads();
        if (kt + 1 < nkt) {
            fkv_fill(sKV, Kh_g, Kl_g, V_g, b, h, (kt + 1) * 64);
            CP_COMMIT();
        }
    }

    // ---- epilogue: adapter attention (staged into dead KV smem) ----
    float* aKs = (float*)(sm + 2 * FQ_TILE);
    float* aVs = aKs + ADL_ * D_;
    for (int idx = tid; idx < ADL_ * D_; idx += 128) {
        int t = idx >> 7, cc = idx & (D_ - 1);
        aKs[idx] = aK[t * DIM_ + h * D_ + cc];
        aVs[idx] = aV[t * DIM_ + h * D_ + cc];
    }
    __syncthreads();

    const float g = tanhf(gate[h]);
    const float inv0 = 1.0f / l0, inv1 = 1.0f / l1;
    const int ccb = (lane & 3) * 2;

#pragma unroll
    for (int rr = 0; rr < 2; rr++) {
        const int lr = wid * 16 + (lane >> 2) + rr * 8;
        const float inv = rr ? inv1 : inv0;
        const size_t rowg = (size_t)(b * S_) + qt * 64 + lr;

        float qv[32];
#pragma unroll
        for (int d = 0; d < 16; d++) {
            int cc = d * 8 + ccb;
            __nv_bfloat162 hh = *(__nv_bfloat162*)(sm + lr * FRSTR + cc * 2);
            __nv_bfloat162 ll = *(__nv_bfloat162*)(sm + FQ_TILE + lr * FRSTR + cc * 2);
            qv[2 * d]     = __bfloat162float(hh.x) + __bfloat162float(ll.x);
            qv[2 * d + 1] = __bfloat162float(hh.y) + __bfloat162float(ll.y);
        }
        float sc[ADL_];
#pragma unroll
        for (int t = 0; t < ADL_; t++) {
            float p = 0.f;
#pragma unroll
            for (int d = 0; d < 16; d++) {
                int cc = d * 8 + ccb;
                p = fmaf(qv[2 * d],     aKs[t * D_ + cc],     p);
                p = fmaf(qv[2 * d + 1], aKs[t * D_ + cc + 1], p);
            }
            p += __shfl_xor_sync(0xffffffffu, p, 1);
            p += __shfl_xor_sync(0xffffffffu, p, 2);
            sc[t] = p * scl;
        }
        float mx = sc[0];
#pragma unroll
        for (int t = 1; t < ADL_; t++) mx = fmaxf(mx, sc[t]);
        float sum = 0.f;
#pragma unroll
        for (int t = 0; t < ADL_; t++) { sc[t] = __expf(sc[t] - mx); sum += sc[t]; }
        float isum = g / sum;
#pragma unroll
        for (int t = 0; t < ADL_; t++) sc[t] *= isum;

#pragma unroll
        for (int d = 0; d < 16; d++) {
            int cc = d * 8 + ccb;
            float a0 = 0.f, a1 = 0.f;
#pragma unroll
            for (int t = 0; t < ADL_; t++) {
                a0 = fmaf(sc[t], aVs[t * D_ + cc],     a0);
                a1 = fmaf(sc[t], aVs[t * D_ + cc + 1], a1);
            }
            float o0 = o[d][rr * 2]     * inv + a0;
            float o1 = o[d][rr * 2 + 1] * inv + a1;
            split_store_h(Oh, Ol, rowg * DIM_ + h * D_ + cc, o0, o1);
        }
    }
}

// ============================================================================
// launch
// ============================================================================
extern "C" void kernel_launch(void* const* d_in, const int* in_sizes, int n_in,
                              void* d_out, int out_size)
{
    const float* x       = (const float*)d_in[0];
    const float* wq      = (const float*)d_in[1];
    const float* wk      = (const float*)d_in[2];
    const float* wv      = (const float*)d_in[3];
    const float* wo      = (const float*)d_in[4];
    const float* gate    = (const float*)d_in[5];
    const float* adapter = (const float*)d_in[6];
    const float* fcos    = (const float*)d_in[7];
    const float* fsin    = (const float*)d_in[8];
    float* out = (float*)d_out;

    float *aKp, *aVp;
    cudaGetSymbolAddress((void**)&aKp, g_aK);
    cudaGetSymbolAddress((void**)&aVp, g_aV);

    __nv_bfloat16 *xh, *xl, *wqh, *wql, *wkh, *wkl, *qh, *ql, *kh, *kl;
    __half *x16h, *x16l, *wv16, *wo16, *v16, *o16h, *o16l;
    cudaGetSymbolAddress((void**)&xh,  g_xh);  cudaGetSymbolAddress((void**)&xl,  g_xl);
    cudaGetSymbolAddress((void**)&wqh, g_wqh); cudaGetSymbolAddress((void**)&wql, g_wql);
    cudaGetSymbolAddress((void**)&wkh, g_wkh); cudaGetSymbolAddress((void**)&wkl, g_wkl);
    cudaGetSymbolAddress((void**)&qh,  g_qh);  cudaGetSymbolAddress((void**)&ql,  g_ql);
    cudaGetSymbolAddress((void**)&kh,  g_kh);  cudaGetSymbolAddress((void**)&kl,  g_kl);
    cudaGetSymbolAddress((void**)&x16h, g_x16h); cudaGetSymbolAddress((void**)&x16l, g_x16l);
    cudaGetSymbolAddress((void**)&wv16, g_wv16); cudaGetSymbolAddress((void**)&wo16, g_wo16);
    cudaGetSymbolAddress((void**)&v16,  g_v16);
    cudaGetSymbolAddress((void**)&o16h, g_o16h); cudaGetSymbolAddress((void**)&o16l, g_o16l);

    cudaFuncSetAttribute(qk_gemm,
                         cudaFuncAttributeMaxDynamicSharedMemorySize, GK_SMEM);
    cudaFuncSetAttribute(v_gemm,
                         cudaFuncAttributeMaxDynamicSharedMemorySize, GH_SMEM);
    cudaFuncSetAttribute(o_gemm,
                         cudaFuncAttributeMaxDynamicSharedMemorySize, GH_SMEM);
    cudaFuncSetAttribute(flash_mma,
                         cudaFuncAttributeMaxDynamicSharedMemorySize, FLASH_SMEM);

    split_all<<<dim3(NELEM / 4 / 256, 5), 256>>>(x, wq, wk, wv, wo,
        xh, xl, x16h, x16l, wqh, wql, wkh, wkl, wv16, wo16);

    adapter_gemv<<<128, 256>>>(adapter, wk, aKp);
    adapter_gemv<<<128, 256>>>(adapter, wv, aVp);

    qk_gemm<<<dim3(DIM_ / 128, MROWS / 128, 2), 256, GK_SMEM>>>(
        xh, xl, wqh, wql, wkh, wkl, qh, ql, kh, kl, fcos, fsin);

    v_gemm<<<dim3(DIM_ / 128, MROWS / 128), 256, GH_SMEM>>>(
        x16h, x16l, wv16, v16);

    flash_mma<<<dim3(S_ / 64, H_, B_), 128, FLASH_SMEM>>>(
        qh, ql, kh, kl, v16, aKp, aVp, gate, o16h, o16l);

    o_gemm<<<dim3(DIM_ / 128, MROWS / 128), 256, GH_SMEM>>>(
        o16h, o16l, wo16, out);
}

// round 13
// speedup vs baseline: 1.4705x; 1.1627x over previous
#include <cuda_runtime.h>
#include <cuda_bf16.h>
#include <cuda_fp16.h>
#include <math.h>
#include <stdint.h>

// ---------------------------------------------------------------- constants
#define B_    2
#define S_    2048
#define H_    32
#define D_    128
#define DIM_  4096
#define ADL_  10
#define MROWS (B_ * S_)
#define NELEM ((size_t)MROWS * DIM_)

// ---------------------------------------------------------------- scratch
__device__ float g_aK[ADL_ * DIM_];
__device__ float g_aV[ADL_ * DIM_];

__device__ __half g_x16h[NELEM], g_x16l[NELEM];
__device__ __half g_wq16[NELEM], g_wk16[NELEM];
__device__ __half g_wv16[NELEM], g_wo16[NELEM];
__device__ __half g_q16h[NELEM], g_q16l[NELEM];
__device__ __half g_k16h[NELEM], g_k16l[NELEM];
__device__ __half g_v16[NELEM];
__device__ __half g_o16h[NELEM], g_o16l[NELEM];

// ---------------------------------------------------------------- PTX utils
__device__ __forceinline__ uint32_t smem_u32(const void* p) {
    uint32_t a;
    asm("{ .reg .u64 t; cvta.to.shared.u64 t, %1; cvt.u32.u64 %0, t; }"
        : "=r"(a) : "l"(p));
    return a;
}
#define CP_ASYNC16(dst, src) \
    asm volatile("cp.async.cg.shared.global [%0], [%1], 16;" \
                 :: "r"(dst), "l"(src) : "memory")
#define CP_COMMIT() asm volatile("cp.async.commit_group;" ::: "memory")
#define CP_WAIT(n)  asm volatile("cp.async.wait_group %0;" :: "n"(n) : "memory")

#define LDSM_X4(r0, r1, r2, r3, addr) \
    asm volatile("ldmatrix.sync.aligned.m8n8.x4.shared.b16 {%0,%1,%2,%3}, [%4];" \
                 : "=r"(r0), "=r"(r1), "=r"(r2), "=r"(r3) : "r"(addr))
#define LDSM_X4_T(r0, r1, r2, r3, addr) \
    asm volatile("ldmatrix.sync.aligned.m8n8.x4.trans.shared.b16 {%0,%1,%2,%3}, [%4];" \
                 : "=r"(r0), "=r"(r1), "=r"(r2), "=r"(r3) : "r"(addr))

#define MMAH16816(c, a, b) \
    asm volatile("mma.sync.aligned.m16n8k16.row.col.f32.f16.f16.f32 " \
                 "{%0,%1,%2,%3}, {%4,%5,%6,%7}, {%8,%9}, {%0,%1,%2,%3};" \
                 : "+f"((c)[0]), "+f"((c)[1]), "+f"((c)[2]), "+f"((c)[3]) \
                 : "r"((a)[0]), "r"((a)[1]), "r"((a)[2]), "r"((a)[3]), \
                   "r"((b)[0]), "r"((b)[1]))

__device__ __forceinline__ uint32_t pack_h2(float lo, float hi) {
    __half2 t = __floats2half2_rn(lo, hi);
    return *(uint32_t*)&t;
}
__device__ __forceinline__ void split_store_h(__half* Xh, __half* Xl,
                                              size_t off, float v0, float v1) {
    __half h0 = __float2half_rn(v0);
    __half h1 = __float2half_rn(v1);
    *(__half2*)(Xh + off) = __half2(h0, h1);
    *(__half2*)(Xl + off) = __half2(
        __float2half_rn(v0 - __half2float(h0)),
        __float2half_rn(v1 - __half2float(h1)));
}

// ============================================================================
// fp16 2-pass GEMM core: A = Ah+Al (fp16), B single fp16. 3 tiles/stage,
// 128x128 CTA tile, BK=32, 2-stage, 2 CTA/SM.
// ============================================================================
#define GK_BK      32
#define GK_TILE_B  10240
#define GK_NIT     (DIM_ / GK_BK)
#define GH_STAGE_B (3 * GK_TILE_B)      // 30720
#define GH_SMEM    (2 * GH_STAGE_B)     // 61440

__device__ __forceinline__ void gh_fill(uint32_t sbase,
    const __half* __restrict__ Ah, const __half* __restrict__ Al,
    const __half* __restrict__ Bs,
    int rowBase, int colBase, int k0)
{
    const int tid = threadIdx.x;
#pragma unroll
    for (int i = 0; i < 6; i++) {
        int idx = tid + i * 256;              // 0..1535
        int arr = idx / 512;                  // 0 Ah, 1 Al, 2 B
        int rem = idx & 511;
        int row = rem >> 2;
        int ch  = rem & 3;
        uint32_t dst = sbase + (uint32_t)(arr * GK_TILE_B + row * 80 + ch * 16);
        const __half* src = (arr == 0) ? Ah : (arr == 1) ? Al : Bs;
        int grow = (arr == 2) ? (colBase + row) : (rowBase + row);
        CP_ASYNC16(dst, src + (size_t)grow * DIM_ + k0 + ch * 8);
    }
}

#define GH_MAINLOOP(Ah, Al, Bs)                                                \
    gh_fill(base, Ah, Al, Bs, rowBase, colBase, 0);                            \
    CP_COMMIT();                                                               \
    const uint32_t aRow = (uint32_t)(wm + (lane & 15));                        \
    const uint32_t bRow = (uint32_t)(wn + (lane & 15));                        \
    const uint32_t kHalf = (uint32_t)((lane >> 4) * 16);                       \
    for (int it = 0; it < GK_NIT; it++) {                                      \
        CP_WAIT(0);                                                            \
        __syncthreads();                                                       \
        if (it + 1 < GK_NIT)                                                   \
            gh_fill(base + (uint32_t)((it + 1) & 1) * GH_STAGE_B,              \
                    Ah, Al, Bs, rowBase, colBase, (it + 1) * GK_BK);           \
        CP_COMMIT();                                                           \
        const uint32_t sb = base + (uint32_t)(it & 1) * GH_STAGE_B;            \
        _Pragma("unroll")                                                      \
        for (int ks = 0; ks < 2; ks++) {                                       \
            const uint32_t kcol = (uint32_t)(ks * 32) + kHalf;                 \
            uint32_t ah[4][4], al[4][4], bb[4][2];                             \
            _Pragma("unroll")                                                  \
            for (int mi = 0; mi < 4; mi++) {                                   \
                uint32_t off = (aRow + mi * 16) * 80 + kcol;                   \
                LDSM_X4(ah[mi][0], ah[mi][1], ah[mi][2], ah[mi][3], sb + off); \
                LDSM_X4(al[mi][0], al[mi][1], al[mi][2], al[mi][3],            \
                        sb + GK_TILE_B + off);                                 \
            }                                                                  \
            _Pragma("unroll")                                                  \
            for (int np = 0; np < 2; np++) {                                   \
                uint32_t off = 2 * GK_TILE_B + (bRow + np * 16) * 80 + kcol;   \
                uint32_t r0, r1, r2, r3;                                       \
                LDSM_X4(r0, r1, r2, r3, sb + off);                             \
                bb[2 * np][0] = r0; bb[2 * np][1] = r2;                        \
                bb[2 * np + 1][0] = r1; bb[2 * np + 1][1] = r3;                \
            }                                                                  \
            _Pragma("unroll")                                                  \
            for (int mi = 0; mi < 4; mi++)                                     \
                _Pragma("unroll")                                              \
                for (int ni = 0; ni < 4; ni++)                                 \
                    MMAH16816(acc[mi][ni], ah[mi], bb[ni]);                    \
            _Pragma("unroll")                                                  \
            for (int mi = 0; mi < 4; mi++)                                     \
                _Pragma("unroll")                                              \
                for (int ni = 0; ni < 4; ni++)                                 \
                    MMAH16816(acc[mi][ni], al[mi], bb[ni]);                    \
        }                                                                      \
    }

// --------- QKV GEMM (fp16 2-pass): z=0 Q, z=1 K (rope + h/l split),
// ---------                         z=2 V (single fp16)
__global__ __launch_bounds__(256, 2)
void qkv_gemm(const __half* __restrict__ Ah, const __half* __restrict__ Al,
              const __half* __restrict__ Bq, const __half* __restrict__ Bk,
              const __half* __restrict__ Bv,
              __half* __restrict__ Qh, __half* __restrict__ Ql,
              __half* __restrict__ Kh, __half* __restrict__ Kl,
              __half* __restrict__ V,
              const float* __restrict__ fcos, const float* __restrict__ fsin)
{
    extern __shared__ char sm[];
    const uint32_t base = smem_u32(sm);
    const int lane = threadIdx.x & 31;
    const int wid  = threadIdx.x >> 5;
    const int rowBase = blockIdx.y * 128;
    const int colBase = blockIdx.x * 128;
    const int wm = (wid & 1) * 64;
    const int wn = (wid >> 1) * 32;
    const int z = blockIdx.z;

    const __half* Bs = (z == 0) ? Bq : (z == 1) ? Bk : Bv;

    float acc[4][4][4];
#pragma unroll
    for (int mi = 0; mi < 4; mi++)
#pragma unroll
        for (int ni = 0; ni < 4; ni++)
#pragma unroll
            for (int q = 0; q < 4; q++) acc[mi][ni][q] = 0.f;

    GH_MAINLOOP(Ah, Al, Bs)

    const int r0 = rowBase + wm + (lane >> 2);
    const int c0 = colBase + wn + (lane & 3) * 2;

    if (z == 2) {
#pragma unroll
        for (int mi = 0; mi < 4; mi++)
#pragma unroll
            for (int ni = 0; ni < 4; ni++) {
                size_t off = (size_t)(r0 + mi * 16) * DIM_ + c0 + ni * 8;
                *(__half2*)(V + off) =
                    __floats2half2_rn(acc[mi][ni][0], acc[mi][ni][1]);
                *(__half2*)(V + off + 8 * DIM_) =
                    __floats2half2_rn(acc[mi][ni][2], acc[mi][ni][3]);
            }
        return;
    }

    __half* Xh = (z == 0) ? Qh : Kh;
    __half* Xl = (z == 0) ? Ql : Kl;
#pragma unroll
    for (int mi = 0; mi < 4; mi++) {
        int r  = r0 + mi * 16;
        int s1 = r & (S_ - 1);
        int s2 = (r + 8) & (S_ - 1);
#pragma unroll
        for (int ni = 0; ni < 4; ni++) {
            int c = c0 + ni * 8;
            float v0 = acc[mi][ni][0], v1 = acc[mi][ni][1];
            float v2 = acc[mi][ni][2], v3 = acc[mi][ni][3];
            int i = (c & (D_ - 1)) >> 1;
            float c1 = fcos[s1 * 64 + i], n1 = fsin[s1 * 64 + i];
            float c2 = fcos[s2 * 64 + i], n2 = fsin[s2 * 64 + i];
            float t;
            t = v0 * c1 - v1 * n1; v1 = v0 * n1 + v1 * c1; v0 = t;
            t = v2 * c2 - v3 * n2; v3 = v2 * n2 + v3 * c2; v2 = t;
            split_store_h(Xh, Xl, (size_t)r * DIM_ + c, v0, v1);
            split_store_h(Xh, Xl, (size_t)(r + 8) * DIM_ + c, v2, v3);
        }
    }
}

// --------- out GEMM (fp16 2-pass): fp32 C ---------
__global__ __launch_bounds__(256, 2)
void o_gemm(const __half* __restrict__ Ah, const __half* __restrict__ Al,
            const __half* __restrict__ Bs, float* __restrict__ C)
{
    extern __shared__ char sm[];
    const uint32_t base = smem_u32(sm);
    const int lane = threadIdx.x & 31;
    const int wid  = threadIdx.x >> 5;
    const int rowBase = blockIdx.y * 128;
    const int colBase = blockIdx.x * 128;
    const int wm = (wid & 1) * 64;
    const int wn = (wid >> 1) * 32;

    float acc[4][4][4];
#pragma unroll
    for (int mi = 0; mi < 4; mi++)
#pragma unroll
        for (int ni = 0; ni < 4; ni++)
#pragma unroll
            for (int q = 0; q < 4; q++) acc[mi][ni][q] = 0.f;

    GH_MAINLOOP(Ah, Al, Bs)

    const int r0 = rowBase + wm + (lane >> 2);
    const int c0 = colBase + wn + (lane & 3) * 2;
#pragma unroll
    for (int mi = 0; mi < 4; mi++)
#pragma unroll
        for (int ni = 0; ni < 4; ni++) {
            float* p = C + (size_t)(r0 + mi * 16) * DIM_ + c0 + ni * 8;
            *(float2*)p = make_float2(acc[mi][ni][0], acc[mi][ni][1]);
            *(float2*)(p + 8 * DIM_) = make_float2(acc[mi][ni][2], acc[mi][ni][3]);
        }
}

// ============================================================================
// split_all: y=0 x -> fp16 hi/lo; y=1..4 wq,wk,wv,wo -> single fp16
// ============================================================================
__global__ void split_all(const float* __restrict__ x,  const float* __restrict__ wq,
                          const float* __restrict__ wk, const float* __restrict__ wv,
                          const float* __restrict__ wo,
                          __half* x16h, __half* x16l,
                          __half* wq16, __half* wk16,
                          __half* wv16, __half* wo16)
{
    size_t i = (size_t)blockIdx.x * blockDim.x + threadIdx.x;
    const int y = blockIdx.y;

    if (y > 0) {
        const float* src = (y == 1) ? wq : (y == 2) ? wk : (y == 3) ? wv : wo;
        __half* dst = (y == 1) ? wq16 : (y == 2) ? wk16 : (y == 3) ? wv16 : wo16;
        float4 v = ((const float4*)src)[i];
        ((__half2*)dst)[2 * i]     = __floats2half2_rn(v.x, v.y);
        ((__half2*)dst)[2 * i + 1] = __floats2half2_rn(v.z, v.w);
        return;
    }

    float4 v = ((const float4*)x)[i];
    __half a0 = __float2half_rn(v.x), a1 = __float2half_rn(v.y);
    __half a2 = __float2half_rn(v.z), a3 = __float2half_rn(v.w);
    ((__half2*)x16h)[2 * i]     = __half2(a0, a1);
    ((__half2*)x16h)[2 * i + 1] = __half2(a2, a3);
    ((__half2*)x16l)[2 * i] = __half2(
        __float2half_rn(v.x - __half2float(a0)),
        __float2half_rn(v.y - __half2float(a1)));
    ((__half2*)x16l)[2 * i + 1] = __half2(
        __float2half_rn(v.z - __half2float(a2)),
        __float2half_rn(v.w - __half2float(a3)));
}

// ============================================================================
// adapter GEMV (fp32)
// ============================================================================
__global__ __launch_bounds__(256)
void adapter_gemv(const float* __restrict__ A, const float* __restrict__ W,
                  float* __restrict__ out)
{
    int warp = (blockIdx.x * blockDim.x + threadIdx.x) >> 5;
    int lane = threadIdx.x & 31;
    int e0 = warp * 4;

    float acc[ADL_][4];
#pragma unroll
    for (int l = 0; l < ADL_; l++)
#pragma unroll
        for (int j = 0; j < 4; j++) acc[l][j] = 0.f;

    for (int d = lane * 4; d < DIM_; d += 128) {
        float4 w4[4];
#pragma unroll
        for (int j = 0; j < 4; j++)
            w4[j] = *(const float4*)(W + (size_t)(e0 + j) * DIM_ + d);
#pragma unroll
        for (int l = 0; l < ADL_; l++) {
            float4 a4 = *(const float4*)(A + (size_t)l * DIM_ + d);
#pragma unroll
            for (int j = 0; j < 4; j++) {
                acc[l][j] = fmaf(a4.x, w4[j].x, acc[l][j]);
                acc[l][j] = fmaf(a4.y, w4[j].y, acc[l][j]);
                acc[l][j] = fmaf(a4.z, w4[j].z, acc[l][j]);
                acc[l][j] = fmaf(a4.w, w4[j].w, acc[l][j]);
            }
        }
    }
#pragma unroll
    for (int l = 0; l < ADL_; l++)
#pragma unroll
        for (int j = 0; j < 4; j++) {
            float v = acc[l][j];
#pragma unroll
            for (int off = 16; off; off >>= 1)
                v += __shfl_xor_sync(0xffffffffu, v, off);
            if (lane == 0) out[l * DIM_ + e0 + j] = v;
        }
}

// ============================================================================
// Flash attention: QK fp16 3-pass (Qh/Ql, Kh/Kl), PV fp16 2-pass (V single).
// 64 q-rows/CTA, 128 threads, single-buffered KV, 2 CTA/SM.
// ============================================================================
#define FRSTR   272
#define FQ_TILE (64 * FRSTR)
#define FK_TILE (64 * FRSTR)
#define FSTAGE  (3 * FK_TILE)
#define FLASH_SMEM (2 * FQ_TILE + FSTAGE)    // 87040

__device__ __forceinline__ void fkv_fill(uint32_t sdst,
    const __half* __restrict__ Kh, const __half* __restrict__ Kl,
    const __half* __restrict__ V,
    int b, int h, int kv0)
{
    const int tid = threadIdx.x;
    const size_t gbase = ((size_t)(b * S_) + kv0) * DIM_ + h * D_;
#pragma unroll
    for (int i = 0; i < 24; i++) {
        int idx = tid + i * 128;
        int arr = idx >> 10;
        int rem = idx & 1023;
        int row = rem >> 4;
        int ch  = rem & 15;
        uint32_t dst = sdst + arr * FK_TILE + row * FRSTR + ch * 16;
        size_t src = gbase + (size_t)row * DIM_ + ch * 8;
        if (arr == 0)      CP_ASYNC16(dst, Kh + src);
        else if (arr == 1) CP_ASYNC16(dst, Kl + src);
        else               CP_ASYNC16(dst, V + src);
    }
}

__global__ __launch_bounds__(128, 2)
void flash_mma(const __half* __restrict__ Qh_g, const __half* __restrict__ Ql_g,
               const __half* __restrict__ Kh_g, const __half* __restrict__ Kl_g,
               const __half* __restrict__ V_g,
               const float* __restrict__ aK, const float* __restrict__ aV,
               const float* __restrict__ gate,
               __half* __restrict__ Oh, __half* __restrict__ Ol)
{
    extern __shared__ char sm[];
    const uint32_t base = smem_u32(sm);
    const int tid  = threadIdx.x;
    const int wid  = tid >> 5;
    const int lane = tid & 31;
    const int qt = (int)gridDim.x - 1 - (int)blockIdx.x;
    const int h = blockIdx.y, b = blockIdx.z;
    const int nkt = qt + 1;

    const uint32_t sQh = base;
    const uint32_t sKV = base + 2 * FQ_TILE;

    {
        size_t gq = ((size_t)(b * S_) + qt * 64) * DIM_ + h * D_;
#pragma unroll
        for (int i = 0; i < 8; i++) {
            int idx = tid + i * 128;
            int row = idx >> 4, ch = idx & 15;
            uint32_t d = row * FRSTR + ch * 16;
            size_t src = gq + (size_t)row * DIM_ + ch * 8;
            CP_ASYNC16(sQh + d,           Qh_g + src);
            CP_ASYNC16(sQh + FQ_TILE + d, Ql_g + src);
        }
    }
    fkv_fill(sKV, Kh_g, Kl_g, V_g, b, h, 0);
    CP_COMMIT();

    const int q0  = qt * 64 + wid * 16;
    const int qg0 = q0 + (lane >> 2);
    const int qg1 = qg0 + 8;
    const float scl = 0.08838834764831845f;

    float m0 = -1e30f, m1 = -1e30f, l0 = 0.f, l1 = 0.f;
    float o[16][4];
#pragma unroll
    for (int d = 0; d < 16; d++)
#pragma unroll
        for (int q = 0; q < 4; q++) o[d][q] = 0.f;

    const uint32_t kh16 = (uint32_t)((lane >> 4) * 16);

    for (int kt = 0; kt < nkt; kt++) {
        CP_WAIT(0);
        __syncthreads();

        const uint32_t st = sKV;
        const int kv0 = kt * 64;

        // ---- S = Q K^T (fp16 3-pass: QhKh + QhKl + QlKh) ----
        float sa[8][4];
#pragma unroll
        for (int n8 = 0; n8 < 8; n8++)
#pragma unroll
            for (int q = 0; q < 4; q++) sa[n8][q] = 0.f;

        const uint32_t qrow = (uint32_t)(wid * 16 + (lane & 15));
        const uint32_t klrow = (uint32_t)(lane & 15);

#pragma unroll
        for (int ch = 0; ch < 8; ch++) {
            uint32_t qa = sQh + qrow * FRSTR + ch * 32 + kh16;
            uint32_t qh[4], ql[4];
            LDSM_X4(qh[0], qh[1], qh[2], qh[3], qa);
            LDSM_X4(ql[0], ql[1], ql[2], ql[3], qa + FQ_TILE);
            uint32_t kb[8][2], lb[8][2];
#pragma unroll
            for (int nb = 0; nb < 4; nb++) {
                uint32_t ka = st + (klrow + nb * 16) * FRSTR + ch * 32 + kh16;
                uint32_t r0, r1, r2, r3;
                LDSM_X4(r0, r1, r2, r3, ka);
                kb[2 * nb][0] = r0; kb[2 * nb][1] = r2;
                kb[2 * nb + 1][0] = r1; kb[2 * nb + 1][1] = r3;
                LDSM_X4(r0, r1, r2, r3, ka + FK_TILE);
                lb[2 * nb][0] = r0; lb[2 * nb][1] = r2;
                lb[2 * nb + 1][0] = r1; lb[2 * nb + 1][1] = r3;
            }
#pragma unroll
            for (int n8 = 0; n8 < 8; n8++) MMAH16816(sa[n8], qh, kb[n8]);
#pragma unroll
            for (int n8 = 0; n8 < 8; n8++) MMAH16816(sa[n8], qh, lb[n8]);
#pragma unroll
            for (int n8 = 0; n8 < 8; n8++) MMAH16816(sa[n8], ql, kb[n8]);
        }

        // ---- mask + online softmax ----
        float rmax0 = -1e30f, rmax1 = -1e30f;
        const int kvb = kv0 + (lane & 3) * 2;
#pragma unroll
        for (int n8 = 0; n8 < 8; n8++) {
            int kvc = kvb + n8 * 8;
            float s0 = sa[n8][0] * scl, s1 = sa[n8][1] * scl;
            float s2 = sa[n8][2] * scl, s3 = sa[n8][3] * scl;
            if (kvc     > qg0) s0 = -1e30f;
            if (kvc + 1 > qg0) s1 = -1e30f;
            if (kvc     > qg1) s2 = -1e30f;
            if (kvc + 1 > qg1) s3 = -1e30f;
            sa[n8][0] = s0; sa[n8][1] = s1; sa[n8][2] = s2; sa[n8][3] = s3;
            rmax0 = fmaxf(rmax0, fmaxf(s0, s1));
            rmax1 = fmaxf(rmax1, fmaxf(s2, s3));
        }
        rmax0 = fmaxf(rmax0, __shfl_xor_sync(0xffffffffu, rmax0, 1));
        rmax0 = fmaxf(rmax0, __shfl_xor_sync(0xffffffffu, rmax0, 2));
        rmax1 = fmaxf(rmax1, __shfl_xor_sync(0xffffffffu, rmax1, 1));
        rmax1 = fmaxf(rmax1, __shfl_xor_sync(0xffffffffu, rmax1, 2));

        float mn0 = fmaxf(m0, rmax0), mn1 = fmaxf(m1, rmax1);
        float sc0 = __expf(m0 - mn0), sc1 = __expf(m1 - mn1);
        m0 = mn0; m1 = mn1;

        uint32_t ph[16], pl[16];
        float rs0 = 0.f, rs1 = 0.f;
#pragma unroll
        for (int n8 = 0; n8 < 8; n8++) {
            float p0 = __expf(sa[n8][0] - mn0);
            float p1 = __expf(sa[n8][1] - mn0);
            float p2 = __expf(sa[n8][2] - mn1);
            float p3 = __expf(sa[n8][3] - mn1);
            rs0 += p0 + p1; rs1 += p2 + p3;
            float h0 = __half2float(__float2half_rn(p0));
            float h1 = __half2float(__float2half_rn(p1));
            float h2 = __half2float(__float2half_rn(p2));
            float h3 = __half2float(__float2half_rn(p3));
            ph[2 * n8]     = pack_h2(h0, h1);
            ph[2 * n8 + 1] = pack_h2(h2, h3);
            pl[2 * n8]     = pack_h2(p0 - h0, p1 - h1);
            pl[2 * n8 + 1] = pack_h2(p2 - h2, p3 - h3);
        }
        rs0 += __shfl_xor_sync(0xffffffffu, rs0, 1);
        rs0 += __shfl_xor_sync(0xffffffffu, rs0, 2);
        rs1 += __shfl_xor_sync(0xffffffffu, rs1, 1);
        rs1 += __shfl_xor_sync(0xffffffffu, rs1, 2);
        l0 = l0 * sc0 + rs0;
        l1 = l1 * sc1 + rs1;

#pragma unroll
        for (int d = 0; d < 16; d++) {
            o[d][0] *= sc0; o[d][1] *= sc0;
            o[d][2] *= sc1; o[d][3] *= sc1;
        }

        // ---- O += P V (fp16 2-pass, V single) ----
#pragma unroll
        for (int j = 0; j < 4; j++) {
            uint32_t ah[4] = {ph[4*j], ph[4*j+1], ph[4*j+2], ph[4*j+3]};
            uint32_t al[4] = {pl[4*j], pl[4*j+1], pl[4*j+2], pl[4*j+3]};
#pragma unroll
            for (int half = 0; half < 2; half++) {
                uint32_t vv[8][2];
#pragma unroll
                for (int k = 0; k < 4; k++) {
                    int nb = half * 4 + k;
                    uint32_t va = st + 2 * FK_TILE +
                                  (uint32_t)(j * 16 + (lane & 15)) * FRSTR +
                                  nb * 32 + kh16;
                    uint32_t r0, r1, r2, r3;
                    LDSM_X4_T(r0, r1, r2, r3, va);
                    vv[2 * k][0] = r0; vv[2 * k][1] = r1;
                    vv[2 * k + 1][0] = r2; vv[2 * k + 1][1] = r3;
                }
                const int ob = half * 8;
#pragma unroll
                for (int n = 0; n < 8; n++) MMAH16816(o[ob + n], ah, vv[n]);
#pragma unroll
                for (int n = 0; n < 8; n++) MMAH16816(o[ob + n], al, vv[n]);
            }
        }

        __syncthreads();
        if (kt + 1 < nkt) {
            fkv_fill(sKV, Kh_g, Kl_g, V_g, b, h, (kt + 1) * 64);
            CP_COMMIT();
        }
    }

    // ---- epilogue: adapter attention (staged into dead KV smem) ----
    float* aKs = (float*)(sm + 2 * FQ_TILE);
    float* aVs = aKs + ADL_ * D_;
    for (int idx = tid; idx < ADL_ * D_; idx += 128) {
        int t = idx >> 7, cc = idx & (D_ - 1);
        aKs[idx] = aK[t * DIM_ + h * D_ + cc];
        aVs[idx] = aV[t * DIM_ + h * D_ + cc];
    }
    __syncthreads();

    const float g = tanhf(gate[h]);
    const float inv0 = 1.0f / l0, inv1 = 1.0f / l1;
    const int ccb = (lane & 3) * 2;

#pragma unroll
    for (int rr = 0; rr < 2; rr++) {
        const int lr = wid * 16 + (lane >> 2) + rr * 8;
        const float inv = rr ? inv1 : inv0;
        const size_t rowg = (size_t)(b * S_) + qt * 64 + lr;

        float qv[32];
#pragma unroll
        for (int d = 0; d < 16; d++) {
            int cc = d * 8 + ccb;
            __half2 hh = *(__half2*)(sm + lr * FRSTR + cc * 2);
            __half2 ll = *(__half2*)(sm + FQ_TILE + lr * FRSTR + cc * 2);
            qv[2 * d]     = __half2float(hh.x) + __half2float(ll.x);
            qv[2 * d + 1] = __half2float(hh.y) + __half2float(ll.y);
        }
        float sc[ADL_];
#pragma unroll
        for (int t = 0; t < ADL_; t++) {
            float p = 0.f;
#pragma unroll
            for (int d = 0; d < 16; d++) {
                int cc = d * 8 + ccb;
                p = fmaf(qv[2 * d],     aKs[t * D_ + cc],     p);
                p = fmaf(qv[2 * d + 1], aKs[t * D_ + cc + 1], p);
            }
            p += __shfl_xor_sync(0xffffffffu, p, 1);
            p += __shfl_xor_sync(0xffffffffu, p, 2);
            sc[t] = p * scl;
        }
        float mx = sc[0];
#pragma unroll
        for (int t = 1; t < ADL_; t++) mx = fmaxf(mx, sc[t]);
        float sum = 0.f;
#pragma unroll
        for (int t = 0; t < ADL_; t++) { sc[t] = __expf(sc[t] - mx); sum += sc[t]; }
        float isum = g / sum;
#pragma unroll
        for (int t = 0; t < ADL_; t++) sc[t] *= isum;

#pragma unroll
        for (int d = 0; d < 16; d++) {
            int cc = d * 8 + ccb;
            float a0 = 0.f, a1 = 0.f;
#pragma unroll
            for (int t = 0; t < ADL_; t++) {
                a0 = fmaf(sc[t], aVs[t * D_ + cc],     a0);
                a1 = fmaf(sc[t], aVs[t * D_ + cc + 1], a1);
            }
            float o0 = o[d][rr * 2]     * inv + a0;
            float o1 = o[d][rr * 2 + 1] * inv + a1;
            split_store_h(Oh, Ol, rowg * DIM_ + h * D_ + cc, o0, o1);
        }
    }
}

// ============================================================================
// launch
// ============================================================================
extern "C" void kernel_launch(void* const* d_in, const int* in_sizes, int n_in,
                              void* d_out, int out_size)
{
    const float* x       = (const float*)d_in[0];
    const float* wq      = (const float*)d_in[1];
    const float* wk      = (const float*)d_in[2];
    const float* wv      = (const float*)d_in[3];
    const float* wo      = (const float*)d_in[4];
    const float* gate    = (const float*)d_in[5];
    const float* adapter = (const float*)d_in[6];
    const float* fcos    = (const float*)d_in[7];
    const float* fsin    = (const float*)d_in[8];
    float* out = (float*)d_out;

    float *aKp, *aVp;
    cudaGetSymbolAddress((void**)&aKp, g_aK);
    cudaGetSymbolAddress((void**)&aVp, g_aV);

    __half *x16h, *x16l, *wq16, *wk16, *wv16, *wo16;
    __half *q16h, *q16l, *k16h, *k16l, *v16, *o16h, *o16l;
    cudaGetSymbolAddress((void**)&x16h, g_x16h); cudaGetSymbolAddress((void**)&x16l, g_x16l);
    cudaGetSymbolAddress((void**)&wq16, g_wq16); cudaGetSymbolAddress((void**)&wk16, g_wk16);
    cudaGetSymbolAddress((void**)&wv16, g_wv16); cudaGetSymbolAddress((void**)&wo16, g_wo16);
    cudaGetSymbolAddress((void**)&q16h, g_q16h); cudaGetSymbolAddress((void**)&q16l, g_q16l);
    cudaGetSymbolAddress((void**)&k16h, g_k16h); cudaGetSymbolAddress((void**)&k16l, g_k16l);
    cudaGetSymbolAddress((void**)&v16,  g_v16);
    cudaGetSymbolAddress((void**)&o16h, g_o16h); cudaGetSymbolAddress((void**)&o16l, g_o16l);

    cudaFuncSetAttribute(qkv_gemm,
                         cudaFuncAttributeMaxDynamicSharedMemorySize, GH_SMEM);
    cudaFuncSetAttribute(o_gemm,
                         cudaFuncAttributeMaxDynamicSharedMemorySize, GH_SMEM);
    cudaFuncSetAttribute(flash_mma,
                         cudaFuncAttributeMaxDynamicSharedMemorySize, FLASH_SMEM);

    split_all<<<dim3(NELEM / 4 / 256, 5), 256>>>(x, wq, wk, wv, wo,
        x16h, x16l, wq16, wk16, wv16, wo16);

    adapter_gemv<<<128, 256>>>(adapter, wk, aKp);
    adapter_gemv<<<128, 256>>>(adapter, wv, aVp);

    qkv_gemm<<<dim3(DIM_ / 128, MROWS / 128, 3), 256, GH_SMEM>>>(
        x16h, x16l, wq16, wk16, wv16,
        q16h, q16l, k16h, k16l, v16, fcos, fsin);

    flash_mma<<<dim3(S_ / 64, H_, B_), 128, FLASH_SMEM>>>(
        q16h, q16l, k16h, k16l, v16, aKp, aVp, gate, o16h, o16l);

    o_gemm<<<dim3(DIM_ / 128, MROWS / 128), 256, GH_SMEM>>>(
        o16h, o16l, wo16, out);
}

// round 14
// speedup vs baseline: 1.8140x; 1.2336x over previous
#include <cuda_runtime.h>
#include <cuda_bf16.h>
#include <cuda_fp16.h>
#include <math.h>
#include <stdint.h>

// ---------------------------------------------------------------- constants
#define B_    2
#define S_    2048
#define H_    32
#define D_    128
#define DIM_  4096
#define ADL_  10
#define MROWS (B_ * S_)
#define NELEM ((size_t)MROWS * DIM_)

// ---------------------------------------------------------------- scratch
__device__ float g_aK[ADL_ * DIM_];
__device__ float g_aV[ADL_ * DIM_];

__device__ __half g_x16h[NELEM], g_x16l[NELEM];
__device__ __half g_wq16[NELEM], g_wk16[NELEM];
__device__ __half g_wv16[NELEM], g_wo16[NELEM];
__device__ __half g_q16h[NELEM], g_q16l[NELEM];
__device__ __half g_k16h[NELEM], g_k16l[NELEM];
__device__ __half g_v16[NELEM];
__device__ __half g_o16[NELEM];

// ---------------------------------------------------------------- PTX utils
__device__ __forceinline__ uint32_t smem_u32(const void* p) {
    uint32_t a;
    asm("{ .reg .u64 t; cvta.to.shared.u64 t, %1; cvt.u32.u64 %0, t; }"
        : "=r"(a) : "l"(p));
    return a;
}
#define CP_ASYNC16(dst, src) \
    asm volatile("cp.async.cg.shared.global [%0], [%1], 16;" \
                 :: "r"(dst), "l"(src) : "memory")
#define CP_COMMIT() asm volatile("cp.async.commit_group;" ::: "memory")
#define CP_WAIT(n)  asm volatile("cp.async.wait_group %0;" :: "n"(n) : "memory")

#define LDSM_X4(r0, r1, r2, r3, addr) \
    asm volatile("ldmatrix.sync.aligned.m8n8.x4.shared.b16 {%0,%1,%2,%3}, [%4];" \
                 : "=r"(r0), "=r"(r1), "=r"(r2), "=r"(r3) : "r"(addr))
#define LDSM_X4_T(r0, r1, r2, r3, addr) \
    asm volatile("ldmatrix.sync.aligned.m8n8.x4.trans.shared.b16 {%0,%1,%2,%3}, [%4];" \
                 : "=r"(r0), "=r"(r1), "=r"(r2), "=r"(r3) : "r"(addr))

#define MMAH16816(c, a, b) \
    asm volatile("mma.sync.aligned.m16n8k16.row.col.f32.f16.f16.f32 " \
                 "{%0,%1,%2,%3}, {%4,%5,%6,%7}, {%8,%9}, {%0,%1,%2,%3};" \
                 : "+f"((c)[0]), "+f"((c)[1]), "+f"((c)[2]), "+f"((c)[3]) \
                 : "r"((a)[0]), "r"((a)[1]), "r"((a)[2]), "r"((a)[3]), \
                   "r"((b)[0]), "r"((b)[1]))

__device__ __forceinline__ uint32_t pack_h2(float lo, float hi) {
    __half2 t = __floats2half2_rn(lo, hi);
    return *(uint32_t*)&t;
}
__device__ __forceinline__ void split_store_h(__half* Xh, __half* Xl,
                                              size_t off, float v0, float v1) {
    __half h0 = __float2half_rn(v0);
    __half h1 = __float2half_rn(v1);
    *(__half2*)(Xh + off) = __half2(h0, h1);
    *(__half2*)(Xl + off) = __half2(
        __float2half_rn(v0 - __half2float(h0)),
        __float2half_rn(v1 - __half2float(h1)));
}

// ============================================================================
// fp16 GEMM core (A hi/lo + B single, pass-2 optional): 128x128, BK=32,
// 2-stage, 2 CTA/SM.
// ============================================================================
#define GK_BK      32
#define GK_TILE_B  10240
#define GK_NIT     (DIM_ / GK_BK)
#define GH_STAGE_B (3 * GK_TILE_B)      // 30720
#define GH_SMEM    (2 * GH_STAGE_B)     // 61440

__device__ __forceinline__ void gh_fill(uint32_t sbase,
    const __half* __restrict__ Ah, const __half* __restrict__ Al,
    const __half* __restrict__ Bs,
    int rowBase, int colBase, int k0)
{
    const int tid = threadIdx.x;
#pragma unroll
    for (int i = 0; i < 6; i++) {
        int idx = tid + i * 256;
        int arr = idx / 512;
        int rem = idx & 511;
        int row = rem >> 2;
        int ch  = rem & 3;
        uint32_t dst = sbase + (uint32_t)(arr * GK_TILE_B + row * 80 + ch * 16);
        const __half* src = (arr == 0) ? Ah : (arr == 1) ? Al : Bs;
        int grow = (arr == 2) ? (colBase + row) : (rowBase + row);
        CP_ASYNC16(dst, src + (size_t)grow * DIM_ + k0 + ch * 8);
    }
}

// do2: include the Al pass (runtime-uniform per CTA)
#define GH_MAINLOOP(Ah, Al, Bs, do2)                                           \
    gh_fill(base, Ah, Al, Bs, rowBase, colBase, 0);                            \
    CP_COMMIT();                                                               \
    const uint32_t aRow = (uint32_t)(wm + (lane & 15));                        \
    const uint32_t bRow = (uint32_t)(wn + (lane & 15));                        \
    const uint32_t kHalf = (uint32_t)((lane >> 4) * 16);                       \
    for (int it = 0; it < GK_NIT; it++) {                                      \
        CP_WAIT(0);                                                            \
        __syncthreads();                                                       \
        if (it + 1 < GK_NIT)                                                   \
            gh_fill(base + (uint32_t)((it + 1) & 1) * GH_STAGE_B,              \
                    Ah, Al, Bs, rowBase, colBase, (it + 1) * GK_BK);           \
        CP_COMMIT();                                                           \
        const uint32_t sb = base + (uint32_t)(it & 1) * GH_STAGE_B;            \
        _Pragma("unroll")                                                      \
        for (int ks = 0; ks < 2; ks++) {                                       \
            const uint32_t kcol = (uint32_t)(ks * 32) + kHalf;                 \
            uint32_t ah[4][4], al[4][4], bb[4][2];                             \
            _Pragma("unroll")                                                  \
            for (int mi = 0; mi < 4; mi++) {                                   \
                uint32_t off = (aRow + mi * 16) * 80 + kcol;                   \
                LDSM_X4(ah[mi][0], ah[mi][1], ah[mi][2], ah[mi][3], sb + off); \
            }                                                                  \
            _Pragma("unroll")                                                  \
            for (int np = 0; np < 2; np++) {                                   \
                uint32_t off = 2 * GK_TILE_B + (bRow + np * 16) * 80 + kcol;   \
                uint32_t r0, r1, r2, r3;                                       \
                LDSM_X4(r0, r1, r2, r3, sb + off);                             \
                bb[2 * np][0] = r0; bb[2 * np][1] = r2;                        \
                bb[2 * np + 1][0] = r1; bb[2 * np + 1][1] = r3;                \
            }                                                                  \
            _Pragma("unroll")                                                  \
            for (int mi = 0; mi < 4; mi++)                                     \
                _Pragma("unroll")                                              \
                for (int ni = 0; ni < 4; ni++)                                 \
                    MMAH16816(acc[mi][ni], ah[mi], bb[ni]);                    \
            if (do2) {                                                         \
                _Pragma("unroll")                                              \
                for (int mi = 0; mi < 4; mi++) {                               \
                    uint32_t off = GK_TILE_B + (aRow + mi * 16) * 80 + kcol;   \
                    LDSM_X4(al[mi][0], al[mi][1], al[mi][2], al[mi][3],        \
                            sb + off);                                         \
                }                                                              \
                _Pragma("unroll")                                              \
                for (int mi = 0; mi < 4; mi++)                                 \
                    _Pragma("unroll")                                          \
                    for (int ni = 0; ni < 4; ni++)                             \
                        MMAH16816(acc[mi][ni], al[mi], bb[ni]);                \
            }                                                                  \
        }                                                                      \
    }

// --------- QKV GEMM: z=0 Q (2-pass, rope, h/l out), z=1 K (same),
// ---------           z=2 V (1-pass, single fp16 out)
__global__ __launch_bounds__(256, 2)
void qkv_gemm(const __half* __restrict__ Ah, const __half* __restrict__ Al,
              const __half* __restrict__ Bq, const __half* __restrict__ Bk,
              const __half* __restrict__ Bv,
              __half* __restrict__ Qh, __half* __restrict__ Ql,
              __half* __restrict__ Kh, __half* __restrict__ Kl,
              __half* __restrict__ V,
              const float* __restrict__ fcos, const float* __restrict__ fsin)
{
    extern __shared__ char sm[];
    const uint32_t base = smem_u32(sm);
    const int lane = threadIdx.x & 31;
    const int wid  = threadIdx.x >> 5;
    const int rowBase = blockIdx.y * 128;
    const int colBase = blockIdx.x * 128;
    const int wm = (wid & 1) * 64;
    const int wn = (wid >> 1) * 32;
    const int z = blockIdx.z;

    const __half* Bs = (z == 0) ? Bq : (z == 1) ? Bk : Bv;
    const int do2 = (z != 2);

    float acc[4][4][4];
#pragma unroll
    for (int mi = 0; mi < 4; mi++)
#pragma unroll
        for (int ni = 0; ni < 4; ni++)
#pragma unroll
            for (int q = 0; q < 4; q++) acc[mi][ni][q] = 0.f;

    GH_MAINLOOP(Ah, Al, Bs, do2)

    const int r0 = rowBase + wm + (lane >> 2);
    const int c0 = colBase + wn + (lane & 3) * 2;

    if (z == 2) {
#pragma unroll
        for (int mi = 0; mi < 4; mi++)
#pragma unroll
            for (int ni = 0; ni < 4; ni++) {
                size_t off = (size_t)(r0 + mi * 16) * DIM_ + c0 + ni * 8;
                *(__half2*)(V + off) =
                    __floats2half2_rn(acc[mi][ni][0], acc[mi][ni][1]);
                *(__half2*)(V + off + 8 * DIM_) =
                    __floats2half2_rn(acc[mi][ni][2], acc[mi][ni][3]);
            }
        return;
    }

    __half* Xh = (z == 0) ? Qh : Kh;
    __half* Xl = (z == 0) ? Ql : Kl;
#pragma unroll
    for (int mi = 0; mi < 4; mi++) {
        int r  = r0 + mi * 16;
        int s1 = r & (S_ - 1);
        int s2 = (r + 8) & (S_ - 1);
#pragma unroll
        for (int ni = 0; ni < 4; ni++) {
            int c = c0 + ni * 8;
            float v0 = acc[mi][ni][0], v1 = acc[mi][ni][1];
            float v2 = acc[mi][ni][2], v3 = acc[mi][ni][3];
            int i = (c & (D_ - 1)) >> 1;
            float c1 = fcos[s1 * 64 + i], n1 = fsin[s1 * 64 + i];
            float c2 = fcos[s2 * 64 + i], n2 = fsin[s2 * 64 + i];
            float t;
            t = v0 * c1 - v1 * n1; v1 = v0 * n1 + v1 * c1; v0 = t;
            t = v2 * c2 - v3 * n2; v3 = v2 * n2 + v3 * c2; v2 = t;
            split_store_h(Xh, Xl, (size_t)r * DIM_ + c, v0, v1);
            split_store_h(Xh, Xl, (size_t)(r + 8) * DIM_ + c, v2, v3);
        }
    }
}

// ============================================================================
// 1-pass fp16 GEMM (A single, B single) for the out projection. 2-tile stage.
// ============================================================================
#define GS_STAGE_B (2 * GK_TILE_B)      // 20480
#define GS_SMEM    (2 * GS_STAGE_B)     // 40960

__device__ __forceinline__ void gs_fill(uint32_t sbase,
    const __half* __restrict__ A, const __half* __restrict__ Bs,
    int rowBase, int colBase, int k0)
{
    const int tid = threadIdx.x;
#pragma unroll
    for (int i = 0; i < 4; i++) {
        int idx = tid + i * 256;              // 0..1023
        int arr = idx >> 9;                   // 0 A, 1 B
        int rem = idx & 511;
        int row = rem >> 2;
        int ch  = rem & 3;
        uint32_t dst = sbase + (uint32_t)(arr * GK_TILE_B + row * 80 + ch * 16);
        const __half* src = (arr == 0) ? A : Bs;
        int grow = (arr == 0) ? (rowBase + row) : (colBase + row);
        CP_ASYNC16(dst, src + (size_t)grow * DIM_ + k0 + ch * 8);
    }
}

__global__ __launch_bounds__(256, 2)
void o_gemm(const __half* __restrict__ A, const __half* __restrict__ Bs,
            float* __restrict__ C)
{
    extern __shared__ char sm[];
    const uint32_t base = smem_u32(sm);
    const int lane = threadIdx.x & 31;
    const int wid  = threadIdx.x >> 5;
    const int rowBase = blockIdx.y * 128;
    const int colBase = blockIdx.x * 128;
    const int wm = (wid & 1) * 64;
    const int wn = (wid >> 1) * 32;

    float acc[4][4][4];
#pragma unroll
    for (int mi = 0; mi < 4; mi++)
#pragma unroll
        for (int ni = 0; ni < 4; ni++)
#pragma unroll
            for (int q = 0; q < 4; q++) acc[mi][ni][q] = 0.f;

    gs_fill(base, A, Bs, rowBase, colBase, 0);
    CP_COMMIT();
    const uint32_t aRow = (uint32_t)(wm + (lane & 15));
    const uint32_t bRow = (uint32_t)(wn + (lane & 15));
    const uint32_t kHalf = (uint32_t)((lane >> 4) * 16);

    for (int it = 0; it < GK_NIT; it++) {
        CP_WAIT(0);
        __syncthreads();
        if (it + 1 < GK_NIT)
            gs_fill(base + (uint32_t)((it + 1) & 1) * GS_STAGE_B,
                    A, Bs, rowBase, colBase, (it + 1) * GK_BK);
        CP_COMMIT();
        const uint32_t sb = base + (uint32_t)(it & 1) * GS_STAGE_B;
#pragma unroll
        for (int ks = 0; ks < 2; ks++) {
            const uint32_t kcol = (uint32_t)(ks * 32) + kHalf;
            uint32_t ah[4][4], bb[4][2];
#pragma unroll
            for (int mi = 0; mi < 4; mi++) {
                uint32_t off = (aRow + mi * 16) * 80 + kcol;
                LDSM_X4(ah[mi][0], ah[mi][1], ah[mi][2], ah[mi][3], sb + off);
            }
#pragma unroll
            for (int np = 0; np < 2; np++) {
                uint32_t off = GK_TILE_B + (bRow + np * 16) * 80 + kcol;
                uint32_t r0, r1, r2, r3;
                LDSM_X4(r0, r1, r2, r3, sb + off);
                bb[2 * np][0] = r0; bb[2 * np][1] = r2;
                bb[2 * np + 1][0] = r1; bb[2 * np + 1][1] = r3;
            }
#pragma unroll
            for (int mi = 0; mi < 4; mi++)
#pragma unroll
                for (int ni = 0; ni < 4; ni++)
                    MMAH16816(acc[mi][ni], ah[mi], bb[ni]);
        }
    }

    const int r0 = rowBase + wm + (lane >> 2);
    const int c0 = colBase + wn + (lane & 3) * 2;
#pragma unroll
    for (int mi = 0; mi < 4; mi++)
#pragma unroll
        for (int ni = 0; ni < 4; ni++) {
            float* p = C + (size_t)(r0 + mi * 16) * DIM_ + c0 + ni * 8;
            *(float2*)p = make_float2(acc[mi][ni][0], acc[mi][ni][1]);
            *(float2*)(p + 8 * DIM_) = make_float2(acc[mi][ni][2], acc[mi][ni][3]);
        }
}

// ============================================================================
// split_all: y=0 x -> fp16 hi/lo; y=1..4 wq,wk,wv,wo -> single fp16
// ============================================================================
__global__ void split_all(const float* __restrict__ x,  const float* __restrict__ wq,
                          const float* __restrict__ wk, const float* __restrict__ wv,
                          const float* __restrict__ wo,
                          __half* x16h, __half* x16l,
                          __half* wq16, __half* wk16,
                          __half* wv16, __half* wo16)
{
    size_t i = (size_t)blockIdx.x * blockDim.x + threadIdx.x;
    const int y = blockIdx.y;

    if (y > 0) {
        const float* src = (y == 1) ? wq : (y == 2) ? wk : (y == 3) ? wv : wo;
        __half* dst = (y == 1) ? wq16 : (y == 2) ? wk16 : (y == 3) ? wv16 : wo16;
        float4 v = ((const float4*)src)[i];
        ((__half2*)dst)[2 * i]     = __floats2half2_rn(v.x, v.y);
        ((__half2*)dst)[2 * i + 1] = __floats2half2_rn(v.z, v.w);
        return;
    }

    float4 v = ((const float4*)x)[i];
    __half a0 = __float2half_rn(v.x), a1 = __float2half_rn(v.y);
    __half a2 = __float2half_rn(v.z), a3 = __float2half_rn(v.w);
    ((__half2*)x16h)[2 * i]     = __half2(a0, a1);
    ((__half2*)x16h)[2 * i + 1] = __half2(a2, a3);
    ((__half2*)x16l)[2 * i] = __half2(
        __float2half_rn(v.x - __half2float(a0)),
        __float2half_rn(v.y - __half2float(a1)));
    ((__half2*)x16l)[2 * i + 1] = __half2(
        __float2half_rn(v.z - __half2float(a2)),
        __float2half_rn(v.w - __half2float(a3)));
}

// ============================================================================
// adapter GEMV (fp32)
// ============================================================================
__global__ __launch_bounds__(256)
void adapter_gemv(const float* __restrict__ A, const float* __restrict__ W,
                  float* __restrict__ out)
{
    int warp = (blockIdx.x * blockDim.x + threadIdx.x) >> 5;
    int lane = threadIdx.x & 31;
    int e0 = warp * 4;

    float acc[ADL_][4];
#pragma unroll
    for (int l = 0; l < ADL_; l++)
#pragma unroll
        for (int j = 0; j < 4; j++) acc[l][j] = 0.f;

    for (int d = lane * 4; d < DIM_; d += 128) {
        float4 w4[4];
#pragma unroll
        for (int j = 0; j < 4; j++)
            w4[j] = *(const float4*)(W + (size_t)(e0 + j) * DIM_ + d);
#pragma unroll
        for (int l = 0; l < ADL_; l++) {
            float4 a4 = *(const float4*)(A + (size_t)l * DIM_ + d);
#pragma unroll
            for (int j = 0; j < 4; j++) {
                acc[l][j] = fmaf(a4.x, w4[j].x, acc[l][j]);
                acc[l][j] = fmaf(a4.y, w4[j].y, acc[l][j]);
                acc[l][j] = fmaf(a4.z, w4[j].z, acc[l][j]);
                acc[l][j] = fmaf(a4.w, w4[j].w, acc[l][j]);
            }
        }
    }
#pragma unroll
    for (int l = 0; l < ADL_; l++)
#pragma unroll
        for (int j = 0; j < 4; j++) {
            float v = acc[l][j];
#pragma unroll
            for (int off = 16; off; off >>= 1)
                v += __shfl_xor_sync(0xffffffffu, v, off);
            if (lane == 0) out[l * DIM_ + e0 + j] = v;
        }
}

// ============================================================================
// Flash attention: QK fp16 3-pass, PV fp16 2-pass, single-fp16 O output.
// 64 q-rows/CTA, 128 threads, single-buffered KV, 2 CTA/SM.
// ============================================================================
#define FRSTR   272
#define FQ_TILE (64 * FRSTR)
#define FK_TILE (64 * FRSTR)
#define FSTAGE  (3 * FK_TILE)
#define FLASH_SMEM (2 * FQ_TILE + FSTAGE)    // 87040

__device__ __forceinline__ void fkv_fill(uint32_t sdst,
    const __half* __restrict__ Kh, const __half* __restrict__ Kl,
    const __half* __restrict__ V,
    int b, int h, int kv0)
{
    const int tid = threadIdx.x;
    const size_t gbase = ((size_t)(b * S_) + kv0) * DIM_ + h * D_;
#pragma unroll
    for (int i = 0; i < 24; i++) {
        int idx = tid + i * 128;
        int arr = idx >> 10;
        int rem = idx & 1023;
        int row = rem >> 4;
        int ch  = rem & 15;
        uint32_t dst = sdst + arr * FK_TILE + row * FRSTR + ch * 16;
        size_t src = gbase + (size_t)row * DIM_ + ch * 8;
        if (arr == 0)      CP_ASYNC16(dst, Kh + src);
        else if (arr == 1) CP_ASYNC16(dst, Kl + src);
        else               CP_ASYNC16(dst, V + src);
    }
}

__global__ __launch_bounds__(128, 2)
void flash_mma(const __half* __restrict__ Qh_g, const __half* __restrict__ Ql_g,
               const __half* __restrict__ Kh_g, const __half* __restrict__ Kl_g,
               const __half* __restrict__ V_g,
               const float* __restrict__ aK, const float* __restrict__ aV,
               const float* __restrict__ gate,
               __half* __restrict__ O)
{
    extern __shared__ char sm[];
    const uint32_t base = smem_u32(sm);
    const int tid  = threadIdx.x;
    const int wid  = tid >> 5;
    const int lane = tid & 31;
    const int qt = (int)gridDim.x - 1 - (int)blockIdx.x;
    const int h = blockIdx.y, b = blockIdx.z;
    const int nkt = qt + 1;

    const uint32_t sQh = base;
    const uint32_t sKV = base + 2 * FQ_TILE;

    {
        size_t gq = ((size_t)(b * S_) + qt * 64) * DIM_ + h * D_;
#pragma unroll
        for (int i = 0; i < 8; i++) {
            int idx = tid + i * 128;
            int row = idx >> 4, ch = idx & 15;
            uint32_t d = row * FRSTR + ch * 16;
            size_t src = gq + (size_t)row * DIM_ + ch * 8;
            CP_ASYNC16(sQh + d,           Qh_g + src);
            CP_ASYNC16(sQh + FQ_TILE + d, Ql_g + src);
        }
    }
    fkv_fill(sKV, Kh_g, Kl_g, V_g, b, h, 0);
    CP_COMMIT();

    const int q0  = qt * 64 + wid * 16;
    const int qg0 = q0 + (lane >> 2);
    const int qg1 = qg0 + 8;
    const float scl = 0.08838834764831845f;

    float m0 = -1e30f, m1 = -1e30f, l0 = 0.f, l1 = 0.f;
    float o[16][4];
#pragma unroll
    for (int d = 0; d < 16; d++)
#pragma unroll
        for (int q = 0; q < 4; q++) o[d][q] = 0.f;

    const uint32_t kh16 = (uint32_t)((lane >> 4) * 16);

    for (int kt = 0; kt < nkt; kt++) {
        CP_WAIT(0);
        __syncthreads();

        const uint32_t st = sKV;
        const int kv0 = kt * 64;

        // ---- S = Q K^T (fp16 3-pass) ----
        float sa[8][4];
#pragma unroll
        for (int n8 = 0; n8 < 8; n8++)
#pragma unroll
            for (int q = 0; q < 4; q++) sa[n8][q] = 0.f;

        const uint32_t qrow = (uint32_t)(wid * 16 + (lane & 15));
        const uint32_t klrow = (uint32_t)(lane & 15);

#pragma unroll
        for (int ch = 0; ch < 8; ch++) {
            uint32_t qa = sQh + qrow * FRSTR + ch * 32 + kh16;
            uint32_t qh[4], ql[4];
            LDSM_X4(qh[0], qh[1], qh[2], qh[3], qa);
            LDSM_X4(ql[0], ql[1], ql[2], ql[3], qa + FQ_TILE);
            uint32_t kb[8][2], lb[8][2];
#pragma unroll
            for (int nb = 0; nb < 4; nb++) {
                uint32_t ka = st + (klrow + nb * 16) * FRSTR + ch * 32 + kh16;
                uint32_t r0, r1, r2, r3;
                LDSM_X4(r0, r1, r2, r3, ka);
                kb[2 * nb][0] = r0; kb[2 * nb][1] = r2;
                kb[2 * nb + 1][0] = r1; kb[2 * nb + 1][1] = r3;
                LDSM_X4(r0, r1, r2, r3, ka + FK_TILE);
                lb[2 * nb][0] = r0; lb[2 * nb][1] = r2;
                lb[2 * nb + 1][0] = r1; lb[2 * nb + 1][1] = r3;
            }
#pragma unroll
            for (int n8 = 0; n8 < 8; n8++) MMAH16816(sa[n8], qh, kb[n8]);
#pragma unroll
            for (int n8 = 0; n8 < 8; n8++) MMAH16816(sa[n8], qh, lb[n8]);
#pragma unroll
            for (int n8 = 0; n8 < 8; n8++) MMAH16816(sa[n8], ql, kb[n8]);
        }

        // ---- mask + online softmax ----
        float rmax0 = -1e30f, rmax1 = -1e30f;
        const int kvb = kv0 + (lane & 3) * 2;
#pragma unroll
        for (int n8 = 0; n8 < 8; n8++) {
            int kvc = kvb + n8 * 8;
            float s0 = sa[n8][0] * scl, s1 = sa[n8][1] * scl;
            float s2 = sa[n8][2] * scl, s3 = sa[n8][3] * scl;
            if (kvc     > qg0) s0 = -1e30f;
            if (kvc + 1 > qg0) s1 = -1e30f;
            if (kvc     > qg1) s2 = -1e30f;
            if (kvc + 1 > qg1) s3 = -1e30f;
            sa[n8][0] = s0; sa[n8][1] = s1; sa[n8][2] = s2; sa[n8][3] = s3;
            rmax0 = fmaxf(rmax0, fmaxf(s0, s1));
            rmax1 = fmaxf(rmax1, fmaxf(s2, s3));
        }
        rmax0 = fmaxf(rmax0, __shfl_xor_sync(0xffffffffu, rmax0, 1));
        rmax0 = fmaxf(rmax0, __shfl_xor_sync(0xffffffffu, rmax0, 2));
        rmax1 = fmaxf(rmax1, __shfl_xor_sync(0xffffffffu, rmax1, 1));
        rmax1 = fmaxf(rmax1, __shfl_xor_sync(0xffffffffu, rmax1, 2));

        float mn0 = fmaxf(m0, rmax0), mn1 = fmaxf(m1, rmax1);
        float sc0 = __expf(m0 - mn0), sc1 = __expf(m1 - mn1);
        m0 = mn0; m1 = mn1;

        uint32_t ph[16], pl[16];
        float rs0 = 0.f, rs1 = 0.f;
#pragma unroll
        for (int n8 = 0; n8 < 8; n8++) {
            float p0 = __expf(sa[n8][0] - mn0);
            float p1 = __expf(sa[n8][1] - mn0);
            float p2 = __expf(sa[n8][2] - mn1);
            float p3 = __expf(sa[n8][3] - mn1);
            rs0 += p0 + p1; rs1 += p2 + p3;
            float h0 = __half2float(__float2half_rn(p0));
            float h1 = __half2float(__float2half_rn(p1));
            float h2 = __half2float(__float2half_rn(p2));
            float h3 = __half2float(__float2half_rn(p3));
            ph[2 * n8]     = pack_h2(h0, h1);
            ph[2 * n8 + 1] = pack_h2(h2, h3);
            pl[2 * n8]     = pack_h2(p0 - h0, p1 - h1);
            pl[2 * n8 + 1] = pack_h2(p2 - h2, p3 - h3);
        }
        rs0 += __shfl_xor_sync(0xffffffffu, rs0, 1);
        rs0 += __shfl_xor_sync(0xffffffffu, rs0, 2);
        rs1 += __shfl_xor_sync(0xffffffffu, rs1, 1);
        rs1 += __shfl_xor_sync(0xffffffffu, rs1, 2);
        l0 = l0 * sc0 + rs0;
        l1 = l1 * sc1 + rs1;

#pragma unroll
        for (int d = 0; d < 16; d++) {
            o[d][0] *= sc0; o[d][1] *= sc0;
            o[d][2] *= sc1; o[d][3] *= sc1;
        }

        // ---- O += P V (fp16 2-pass, V single) ----
#pragma unroll
        for (int j = 0; j < 4; j++) {
            uint32_t ah[4] = {ph[4*j], ph[4*j+1], ph[4*j+2], ph[4*j+3]};
            uint32_t al[4] = {pl[4*j], pl[4*j+1], pl[4*j+2], pl[4*j+3]};
#pragma unroll
            for (int half = 0; half < 2; half++) {
                uint32_t vv[8][2];
#pragma unroll
                for (int k = 0; k < 4; k++) {
                    int nb = half * 4 + k;
                    uint32_t va = st + 2 * FK_TILE +
                                  (uint32_t)(j * 16 + (lane & 15)) * FRSTR +
                                  nb * 32 + kh16;
                    uint32_t r0, r1, r2, r3;
                    LDSM_X4_T(r0, r1, r2, r3, va);
                    vv[2 * k][0] = r0; vv[2 * k][1] = r1;
                    vv[2 * k + 1][0] = r2; vv[2 * k + 1][1] = r3;
                }
                const int ob = half * 8;
#pragma unroll
                for (int n = 0; n < 8; n++) MMAH16816(o[ob + n], ah, vv[n]);
#pragma unroll
                for (int n = 0; n < 8; n++) MMAH16816(o[ob + n], al, vv[n]);
            }
        }

        __syncthreads();
        if (kt + 1 < nkt) {
            fkv_fill(sKV, Kh_g, Kl_g, V_g, b, h, (kt + 1) * 64);
            CP_COMMIT();
        }
    }

    // ---- epilogue: adapter attention, single-fp16 output ----
    float* aKs = (float*)(sm + 2 * FQ_TILE);
    float* aVs = aKs + ADL_ * D_;
    for (int idx = tid; idx < ADL_ * D_; idx += 128) {
        int t = idx >> 7, cc = idx & (D_ - 1);
        aKs[idx] = aK[t * DIM_ + h * D_ + cc];
        aVs[idx] = aV[t * DIM_ + h * D_ + cc];
    }
    __syncthreads();

    const float g = tanhf(gate[h]);
    const float inv0 = 1.0f / l0, inv1 = 1.0f / l1;
    const int ccb = (lane & 3) * 2;

#pragma unroll
    for (int rr = 0; rr < 2; rr++) {
        const int lr = wid * 16 + (lane >> 2) + rr * 8;
        const float inv = rr ? inv1 : inv0;
        const size_t rowg = (size_t)(b * S_) + qt * 64 + lr;

        float qv[32];
#pragma unroll
        for (int d = 0; d < 16; d++) {
            int cc = d * 8 + ccb;
            __half2 hh = *(__half2*)(sm + lr * FRSTR + cc * 2);
            __half2 ll = *(__half2*)(sm + FQ_TILE + lr * FRSTR + cc * 2);
            qv[2 * d]     = __half2float(hh.x) + __half2float(ll.x);
            qv[2 * d + 1] = __half2float(hh.y) + __half2float(ll.y);
        }
        float sc[ADL_];
#pragma unroll
        for (int t = 0; t < ADL_; t++) {
            float p = 0.f;
#pragma unroll
            for (int d = 0; d < 16; d++) {
                int cc = d * 8 + ccb;
                p = fmaf(qv[2 * d],     aKs[t * D_ + cc],     p);
                p = fmaf(qv[2 * d + 1], aKs[t * D_ + cc + 1], p);
            }
            p += __shfl_xor_sync(0xffffffffu, p, 1);
            p += __shfl_xor_sync(0xffffffffu, p, 2);
            sc[t] = p * scl;
        }
        float mx = sc[0];
#pragma unroll
        for (int t = 1; t < ADL_; t++) mx = fmaxf(mx, sc[t]);
        float sum = 0.f;
#pragma unroll
        for (int t = 0; t < ADL_; t++) { sc[t] = __expf(sc[t] - mx); sum += sc[t]; }
        float isum = g / sum;
#pragma unroll
        for (int t = 0; t < ADL_; t++) sc[t] *= isum;

#pragma unroll
        for (int d = 0; d < 16; d++) {
            int cc = d * 8 + ccb;
            float a0 = 0.f, a1 = 0.f;
#pragma unroll
            for (int t = 0; t < ADL_; t++) {
                a0 = fmaf(sc[t], aVs[t * D_ + cc],     a0);
                a1 = fmaf(sc[t], aVs[t * D_ + cc + 1], a1);
            }
            float o0 = o[d][rr * 2]     * inv + a0;
            float o1 = o[d][rr * 2 + 1] * inv + a1;
            *(__half2*)(O + rowg * DIM_ + h * D_ + cc) =
                __floats2half2_rn(o0, o1);
        }
    }
}

// ============================================================================
// launch
// ============================================================================
extern "C" void kernel_launch(void* const* d_in, const int* in_sizes, int n_in,
                              void* d_out, int out_size)
{
    const float* x       = (const float*)d_in[0];
    const float* wq      = (const float*)d_in[1];
    const float* wk      = (const float*)d_in[2];
    const float* wv      = (const float*)d_in[3];
    const float* wo      = (const float*)d_in[4];
    const float* gate    = (const float*)d_in[5];
    const float* adapter = (const float*)d_in[6];
    const float* fcos    = (const float*)d_in[7];
    const float* fsin    = (const float*)d_in[8];
    float* out = (float*)d_out;

    float *aKp, *aVp;
    cudaGetSymbolAddress((void**)&aKp, g_aK);
    cudaGetSymbolAddress((void**)&aVp, g_aV);

    __half *x16h, *x16l, *wq16, *wk16, *wv16, *wo16;
    __half *q16h, *q16l, *k16h, *k16l, *v16, *o16;
    cudaGetSymbolAddress((void**)&x16h, g_x16h); cudaGetSymbolAddress((void**)&x16l, g_x16l);
    cudaGetSymbolAddress((void**)&wq16, g_wq16); cudaGetSymbolAddress((void**)&wk16, g_wk16);
    cudaGetSymbolAddress((void**)&wv16, g_wv16); cudaGetSymbolAddress((void**)&wo16, g_wo16);
    cudaGetSymbolAddress((void**)&q16h, g_q16h); cudaGetSymbolAddress((void**)&q16l, g_q16l);
    cudaGetSymbolAddress((void**)&k16h, g_k16h); cudaGetSymbolAddress((void**)&k16l, g_k16l);
    cudaGetSymbolAddress((void**)&v16,  g_v16);
    cudaGetSymbolAddress((void**)&o16,  g_o16);

    cudaFuncSetAttribute(qkv_gemm,
                         cudaFuncAttributeMaxDynamicSharedMemorySize, GH_SMEM);
    cudaFuncSetAttribute(o_gemm,
                         cudaFuncAttributeMaxDynamicSharedMemorySize, GS_SMEM);
    cudaFuncSetAttribute(flash_mma,
                         cudaFuncAttributeMaxDynamicSharedMemorySize, FLASH_SMEM);

    split_all<<<dim3(NELEM / 4 / 256, 5), 256>>>(x, wq, wk, wv, wo,
        x16h, x16l, wq16, wk16, wv16, wo16);

    adapter_gemv<<<128, 256>>>(adapter, wk, aKp);
    adapter_gemv<<<128, 256>>>(adapter, wv, aVp);

    qkv_gemm<<<dim3(DIM_ / 128, MROWS / 128, 3), 256, GH_SMEM>>>(
        x16h, x16l, wq16, wk16, wv16,
        q16h, q16l, k16h, k16l, v16, fcos, fsin);

    flash_mma<<<dim3(S_ / 64, H_, B_), 128, FLASH_SMEM>>>(
        q16h, q16l, k16h, k16l, v16, aKp, aVp, gate, o16);

    o_gemm<<<dim3(DIM_ / 128, MROWS / 128), 256, GS_SMEM>>>(
        o16, wo16, out);
}

// round 15
// speedup vs baseline: 2.4406x; 1.3454x over previous
#include <cuda_runtime.h>
#include <cuda_bf16.h>
#include <cuda_fp16.h>
#include <math.h>
#include <stdint.h>

// ---------------------------------------------------------------- constants
#define B_    2
#define S_    2048
#define H_    32
#define D_    128
#define DIM_  4096
#define ADL_  10
#define MROWS (B_ * S_)
#define NELEM ((size_t)MROWS * DIM_)

// ---------------------------------------------------------------- scratch
__device__ float g_aK[ADL_ * DIM_];
__device__ float g_aV[ADL_ * DIM_];

__device__ __half g_x16[NELEM];
__device__ __half g_wq16[NELEM], g_wk16[NELEM];
__device__ __half g_wv16[NELEM], g_wo16[NELEM];
__device__ __half g_q16h[NELEM], g_q16l[NELEM];
__device__ __half g_k16h[NELEM], g_k16l[NELEM];
__device__ __half g_v16[NELEM];
__device__ __half g_o16[NELEM];

// ---------------------------------------------------------------- PTX utils
__device__ __forceinline__ uint32_t smem_u32(const void* p) {
    uint32_t a;
    asm("{ .reg .u64 t; cvta.to.shared.u64 t, %1; cvt.u32.u64 %0, t; }"
        : "=r"(a) : "l"(p));
    return a;
}
#define CP_ASYNC16(dst, src) \
    asm volatile("cp.async.cg.shared.global [%0], [%1], 16;" \
                 :: "r"(dst), "l"(src) : "memory")
#define CP_COMMIT() asm volatile("cp.async.commit_group;" ::: "memory")
#define CP_WAIT(n)  asm volatile("cp.async.wait_group %0;" :: "n"(n) : "memory")

#define LDSM_X4(r0, r1, r2, r3, addr) \
    asm volatile("ldmatrix.sync.aligned.m8n8.x4.shared.b16 {%0,%1,%2,%3}, [%4];" \
                 : "=r"(r0), "=r"(r1), "=r"(r2), "=r"(r3) : "r"(addr))
#define LDSM_X4_T(r0, r1, r2, r3, addr) \
    asm volatile("ldmatrix.sync.aligned.m8n8.x4.trans.shared.b16 {%0,%1,%2,%3}, [%4];" \
                 : "=r"(r0), "=r"(r1), "=r"(r2), "=r"(r3) : "r"(addr))

#define MMAH16816(c, a, b) \
    asm volatile("mma.sync.aligned.m16n8k16.row.col.f32.f16.f16.f32 " \
                 "{%0,%1,%2,%3}, {%4,%5,%6,%7}, {%8,%9}, {%0,%1,%2,%3};" \
                 : "+f"((c)[0]), "+f"((c)[1]), "+f"((c)[2]), "+f"((c)[3]) \
                 : "r"((a)[0]), "r"((a)[1]), "r"((a)[2]), "r"((a)[3]), \
                   "r"((b)[0]), "r"((b)[1]))

__device__ __forceinline__ uint32_t pack_h2(float lo, float hi) {
    __half2 t = __floats2half2_rn(lo, hi);
    return *(uint32_t*)&t;
}
__device__ __forceinline__ void split_store_h(__half* Xh, __half* Xl,
                                              size_t off, float v0, float v1) {
    __half h0 = __float2half_rn(v0);
    __half h1 = __float2half_rn(v1);
    *(__half2*)(Xh + off) = __half2(h0, h1);
    *(__half2*)(Xl + off) = __half2(
        __float2half_rn(v0 - __half2float(h0)),
        __float2half_rn(v1 - __half2float(h1)));
}

// ============================================================================
// 1-pass fp16 GEMM core (A single, B single): 128x128 tile, BK=32,
// 2-tile stage, 2-stage pipeline, 2 CTA/SM.
// ============================================================================
#define GK_BK      32
#define GK_TILE_B  10240
#define GK_NIT     (DIM_ / GK_BK)
#define GS_STAGE_B (2 * GK_TILE_B)      // 20480
#define GS_SMEM    (2 * GS_STAGE_B)     // 40960

__device__ __forceinline__ void gs_fill(uint32_t sbase,
    const __half* __restrict__ A, const __half* __restrict__ Bs,
    int rowBase, int colBase, int k0)
{
    const int tid = threadIdx.x;
#pragma unroll
    for (int i = 0; i < 4; i++) {
        int idx = tid + i * 256;
        int arr = idx >> 9;
        int rem = idx & 511;
        int row = rem >> 2;
        int ch  = rem & 3;
        uint32_t dst = sbase + (uint32_t)(arr * GK_TILE_B + row * 80 + ch * 16);
        const __half* src = (arr == 0) ? A : Bs;
        int grow = (arr == 0) ? (rowBase + row) : (colBase + row);
        CP_ASYNC16(dst, src + (size_t)grow * DIM_ + k0 + ch * 8);
    }
}

#define GS_MAINLOOP(A, Bs)                                                     \
    gs_fill(base, A, Bs, rowBase, colBase, 0);                                 \
    CP_COMMIT();                                                               \
    const uint32_t aRow = (uint32_t)(wm + (lane & 15));                        \
    const uint32_t bRow = (uint32_t)(wn + (lane & 15));                        \
    const uint32_t kHalf = (uint32_t)((lane >> 4) * 16);                       \
    for (int it = 0; it < GK_NIT; it++) {                                      \
        CP_WAIT(0);                                                            \
        __syncthreads();                                                       \
        if (it + 1 < GK_NIT)                                                   \
            gs_fill(base + (uint32_t)((it + 1) & 1) * GS_STAGE_B,              \
                    A, Bs, rowBase, colBase, (it + 1) * GK_BK);                \
        CP_COMMIT();                                                           \
        const uint32_t sb = base + (uint32_t)(it & 1) * GS_STAGE_B;            \
        _Pragma("unroll")                                                      \
        for (int ks = 0; ks < 2; ks++) {                                       \
            const uint32_t kcol = (uint32_t)(ks * 32) + kHalf;                 \
            uint32_t ah[4][4], bb[4][2];                                       \
            _Pragma("unroll")                                                  \
            for (int mi = 0; mi < 4; mi++) {                                   \
                uint32_t off = (aRow + mi * 16) * 80 + kcol;                   \
                LDSM_X4(ah[mi][0], ah[mi][1], ah[mi][2], ah[mi][3], sb + off); \
            }                                                                  \
            _Pragma("unroll")                                                  \
            for (int np = 0; np < 2; np++) {                                   \
                uint32_t off = GK_TILE_B + (bRow + np * 16) * 80 + kcol;       \
                uint32_t r0, r1, r2, r3;                                       \
                LDSM_X4(r0, r1, r2, r3, sb + off);                             \
                bb[2 * np][0] = r0; bb[2 * np][1] = r2;                        \
                bb[2 * np + 1][0] = r1; bb[2 * np + 1][1] = r3;                \
            }                                                                  \
            _Pragma("unroll")                                                  \
            for (int mi = 0; mi < 4; mi++)                                     \
                _Pragma("unroll")                                              \
                for (int ni = 0; ni < 4; ni++)                                 \
                    MMAH16816(acc[mi][ni], ah[mi], bb[ni]);                    \
        }                                                                      \
    }

// --------- QKV GEMM (1-pass): z=0 Q, z=1 K (rope + h/l out), z=2 V (single)
__global__ __launch_bounds__(256, 2)
void qkv_gemm(const __half* __restrict__ X,
              const __half* __restrict__ Bq, const __half* __restrict__ Bk,
              const __half* __restrict__ Bv,
              __half* __restrict__ Qh, __half* __restrict__ Ql,
              __half* __restrict__ Kh, __half* __restrict__ Kl,
              __half* __restrict__ V,
              const float* __restrict__ fcos, const float* __restrict__ fsin)
{
    extern __shared__ char sm[];
    const uint32_t base = smem_u32(sm);
    const int lane = threadIdx.x & 31;
    const int wid  = threadIdx.x >> 5;
    const int rowBase = blockIdx.y * 128;
    const int colBase = blockIdx.x * 128;
    const int wm = (wid & 1) * 64;
    const int wn = (wid >> 1) * 32;
    const int z = blockIdx.z;

    const __half* Bs = (z == 0) ? Bq : (z == 1) ? Bk : Bv;

    float acc[4][4][4];
#pragma unroll
    for (int mi = 0; mi < 4; mi++)
#pragma unroll
        for (int ni = 0; ni < 4; ni++)
#pragma unroll
            for (int q = 0; q < 4; q++) acc[mi][ni][q] = 0.f;

    GS_MAINLOOP(X, Bs)

    const int r0 = rowBase + wm + (lane >> 2);
    const int c0 = colBase + wn + (lane & 3) * 2;

    if (z == 2) {
#pragma unroll
        for (int mi = 0; mi < 4; mi++)
#pragma unroll
            for (int ni = 0; ni < 4; ni++) {
                size_t off = (size_t)(r0 + mi * 16) * DIM_ + c0 + ni * 8;
                *(__half2*)(V + off) =
                    __floats2half2_rn(acc[mi][ni][0], acc[mi][ni][1]);
                *(__half2*)(V + off + 8 * DIM_) =
                    __floats2half2_rn(acc[mi][ni][2], acc[mi][ni][3]);
            }
        return;
    }

    __half* Xh = (z == 0) ? Qh : Kh;
    __half* Xl = (z == 0) ? Ql : Kl;
#pragma unroll
    for (int mi = 0; mi < 4; mi++) {
        int r  = r0 + mi * 16;
        int s1 = r & (S_ - 1);
        int s2 = (r + 8) & (S_ - 1);
#pragma unroll
        for (int ni = 0; ni < 4; ni++) {
            int c = c0 + ni * 8;
            float v0 = acc[mi][ni][0], v1 = acc[mi][ni][1];
            float v2 = acc[mi][ni][2], v3 = acc[mi][ni][3];
            int i = (c & (D_ - 1)) >> 1;
            float c1 = fcos[s1 * 64 + i], n1 = fsin[s1 * 64 + i];
            float c2 = fcos[s2 * 64 + i], n2 = fsin[s2 * 64 + i];
            float t;
            t = v0 * c1 - v1 * n1; v1 = v0 * n1 + v1 * c1; v0 = t;
            t = v2 * c2 - v3 * n2; v3 = v2 * n2 + v3 * c2; v2 = t;
            split_store_h(Xh, Xl, (size_t)r * DIM_ + c, v0, v1);
            split_store_h(Xh, Xl, (size_t)(r + 8) * DIM_ + c, v2, v3);
        }
    }
}

// --------- out GEMM (1-pass): fp32 C ---------
__global__ __launch_bounds__(256, 2)
void o_gemm(const __half* __restrict__ A, const __half* __restrict__ Bs,
            float* __restrict__ C)
{
    extern __shared__ char sm[];
    const uint32_t base = smem_u32(sm);
    const int lane = threadIdx.x & 31;
    const int wid  = threadIdx.x >> 5;
    const int rowBase = blockIdx.y * 128;
    const int colBase = blockIdx.x * 128;
    const int wm = (wid & 1) * 64;
    const int wn = (wid >> 1) * 32;

    float acc[4][4][4];
#pragma unroll
    for (int mi = 0; mi < 4; mi++)
#pragma unroll
        for (int ni = 0; ni < 4; ni++)
#pragma unroll
            for (int q = 0; q < 4; q++) acc[mi][ni][q] = 0.f;

    GS_MAINLOOP(A, Bs)

    const int r0 = rowBase + wm + (lane >> 2);
    const int c0 = colBase + wn + (lane & 3) * 2;
#pragma unroll
    for (int mi = 0; mi < 4; mi++)
#pragma unroll
        for (int ni = 0; ni < 4; ni++) {
            float* p = C + (size_t)(r0 + mi * 16) * DIM_ + c0 + ni * 8;
            *(float2*)p = make_float2(acc[mi][ni][0], acc[mi][ni][1]);
            *(float2*)(p + 8 * DIM_) = make_float2(acc[mi][ni][2], acc[mi][ni][3]);
        }
}

// ============================================================================
// split_all: y=0..4 -> single fp16 (x, wq, wk, wv, wo)
// ============================================================================
__global__ void split_all(const float* __restrict__ x,  const float* __restrict__ wq,
                          const float* __restrict__ wk, const float* __restrict__ wv,
                          const float* __restrict__ wo,
                          __half* x16, __half* wq16, __half* wk16,
                          __half* wv16, __half* wo16)
{
    size_t i = (size_t)blockIdx.x * blockDim.x + threadIdx.x;
    const int y = blockIdx.y;
    const float* src = (y == 0) ? x : (y == 1) ? wq : (y == 2) ? wk
                     : (y == 3) ? wv : wo;
    __half* dst = (y == 0) ? x16 : (y == 1) ? wq16 : (y == 2) ? wk16
                : (y == 3) ? wv16 : wo16;
    float4 v = ((const float4*)src)[i];
    ((__half2*)dst)[2 * i]     = __floats2half2_rn(v.x, v.y);
    ((__half2*)dst)[2 * i + 1] = __floats2half2_rn(v.z, v.w);
}

// ============================================================================
// adapter GEMV (fp32)
// ============================================================================
__global__ __launch_bounds__(256)
void adapter_gemv(const float* __restrict__ A, const float* __restrict__ W,
                  float* __restrict__ out)
{
    int warp = (blockIdx.x * blockDim.x + threadIdx.x) >> 5;
    int lane = threadIdx.x & 31;
    int e0 = warp * 4;

    float acc[ADL_][4];
#pragma unroll
    for (int l = 0; l < ADL_; l++)
#pragma unroll
        for (int j = 0; j < 4; j++) acc[l][j] = 0.f;

    for (int d = lane * 4; d < DIM_; d += 128) {
        float4 w4[4];
#pragma unroll
        for (int j = 0; j < 4; j++)
            w4[j] = *(const float4*)(W + (size_t)(e0 + j) * DIM_ + d);
#pragma unroll
        for (int l = 0; l < ADL_; l++) {
            float4 a4 = *(const float4*)(A + (size_t)l * DIM_ + d);
#pragma unroll
            for (int j = 0; j < 4; j++) {
                acc[l][j] = fmaf(a4.x, w4[j].x, acc[l][j]);
                acc[l][j] = fmaf(a4.y, w4[j].y, acc[l][j]);
                acc[l][j] = fmaf(a4.z, w4[j].z, acc[l][j]);
                acc[l][j] = fmaf(a4.w, w4[j].w, acc[l][j]);
            }
        }
    }
#pragma unroll
    for (int l = 0; l < ADL_; l++)
#pragma unroll
        for (int j = 0; j < 4; j++) {
            float v = acc[l][j];
#pragma unroll
            for (int off = 16; off; off >>= 1)
                v += __shfl_xor_sync(0xffffffffu, v, off);
            if (lane == 0) out[l * DIM_ + e0 + j] = v;
        }
}

// ============================================================================
// Flash attention: QK fp16 3-pass (stored hi/lo), PV fp16 2-pass (V single),
// single-fp16 O. 64 q-rows/CTA, 128 threads, single-buffered KV, 2 CTA/SM.
// ============================================================================
#define FRSTR   272
#define FQ_TILE (64 * FRSTR)
#define FK_TILE (64 * FRSTR)
#define FSTAGE  (3 * FK_TILE)
#define FLASH_SMEM (2 * FQ_TILE + FSTAGE)    // 87040

__device__ __forceinline__ void fkv_fill(uint32_t sdst,
    const __half* __restrict__ Kh, const __half* __restrict__ Kl,
    const __half* __restrict__ V,
    int b, int h, int kv0)
{
    const int tid = threadIdx.x;
    const size_t gbase = ((size_t)(b * S_) + kv0) * DIM_ + h * D_;
#pragma unroll
    for (int i = 0; i < 24; i++) {
        int idx = tid + i * 128;
        int arr = idx >> 10;
        int rem = idx & 1023;
        int row = rem >> 4;
        int ch  = rem & 15;
        uint32_t dst = sdst + arr * FK_TILE + row * FRSTR + ch * 16;
        size_t src = gbase + (size_t)row * DIM_ + ch * 8;
        if (arr == 0)      CP_ASYNC16(dst, Kh + src);
        else if (arr == 1) CP_ASYNC16(dst, Kl + src);
        else               CP_ASYNC16(dst, V + src);
    }
}

__global__ __launch_bounds__(128, 2)
void flash_mma(const __half* __restrict__ Qh_g, const __half* __restrict__ Ql_g,
               const __half* __restrict__ Kh_g, const __half* __restrict__ Kl_g,
               const __half* __restrict__ V_g,
               const float* __restrict__ aK, const float* __restrict__ aV,
               const float* __restrict__ gate,
               __half* __restrict__ O)
{
    extern __shared__ char sm[];
    const uint32_t base = smem_u32(sm);
    const int tid  = threadIdx.x;
    const int wid  = tid >> 5;
    const int lane = tid & 31;
    const int qt = (int)gridDim.x - 1 - (int)blockIdx.x;
    const int h = blockIdx.y, b = blockIdx.z;
    const int nkt = qt + 1;

    const uint32_t sQh = base;
    const uint32_t sKV = base + 2 * FQ_TILE;

    {
        size_t gq = ((size_t)(b * S_) + qt * 64) * DIM_ + h * D_;
#pragma unroll
        for (int i = 0; i < 8; i++) {
            int idx = tid + i * 128;
            int row = idx >> 4, ch = idx & 15;
            uint32_t d = row * FRSTR + ch * 16;
            size_t src = gq + (size_t)row * DIM_ + ch * 8;
            CP_ASYNC16(sQh + d,           Qh_g + src);
            CP_ASYNC16(sQh + FQ_TILE + d, Ql_g + src);
        }
    }
    fkv_fill(sKV, Kh_g, Kl_g, V_g, b, h, 0);
    CP_COMMIT();

    const int q0  = qt * 64 + wid * 16;
    const int qg0 = q0 + (lane >> 2);
    const int qg1 = qg0 + 8;
    const float scl = 0.08838834764831845f;

    float m0 = -1e30f, m1 = -1e30f, l0 = 0.f, l1 = 0.f;
    float o[16][4];
#pragma unroll
    for (int d = 0; d < 16; d++)
#pragma unroll
        for (int q = 0; q < 4; q++) o[d][q] = 0.f;

    const uint32_t kh16 = (uint32_t)((lane >> 4) * 16);

    for (int kt = 0; kt < nkt; kt++) {
        CP_WAIT(0);
        __syncthreads();

        const uint32_t st = sKV;
        const int kv0 = kt * 64;

        float sa[8][4];
#pragma unroll
        for (int n8 = 0; n8 < 8; n8++)
#pragma unroll
            for (int q = 0; q < 4; q++) sa[n8][q] = 0.f;

        const uint32_t qrow = (uint32_t)(wid * 16 + (lane & 15));
        const uint32_t klrow = (uint32_t)(lane & 15);

#pragma unroll
        for (int ch = 0; ch < 8; ch++) {
            uint32_t qa = sQh + qrow * FRSTR + ch * 32 + kh16;
            uint32_t qh[4], ql[4];
            LDSM_X4(qh[0], qh[1], qh[2], qh[3], qa);
            LDSM_X4(ql[0], ql[1], ql[2], ql[3], qa + FQ_TILE);
            uint32_t kb[8][2], lb[8][2];
#pragma unroll
            for (int nb = 0; nb < 4; nb++) {
                uint32_t ka = st + (klrow + nb * 16) * FRSTR + ch * 32 + kh16;
                uint32_t r0, r1, r2, r3;
                LDSM_X4(r0, r1, r2, r3, ka);
                kb[2 * nb][0] = r0; kb[2 * nb][1] = r2;
                kb[2 * nb + 1][0] = r1; kb[2 * nb + 1][1] = r3;
                LDSM_X4(r0, r1, r2, r3, ka + FK_TILE);
                lb[2 * nb][0] = r0; lb[2 * nb][1] = r2;
                lb[2 * nb + 1][0] = r1; lb[2 * nb + 1][1] = r3;
            }
#pragma unroll
            for (int n8 = 0; n8 < 8; n8++) MMAH16816(sa[n8], qh, kb[n8]);
#pragma unroll
            for (int n8 = 0; n8 < 8; n8++) MMAH16816(sa[n8], qh, lb[n8]);
#pragma unroll
            for (int n8 = 0; n8 < 8; n8++) MMAH16816(sa[n8], ql, kb[n8]);
        }

        float rmax0 = -1e30f, rmax1 = -1e30f;
        const int kvb = kv0 + (lane & 3) * 2;
#pragma unroll
        for (int n8 = 0; n8 < 8; n8++) {
            int kvc = kvb + n8 * 8;
            float s0 = sa[n8][0] * scl, s1 = sa[n8][1] * scl;
            float s2 = sa[n8][2] * scl, s3 = sa[n8][3] * scl;
            if (kvc     > qg0) s0 = -1e30f;
            if (kvc + 1 > qg0) s1 = -1e30f;
            if (kvc     > qg1) s2 = -1e30f;
            if (kvc + 1 > qg1) s3 = -1e30f;
            sa[n8][0] = s0; sa[n8][1] = s1; sa[n8][2] = s2; sa[n8][3] = s3;
            rmax0 = fmaxf(rmax0, fmaxf(s0, s1));
            rmax1 = fmaxf(rmax1, fmaxf(s2, s3));
        }
        rmax0 = fmaxf(rmax0, __shfl_xor_sync(0xffffffffu, rmax0, 1));
        rmax0 = fmaxf(rmax0, __shfl_xor_sync(0xffffffffu, rmax0, 2));
        rmax1 = fmaxf(rmax1, __shfl_xor_sync(0xffffffffu, rmax1, 1));
        rmax1 = fmaxf(rmax1, __shfl_xor_sync(0xffffffffu, rmax1, 2));

        float mn0 = fmaxf(m0, rmax0), mn1 = fmaxf(m1, rmax1);
        float sc0 = __expf(m0 - mn0), sc1 = __expf(m1 - mn1);
        m0 = mn0; m1 = mn1;

        uint32_t ph[16], pl[16];
        float rs0 = 0.f, rs1 = 0.f;
#pragma unroll
        for (int n8 = 0; n8 < 8; n8++) {
            float p0 = __expf(sa[n8][0] - mn0);
            float p1 = __expf(sa[n8][1] - mn0);
            float p2 = __expf(sa[n8][2] - mn1);
            float p3 = __expf(sa[n8][3] - mn1);
            rs0 += p0 + p1; rs1 += p2 + p3;
            float h0 = __half2float(__float2half_rn(p0));
            float h1 = __half2float(__float2half_rn(p1));
            float h2 = __half2float(__float2half_rn(p2));
            float h3 = __half2float(__float2half_rn(p3));
            ph[2 * n8]     = pack_h2(h0, h1);
            ph[2 * n8 + 1] = pack_h2(h2, h3);
            pl[2 * n8]     = pack_h2(p0 - h0, p1 - h1);
            pl[2 * n8 + 1] = pack_h2(p2 - h2, p3 - h3);
        }
        rs0 += __shfl_xor_sync(0xffffffffu, rs0, 1);
        rs0 += __shfl_xor_sync(0xffffffffu, rs0, 2);
        rs1 += __shfl_xor_sync(0xffffffffu, rs1, 1);
        rs1 += __shfl_xor_sync(0xffffffffu, rs1, 2);
        l0 = l0 * sc0 + rs0;
        l1 = l1 * sc1 + rs1;

#pragma unroll
        for (int d = 0; d < 16; d++) {
            o[d][0] *= sc0; o[d][1] *= sc0;
            o[d][2] *= sc1; o[d][3] *= sc1;
        }

#pragma unroll
        for (int j = 0; j < 4; j++) {
            uint32_t ah[4] = {ph[4*j], ph[4*j+1], ph[4*j+2], ph[4*j+3]};
            uint32_t al[4] = {pl[4*j], pl[4*j+1], pl[4*j+2], pl[4*j+3]};
#pragma unroll
            for (int half = 0; half < 2; half++) {
                uint32_t vv[8][2];
#pragma unroll
                for (int k = 0; k < 4; k++) {
                    int nb = half * 4 + k;
                    uint32_t va = st + 2 * FK_TILE +
                                  (uint32_t)(j * 16 + (lane & 15)) * FRSTR +
                                  nb * 32 + kh16;
                    uint32_t r0, r1, r2, r3;
                    LDSM_X4_T(r0, r1, r2, r3, va);
                    vv[2 * k][0] = r0; vv[2 * k][1] = r1;
                    vv[2 * k + 1][0] = r2; vv[2 * k + 1][1] = r3;
                }
                const int ob = half * 8;
#pragma unroll
                for (int n = 0; n < 8; n++) MMAH16816(o[ob + n], ah, vv[n]);
#pragma unroll
                for (int n = 0; n < 8; n++) MMAH16816(o[ob + n], al, vv[n]);
            }
        }

        __syncthreads();
        if (kt + 1 < nkt) {
            fkv_fill(sKV, Kh_g, Kl_g, V_g, b, h, (kt + 1) * 64);
            CP_COMMIT();
        }
    }

    // ---- epilogue: adapter attention, single-fp16 output ----
    float* aKs = (float*)(sm + 2 * FQ_TILE);
    float* aVs = aKs + ADL_ * D_;
    for (int idx = tid; idx < ADL_ * D_; idx += 128) {
        int t = idx >> 7, cc = idx & (D_ - 1);
        aKs[idx] = aK[t * DIM_ + h * D_ + cc];
        aVs[idx] = aV[t * DIM_ + h * D_ + cc];
    }
    __syncthreads();

    const float g = tanhf(gate[h]);
    const float inv0 = 1.0f / l0, inv1 = 1.0f / l1;
    const int ccb = (lane & 3) * 2;

#pragma unroll
    for (int rr = 0; rr < 2; rr++) {
        const int lr = wid * 16 + (lane >> 2) + rr * 8;
        const float inv = rr ? inv1 : inv0;
        const size_t rowg = (size_t)(b * S_) + qt * 64 + lr;

        float qv[32];
#pragma unroll
        for (int d = 0; d < 16; d++) {
            int cc = d * 8 + ccb;
            __half2 hh = *(__half2*)(sm + lr * FRSTR + cc * 2);
            __half2 ll = *(__half2*)(sm + FQ_TILE + lr * FRSTR + cc * 2);
            qv[2 * d]     = __half2float(hh.x) + __half2float(ll.x);
            qv[2 * d + 1] = __half2float(hh.y) + __half2float(ll.y);
        }
        float sc[ADL_];
#pragma unroll
        for (int t = 0; t < ADL_; t++) {
            float p = 0.f;
#pragma unroll
            for (int d = 0; d < 16; d++) {
                int cc = d * 8 + ccb;
                p = fmaf(qv[2 * d],     aKs[t * D_ + cc],     p);
                p = fmaf(qv[2 * d + 1], aKs[t * D_ + cc + 1], p);
            }
            p += __shfl_xor_sync(0xffffffffu, p, 1);
            p += __shfl_xor_sync(0xffffffffu, p, 2);
            sc[t] = p * scl;
        }
        float mx = sc[0];
#pragma unroll
        for (int t = 1; t < ADL_; t++) mx = fmaxf(mx, sc[t]);
        float sum = 0.f;
#pragma unroll
        for (int t = 0; t < ADL_; t++) { sc[t] = __expf(sc[t] - mx); sum += sc[t]; }
        float isum = g / sum;
#pragma unroll
        for (int t = 0; t < ADL_; t++) sc[t] *= isum;

#pragma unroll
        for (int d = 0; d < 16; d++) {
            int cc = d * 8 + ccb;
            float a0 = 0.f, a1 = 0.f;
#pragma unroll
            for (int t = 0; t < ADL_; t++) {
                a0 = fmaf(sc[t], aVs[t * D_ + cc],     a0);
                a1 = fmaf(sc[t], aVs[t * D_ + cc + 1], a1);
            }
            float o0 = o[d][rr * 2]     * inv + a0;
            float o1 = o[d][rr * 2 + 1] * inv + a1;
            *(__half2*)(O + rowg * DIM_ + h * D_ + cc) =
                __floats2half2_rn(o0, o1);
        }
    }
}

// ============================================================================
// launch
// ============================================================================
extern "C" void kernel_launch(void* const* d_in, const int* in_sizes, int n_in,
                              void* d_out, int out_size)
{
    const float* x       = (const float*)d_in[0];
    const float* wq      = (const float*)d_in[1];
    const float* wk      = (const float*)d_in[2];
    const float* wv      = (const float*)d_in[3];
    const float* wo      = (const float*)d_in[4];
    const float* gate    = (const float*)d_in[5];
    const float* adapter = (const float*)d_in[6];
    const float* fcos    = (const float*)d_in[7];
    const float* fsin    = (const float*)d_in[8];
    float* out = (float*)d_out;

    float *aKp, *aVp;
    cudaGetSymbolAddress((void**)&aKp, g_aK);
    cudaGetSymbolAddress((void**)&aVp, g_aV);

    __half *x16, *wq16, *wk16, *wv16, *wo16;
    __half *q16h, *q16l, *k16h, *k16l, *v16, *o16;
    cudaGetSymbolAddress((void**)&x16,  g_x16);
    cudaGetSymbolAddress((void**)&wq16, g_wq16); cudaGetSymbolAddress((void**)&wk16, g_wk16);
    cudaGetSymbolAddress((void**)&wv16, g_wv16); cudaGetSymbolAddress((void**)&wo16, g_wo16);
    cudaGetSymbolAddress((void**)&q16h, g_q16h); cudaGetSymbolAddress((void**)&q16l, g_q16l);
    cudaGetSymbolAddress((void**)&k16h, g_k16h); cudaGetSymbolAddress((void**)&k16l, g_k16l);
    cudaGetSymbolAddress((void**)&v16,  g_v16);
    cudaGetSymbolAddress((void**)&o16,  g_o16);

    cudaFuncSetAttribute(qkv_gemm,
                         cudaFuncAttributeMaxDynamicSharedMemorySize, GS_SMEM);
    cudaFuncSetAttribute(o_gemm,
                         cudaFuncAttributeMaxDynamicSharedMemorySize, GS_SMEM);
    cudaFuncSetAttribute(flash_mma,
                         cudaFuncAttributeMaxDynamicSharedMemorySize, FLASH_SMEM);

    split_all<<<dim3(NELEM / 4 / 256, 5), 256>>>(x, wq, wk, wv, wo,
        x16, wq16, wk16, wv16, wo16);

    adapter_gemv<<<128, 256>>>(adapter, wk, aKp);
    adapter_gemv<<<128, 256>>>(adapter, wv, aVp);

    qkv_gemm<<<dim3(DIM_ / 128, MROWS / 128, 3), 256, GS_SMEM>>>(
        x16, wq16, wk16, wv16,
        q16h, q16l, k16h, k16l, v16, fcos, fsin);

    flash_mma<<<dim3(S_ / 64, H_, B_), 128, FLASH_SMEM>>>(
        q16h, q16l, k16h, k16l, v16, aKp, aVp, gate, o16);

    o_gemm<<<dim3(DIM_ / 128, MROWS / 128), 256, GS_SMEM>>>(
        o16, wo16, out);
}

// round 16
// speedup vs baseline: 2.5712x; 1.0535x over previous
#include <cuda_runtime.h>
#include <cuda_bf16.h>
#include <cuda_fp16.h>
#include <math.h>
#include <stdint.h>

// ---------------------------------------------------------------- constants
#define B_    2
#define S_    2048
#define H_    32
#define D_    128
#define DIM_  4096
#define ADL_  10
#define MROWS (B_ * S_)
#define NELEM ((size_t)MROWS * DIM_)

// ---------------------------------------------------------------- scratch
__device__ float g_aK[ADL_ * DIM_];
__device__ float g_aV[ADL_ * DIM_];

__device__ __half g_x16[NELEM];
__device__ __half g_wq16[NELEM], g_wk16[NELEM];
__device__ __half g_wv16[NELEM], g_wo16[NELEM];
__device__ __half g_q16h[NELEM], g_q16l[NELEM];
__device__ __half g_k16[NELEM];
__device__ __half g_v16[NELEM];
__device__ __half g_o16[NELEM];

// ---------------------------------------------------------------- PTX utils
__device__ __forceinline__ uint32_t smem_u32(const void* p) {
    uint32_t a;
    asm("{ .reg .u64 t; cvta.to.shared.u64 t, %1; cvt.u32.u64 %0, t; }"
        : "=r"(a) : "l"(p));
    return a;
}
#define CP_ASYNC16(dst, src) \
    asm volatile("cp.async.cg.shared.global [%0], [%1], 16;" \
                 :: "r"(dst), "l"(src) : "memory")
#define CP_COMMIT() asm volatile("cp.async.commit_group;" ::: "memory")
#define CP_WAIT(n)  asm volatile("cp.async.wait_group %0;" :: "n"(n) : "memory")

#define LDSM_X4(r0, r1, r2, r3, addr) \
    asm volatile("ldmatrix.sync.aligned.m8n8.x4.shared.b16 {%0,%1,%2,%3}, [%4];" \
                 : "=r"(r0), "=r"(r1), "=r"(r2), "=r"(r3) : "r"(addr))
#define LDSM_X4_T(r0, r1, r2, r3, addr) \
    asm volatile("ldmatrix.sync.aligned.m8n8.x4.trans.shared.b16 {%0,%1,%2,%3}, [%4];" \
                 : "=r"(r0), "=r"(r1), "=r"(r2), "=r"(r3) : "r"(addr))

#define MMAH16816(c, a, b) \
    asm volatile("mma.sync.aligned.m16n8k16.row.col.f32.f16.f16.f32 " \
                 "{%0,%1,%2,%3}, {%4,%5,%6,%7}, {%8,%9}, {%0,%1,%2,%3};" \
                 : "+f"((c)[0]), "+f"((c)[1]), "+f"((c)[2]), "+f"((c)[3]) \
                 : "r"((a)[0]), "r"((a)[1]), "r"((a)[2]), "r"((a)[3]), \
                   "r"((b)[0]), "r"((b)[1]))

__device__ __forceinline__ uint32_t pack_h2(float lo, float hi) {
    __half2 t = __floats2half2_rn(lo, hi);
    return *(uint32_t*)&t;
}
__device__ __forceinline__ void split_store_h(__half* Xh, __half* Xl,
                                              size_t off, float v0, float v1) {
    __half h0 = __float2half_rn(v0);
    __half h1 = __float2half_rn(v1);
    *(__half2*)(Xh + off) = __half2(h0, h1);
    *(__half2*)(Xl + off) = __half2(
        __float2half_rn(v0 - __half2float(h0)),
        __float2half_rn(v1 - __half2float(h1)));
}

// ============================================================================
// 1-pass fp16 GEMM core (A single, B single): 128x128 tile, BK=32,
// 2-tile stage, 2-stage pipeline, 2 CTA/SM.
// ============================================================================
#define GK_BK      32
#define GK_TILE_B  10240
#define GK_NIT     (DIM_ / GK_BK)
#define GS_STAGE_B (2 * GK_TILE_B)
#define GS_SMEM    (2 * GS_STAGE_B)     // 40960

__device__ __forceinline__ void gs_fill(uint32_t sbase,
    const __half* __restrict__ A, const __half* __restrict__ Bs,
    int rowBase, int colBase, int k0)
{
    const int tid = threadIdx.x;
#pragma unroll
    for (int i = 0; i < 4; i++) {
        int idx = tid + i * 256;
        int arr = idx >> 9;
        int rem = idx & 511;
        int row = rem >> 2;
        int ch  = rem & 3;
        uint32_t dst = sbase + (uint32_t)(arr * GK_TILE_B + row * 80 + ch * 16);
        const __half* src = (arr == 0) ? A : Bs;
        int grow = (arr == 0) ? (rowBase + row) : (colBase + row);
        CP_ASYNC16(dst, src + (size_t)grow * DIM_ + k0 + ch * 8);
    }
}

#define GS_MAINLOOP(A, Bs)                                                     \
    gs_fill(base, A, Bs, rowBase, colBase, 0);                                 \
    CP_COMMIT();                                                               \
    const uint32_t aRow = (uint32_t)(wm + (lane & 15));                        \
    const uint32_t bRow = (uint32_t)(wn + (lane & 15));                        \
    const uint32_t kHalf = (uint32_t)((lane >> 4) * 16);                       \
    for (int it = 0; it < GK_NIT; it++) {                                      \
        CP_WAIT(0);                                                            \
        __syncthreads();                                                       \
        if (it + 1 < GK_NIT)                                                   \
            gs_fill(base + (uint32_t)((it + 1) & 1) * GS_STAGE_B,              \
                    A, Bs, rowBase, colBase, (it + 1) * GK_BK);                \
        CP_COMMIT();                                                           \
        const uint32_t sb = base + (uint32_t)(it & 1) * GS_STAGE_B;            \
        _Pragma("unroll")                                                      \
        for (int ks = 0; ks < 2; ks++) {                                       \
            const uint32_t kcol = (uint32_t)(ks * 32) + kHalf;                 \
            uint32_t ah[4][4], bb[4][2];                                       \
            _Pragma("unroll")                                                  \
            for (int mi = 0; mi < 4; mi++) {                                   \
                uint32_t off = (aRow + mi * 16) * 80 + kcol;                   \
                LDSM_X4(ah[mi][0], ah[mi][1], ah[mi][2], ah[mi][3], sb + off); \
            }                                                                  \
            _Pragma("unroll")                                                  \
            for (int np = 0; np < 2; np++) {                                   \
                uint32_t off = GK_TILE_B + (bRow + np * 16) * 80 + kcol;       \
                uint32_t r0, r1, r2, r3;                                       \
                LDSM_X4(r0, r1, r2, r3, sb + off);                             \
                bb[2 * np][0] = r0; bb[2 * np][1] = r2;                        \
                bb[2 * np + 1][0] = r1; bb[2 * np + 1][1] = r3;                \
            }                                                                  \
            _Pragma("unroll")                                                  \
            for (int mi = 0; mi < 4; mi++)                                     \
                _Pragma("unroll")                                              \
                for (int ni = 0; ni < 4; ni++)                                 \
                    MMAH16816(acc[mi][ni], ah[mi], bb[ni]);                    \
        }                                                                      \
    }

// --------- QKV GEMM (1-pass): z=0 Q (rope, hi/lo out), z=1 K (rope, single),
// ---------                    z=2 V (single)
__global__ __launch_bounds__(256, 2)
void qkv_gemm(const __half* __restrict__ X,
              const __half* __restrict__ Bq, const __half* __restrict__ Bk,
              const __half* __restrict__ Bv,
              __half* __restrict__ Qh, __half* __restrict__ Ql,
              __half* __restrict__ K, __half* __restrict__ V,
              const float* __restrict__ fcos, const float* __restrict__ fsin)
{
    extern __shared__ char sm[];
    const uint32_t base = smem_u32(sm);
    const int lane = threadIdx.x & 31;
    const int wid  = threadIdx.x >> 5;
    const int rowBase = blockIdx.y * 128;
    const int colBase = blockIdx.x * 128;
    const int wm = (wid & 1) * 64;
    const int wn = (wid >> 1) * 32;
    const int z = blockIdx.z;

    const __half* Bs = (z == 0) ? Bq : (z == 1) ? Bk : Bv;

    float acc[4][4][4];
#pragma unroll
    for (int mi = 0; mi < 4; mi++)
#pragma unroll
        for (int ni = 0; ni < 4; ni++)
#pragma unroll
            for (int q = 0; q < 4; q++) acc[mi][ni][q] = 0.f;

    GS_MAINLOOP(X, Bs)

    const int r0 = rowBase + wm + (lane >> 2);
    const int c0 = colBase + wn + (lane & 3) * 2;

    if (z == 2) {
#pragma unroll
        for (int mi = 0; mi < 4; mi++)
#pragma unroll
            for (int ni = 0; ni < 4; ni++) {
                size_t off = (size_t)(r0 + mi * 16) * DIM_ + c0 + ni * 8;
                *(__half2*)(V + off) =
                    __floats2half2_rn(acc[mi][ni][0], acc[mi][ni][1]);
                *(__half2*)(V + off + 8 * DIM_) =
                    __floats2half2_rn(acc[mi][ni][2], acc[mi][ni][3]);
            }
        return;
    }

#pragma unroll
    for (int mi = 0; mi < 4; mi++) {
        int r  = r0 + mi * 16;
        int s1 = r & (S_ - 1);
        int s2 = (r + 8) & (S_ - 1);
#pragma unroll
        for (int ni = 0; ni < 4; ni++) {
            int c = c0 + ni * 8;
            float v0 = acc[mi][ni][0], v1 = acc[mi][ni][1];
            float v2 = acc[mi][ni][2], v3 = acc[mi][ni][3];
            int i = (c & (D_ - 1)) >> 1;
            float c1 = fcos[s1 * 64 + i], n1 = fsin[s1 * 64 + i];
            float c2 = fcos[s2 * 64 + i], n2 = fsin[s2 * 64 + i];
            float t;
            t = v0 * c1 - v1 * n1; v1 = v0 * n1 + v1 * c1; v0 = t;
            t = v2 * c2 - v3 * n2; v3 = v2 * n2 + v3 * c2; v2 = t;
            if (z == 0) {
                split_store_h(Qh, Ql, (size_t)r * DIM_ + c, v0, v1);
                split_store_h(Qh, Ql, (size_t)(r + 8) * DIM_ + c, v2, v3);
            } else {
                *(__half2*)(K + (size_t)r * DIM_ + c) = __floats2half2_rn(v0, v1);
                *(__half2*)(K + (size_t)(r + 8) * DIM_ + c) = __floats2half2_rn(v2, v3);
            }
        }
    }
}

// --------- out GEMM (1-pass): fp32 C ---------
__global__ __launch_bounds__(256, 2)
void o_gemm(const __half* __restrict__ A, const __half* __restrict__ Bs,
            float* __restrict__ C)
{
    extern __shared__ char sm[];
    const uint32_t base = smem_u32(sm);
    const int lane = threadIdx.x & 31;
    const int wid  = threadIdx.x >> 5;
    const int rowBase = blockIdx.y * 128;
    const int colBase = blockIdx.x * 128;
    const int wm = (wid & 1) * 64;
    const int wn = (wid >> 1) * 32;

    float acc[4][4][4];
#pragma unroll
    for (int mi = 0; mi < 4; mi++)
#pragma unroll
        for (int ni = 0; ni < 4; ni++)
#pragma unroll
            for (int q = 0; q < 4; q++) acc[mi][ni][q] = 0.f;

    GS_MAINLOOP(A, Bs)

    const int r0 = rowBase + wm + (lane >> 2);
    const int c0 = colBase + wn + (lane & 3) * 2;
#pragma unroll
    for (int mi = 0; mi < 4; mi++)
#pragma unroll
        for (int ni = 0; ni < 4; ni++) {
            float* p = C + (size_t)(r0 + mi * 16) * DIM_ + c0 + ni * 8;
            *(float2*)p = make_float2(acc[mi][ni][0], acc[mi][ni][1]);
            *(float2*)(p + 8 * DIM_) = make_float2(acc[mi][ni][2], acc[mi][ni][3]);
        }
}

// ============================================================================
// split_all: y=0..4 -> single fp16 (x, wq, wk, wv, wo)
// ============================================================================
__global__ void split_all(const float* __restrict__ x,  const float* __restrict__ wq,
                          const float* __restrict__ wk, const float* __restrict__ wv,
                          const float* __restrict__ wo,
                          __half* x16, __half* wq16, __half* wk16,
                          __half* wv16, __half* wo16)
{
    size_t i = (size_t)blockIdx.x * blockDim.x + threadIdx.x;
    const int y = blockIdx.y;
    const float* src = (y == 0) ? x : (y == 1) ? wq : (y == 2) ? wk
                     : (y == 3) ? wv : wo;
    __half* dst = (y == 0) ? x16 : (y == 1) ? wq16 : (y == 2) ? wk16
                : (y == 3) ? wv16 : wo16;
    float4 v = ((const float4*)src)[i];
    ((__half2*)dst)[2 * i]     = __floats2half2_rn(v.x, v.y);
    ((__half2*)dst)[2 * i + 1] = __floats2half2_rn(v.z, v.w);
}

// ============================================================================
// adapter GEMV (fp32)
// ============================================================================
__global__ __launch_bounds__(256)
void adapter_gemv(const float* __restrict__ A, const float* __restrict__ W,
                  float* __restrict__ out)
{
    int warp = (blockIdx.x * blockDim.x + threadIdx.x) >> 5;
    int lane = threadIdx.x & 31;
    int e0 = warp * 4;

    float acc[ADL_][4];
#pragma unroll
    for (int l = 0; l < ADL_; l++)
#pragma unroll
        for (int j = 0; j < 4; j++) acc[l][j] = 0.f;

    for (int d = lane * 4; d < DIM_; d += 128) {
        float4 w4[4];
#pragma unroll
        for (int j = 0; j < 4; j++)
            w4[j] = *(const float4*)(W + (size_t)(e0 + j) * DIM_ + d);
#pragma unroll
        for (int l = 0; l < ADL_; l++) {
            float4 a4 = *(const float4*)(A + (size_t)l * DIM_ + d);
#pragma unroll
            for (int j = 0; j < 4; j++) {
                acc[l][j] = fmaf(a4.x, w4[j].x, acc[l][j]);
                acc[l][j] = fmaf(a4.y, w4[j].y, acc[l][j]);
                acc[l][j] = fmaf(a4.z, w4[j].z, acc[l][j]);
                acc[l][j] = fmaf(a4.w, w4[j].w, acc[l][j]);
            }
        }
    }
#pragma unroll
    for (int l = 0; l < ADL_; l++)
#pragma unroll
        for (int j = 0; j < 4; j++) {
            float v = acc[l][j];
#pragma unroll
            for (int off = 16; off; off >>= 1)
                v += __shfl_xor_sync(0xffffffffu, v, off);
            if (lane == 0) out[l * DIM_ + e0 + j] = v;
        }
}

// ============================================================================
// Flash attention: QK fp16 2-pass (Q hi/lo, K single), PV fp16 2-pass
// (V single), single-fp16 O. 64 q-rows/CTA, 128 threads,
// DOUBLE-buffered KV (K+V = 2 tiles/stage), 2 CTA/SM.
// ============================================================================
#define FRSTR   272
#define FQ_TILE (64 * FRSTR)             // 17408
#define FK_TILE (64 * FRSTR)
#define FSTAGE  (2 * FK_TILE)            // 34816  (K, V)
#define FLASH_SMEM (2 * FQ_TILE + 2 * FSTAGE)   // 104448

__device__ __forceinline__ void fkv_fill(uint32_t sdst,
    const __half* __restrict__ K, const __half* __restrict__ V,
    int b, int h, int kv0)
{
    const int tid = threadIdx.x;
    const size_t gbase = ((size_t)(b * S_) + kv0) * DIM_ + h * D_;
#pragma unroll
    for (int i = 0; i < 16; i++) {
        int idx = tid + i * 128;              // 0..2047
        int arr = idx >> 10;                  // 0 K, 1 V
        int rem = idx & 1023;
        int row = rem >> 4;
        int ch  = rem & 15;
        uint32_t dst = sdst + arr * FK_TILE + row * FRSTR + ch * 16;
        size_t src = gbase + (size_t)row * DIM_ + ch * 8;
        if (arr == 0) CP_ASYNC16(dst, K + src);
        else          CP_ASYNC16(dst, V + src);
    }
}

__global__ __launch_bounds__(128, 2)
void flash_mma(const __half* __restrict__ Qh_g, const __half* __restrict__ Ql_g,
               const __half* __restrict__ K_g, const __half* __restrict__ V_g,
               const float* __restrict__ aK, const float* __restrict__ aV,
               const float* __restrict__ gate,
               __half* __restrict__ O)
{
    extern __shared__ char sm[];
    const uint32_t base = smem_u32(sm);
    const int tid  = threadIdx.x;
    const int wid  = tid >> 5;
    const int lane = tid & 31;
    const int qt = (int)gridDim.x - 1 - (int)blockIdx.x;
    const int h = blockIdx.y, b = blockIdx.z;
    const int nkt = qt + 1;

    const uint32_t sQh = base;
    const uint32_t sKV = base + 2 * FQ_TILE;

    {
        size_t gq = ((size_t)(b * S_) + qt * 64) * DIM_ + h * D_;
#pragma unroll
        for (int i = 0; i < 8; i++) {
            int idx = tid + i * 128;
            int row = idx >> 4, ch = idx & 15;
            uint32_t d = row * FRSTR + ch * 16;
            size_t src = gq + (size_t)row * DIM_ + ch * 8;
            CP_ASYNC16(sQh + d,           Qh_g + src);
            CP_ASYNC16(sQh + FQ_TILE + d, Ql_g + src);
        }
    }
    fkv_fill(sKV, K_g, V_g, b, h, 0);
    CP_COMMIT();

    const int q0  = qt * 64 + wid * 16;
    const int qg0 = q0 + (lane >> 2);
    const int qg1 = qg0 + 8;
    const float scl = 0.08838834764831845f;

    float m0 = -1e30f, m1 = -1e30f, l0 = 0.f, l1 = 0.f;
    float o[16][4];
#pragma unroll
    for (int d = 0; d < 16; d++)
#pragma unroll
        for (int q = 0; q < 4; q++) o[d][q] = 0.f;

    const uint32_t kh16 = (uint32_t)((lane >> 4) * 16);

    for (int kt = 0; kt < nkt; kt++) {
        if (kt + 1 < nkt) {
            fkv_fill(sKV + (uint32_t)((kt + 1) & 1) * FSTAGE,
                     K_g, V_g, b, h, (kt + 1) * 64);
        }
        CP_COMMIT();
        CP_WAIT(1);
        __syncthreads();

        const uint32_t st = sKV + (uint32_t)(kt & 1) * FSTAGE;
        const int kv0 = kt * 64;

        // ---- S = Q K^T (fp16 2-pass: Qh·K + Ql·K) ----
        float sa[8][4];
#pragma unroll
        for (int n8 = 0; n8 < 8; n8++)
#pragma unroll
            for (int q = 0; q < 4; q++) sa[n8][q] = 0.f;

        const uint32_t qrow = (uint32_t)(wid * 16 + (lane & 15));
        const uint32_t klrow = (uint32_t)(lane & 15);

#pragma unroll
        for (int ch = 0; ch < 8; ch++) {
            uint32_t qa = sQh + qrow * FRSTR + ch * 32 + kh16;
            uint32_t qh[4], ql[4];
            LDSM_X4(qh[0], qh[1], qh[2], qh[3], qa);
            LDSM_X4(ql[0], ql[1], ql[2], ql[3], qa + FQ_TILE);
            uint32_t kb[8][2];
#pragma unroll
            for (int nb = 0; nb < 4; nb++) {
                uint32_t ka = st + (klrow + nb * 16) * FRSTR + ch * 32 + kh16;
                uint32_t r0, r1, r2, r3;
                LDSM_X4(r0, r1, r2, r3, ka);
                kb[2 * nb][0] = r0; kb[2 * nb][1] = r2;
                kb[2 * nb + 1][0] = r1; kb[2 * nb + 1][1] = r3;
            }
#pragma unroll
            for (int n8 = 0; n8 < 8; n8++) MMAH16816(sa[n8], qh, kb[n8]);
#pragma unroll
            for (int n8 = 0; n8 < 8; n8++) MMAH16816(sa[n8], ql, kb[n8]);
        }

        // ---- mask + online softmax ----
        float rmax0 = -1e30f, rmax1 = -1e30f;
        const int kvb = kv0 + (lane & 3) * 2;
#pragma unroll
        for (int n8 = 0; n8 < 8; n8++) {
            int kvc = kvb + n8 * 8;
            float s0 = sa[n8][0] * scl, s1 = sa[n8][1] * scl;
            float s2 = sa[n8][2] * scl, s3 = sa[n8][3] * scl;
            if (kvc     > qg0) s0 = -1e30f;
            if (kvc + 1 > qg0) s1 = -1e30f;
            if (kvc     > qg1) s2 = -1e30f;
            if (kvc + 1 > qg1) s3 = -1e30f;
            sa[n8][0] = s0; sa[n8][1] = s1; sa[n8][2] = s2; sa[n8][3] = s3;
            rmax0 = fmaxf(rmax0, fmaxf(s0, s1));
            rmax1 = fmaxf(rmax1, fmaxf(s2, s3));
        }
        rmax0 = fmaxf(rmax0, __shfl_xor_sync(0xffffffffu, rmax0, 1));
        rmax0 = fmaxf(rmax0, __shfl_xor_sync(0xffffffffu, rmax0, 2));
        rmax1 = fmaxf(rmax1, __shfl_xor_sync(0xffffffffu, rmax1, 1));
        rmax1 = fmaxf(rmax1, __shfl_xor_sync(0xffffffffu, rmax1, 2));

        float mn0 = fmaxf(m0, rmax0), mn1 = fmaxf(m1, rmax1);
        float sc0 = __expf(m0 - mn0), sc1 = __expf(m1 - mn1);
        m0 = mn0; m1 = mn1;

        uint32_t ph[16], pl[16];
        float rs0 = 0.f, rs1 = 0.f;
#pragma unroll
        for (int n8 = 0; n8 < 8; n8++) {
            float p0 = __expf(sa[n8][0] - mn0);
            float p1 = __expf(sa[n8][1] - mn0);
            float p2 = __expf(sa[n8][2] - mn1);
            float p3 = __expf(sa[n8][3] - mn1);
            rs0 += p0 + p1; rs1 += p2 + p3;
            float h0 = __half2float(__float2half_rn(p0));
            float h1 = __half2float(__float2half_rn(p1));
            float h2 = __half2float(__float2half_rn(p2));
            float h3 = __half2float(__float2half_rn(p3));
            ph[2 * n8]     = pack_h2(h0, h1);
            ph[2 * n8 + 1] = pack_h2(h2, h3);
            pl[2 * n8]     = pack_h2(p0 - h0, p1 - h1);
            pl[2 * n8 + 1] = pack_h2(p2 - h2, p3 - h3);
        }
        rs0 += __shfl_xor_sync(0xffffffffu, rs0, 1);
        rs0 += __shfl_xor_sync(0xffffffffu, rs0, 2);
        rs1 += __shfl_xor_sync(0xffffffffu, rs1, 1);
        rs1 += __shfl_xor_sync(0xffffffffu, rs1, 2);
        l0 = l0 * sc0 + rs0;
        l1 = l1 * sc1 + rs1;

#pragma unroll
        for (int d = 0; d < 16; d++) {
            o[d][0] *= sc0; o[d][1] *= sc0;
            o[d][2] *= sc1; o[d][3] *= sc1;
        }

        // ---- O += P V (fp16 2-pass, V single) ----
#pragma unroll
        for (int j = 0; j < 4; j++) {
            uint32_t ah[4] = {ph[4*j], ph[4*j+1], ph[4*j+2], ph[4*j+3]};
            uint32_t al[4] = {pl[4*j], pl[4*j+1], pl[4*j+2], pl[4*j+3]};
#pragma unroll
            for (int half = 0; half < 2; half++) {
                uint32_t vv[8][2];
#pragma unroll
                for (int k = 0; k < 4; k++) {
                    int nb = half * 4 + k;
                    uint32_t va = st + FK_TILE +
                                  (uint32_t)(j * 16 + (lane & 15)) * FRSTR +
                                  nb * 32 + kh16;
                    uint32_t r0, r1, r2, r3;
                    LDSM_X4_T(r0, r1, r2, r3, va);
                    vv[2 * k][0] = r0; vv[2 * k][1] = r1;
                    vv[2 * k + 1][0] = r2; vv[2 * k + 1][1] = r3;
                }
                const int ob = half * 8;
#pragma unroll
                for (int n = 0; n < 8; n++) MMAH16816(o[ob + n], ah, vv[n]);
#pragma unroll
                for (int n = 0; n < 8; n++) MMAH16816(o[ob + n], al, vv[n]);
            }
        }
        __syncthreads();
    }

    // ---- epilogue: adapter attention, single-fp16 output ----
    float* aKs = (float*)(sm + 2 * FQ_TILE);
    float* aVs = aKs + ADL_ * D_;
    for (int idx = tid; idx < ADL_ * D_; idx += 128) {
        int t = idx >> 7, cc = idx & (D_ - 1);
        aKs[idx] = aK[t * DIM_ + h * D_ + cc];
        aVs[idx] = aV[t * DIM_ + h * D_ + cc];
    }
    __syncthreads();

    const float g = tanhf(gate[h]);
    const float inv0 = 1.0f / l0, inv1 = 1.0f / l1;
    const int ccb = (lane & 3) * 2;

#pragma unroll
    for (int rr = 0; rr < 2; rr++) {
        const int lr = wid * 16 + (lane >> 2) + rr * 8;
        const float inv = rr ? inv1 : inv0;
        const size_t rowg = (size_t)(b * S_) + qt * 64 + lr;

        float qv[32];
#pragma unroll
        for (int d = 0; d < 16; d++) {
            int cc = d * 8 + ccb;
            __half2 hh = *(__half2*)(sm + lr * FRSTR + cc * 2);
            __half2 ll = *(__half2*)(sm + FQ_TILE + lr * FRSTR + cc * 2);
            qv[2 * d]     = __half2float(hh.x) + __half2float(ll.x);
            qv[2 * d + 1] = __half2float(hh.y) + __half2float(ll.y);
        }
        float sc[ADL_];
#pragma unroll
        for (int t = 0; t < ADL_; t++) {
            float p = 0.f;
#pragma unroll
            for (int d = 0; d < 16; d++) {
                int cc = d * 8 + ccb;
                p = fmaf(qv[2 * d],     aKs[t * D_ + cc],     p);
                p = fmaf(qv[2 * d + 1], aKs[t * D_ + cc + 1], p);
            }
            p += __shfl_xor_sync(0xffffffffu, p, 1);
            p += __shfl_xor_sync(0xffffffffu, p, 2);
            sc[t] = p * scl;
        }
        float mx = sc[0];
#pragma unroll
        for (int t = 1; t < ADL_; t++) mx = fmaxf(mx, sc[t]);
        float sum = 0.f;
#pragma unroll
        for (int t = 0; t < ADL_; t++) { sc[t] = __expf(sc[t] - mx); sum += sc[t]; }
        float isum = g / sum;
#pragma unroll
        for (int t = 0; t < ADL_; t++) sc[t] *= isum;

#pragma unroll
        for (int d = 0; d < 16; d++) {
            int cc = d * 8 + ccb;
            float a0 = 0.f, a1 = 0.f;
#pragma unroll
            for (int t = 0; t < ADL_; t++) {
                a0 = fmaf(sc[t], aVs[t * D_ + cc],     a0);
                a1 = fmaf(sc[t], aVs[t * D_ + cc + 1], a1);
            }
            float o0 = o[d][rr * 2]     * inv + a0;
            float o1 = o[d][rr * 2 + 1] * inv + a1;
            *(__half2*)(O + rowg * DIM_ + h * D_ + cc) =
                __floats2half2_rn(o0, o1);
        }
    }
}

// ============================================================================
// launch
// ============================================================================
extern "C" void kernel_launch(void* const* d_in, const int* in_sizes, int n_in,
                              void* d_out, int out_size)
{
    const float* x       = (const float*)d_in[0];
    const float* wq      = (const float*)d_in[1];
    const float* wk      = (const float*)d_in[2];
    const float* wv      = (const float*)d_in[3];
    const float* wo      = (const float*)d_in[4];
    const float* gate    = (const float*)d_in[5];
    const float* adapter = (const float*)d_in[6];
    const float* fcos    = (const float*)d_in[7];
    const float* fsin    = (const float*)d_in[8];
    float* out = (float*)d_out;

    float *aKp, *aVp;
    cudaGetSymbolAddress((void**)&aKp, g_aK);
    cudaGetSymbolAddress((void**)&aVp, g_aV);

    __half *x16, *wq16, *wk16, *wv16, *wo16;
    __half *q16h, *q16l, *k16, *v16, *o16;
    cudaGetSymbolAddress((void**)&x16,  g_x16);
    cudaGetSymbolAddress((void**)&wq16, g_wq16); cudaGetSymbolAddress((void**)&wk16, g_wk16);
    cudaGetSymbolAddress((void**)&wv16, g_wv16); cudaGetSymbolAddress((void**)&wo16, g_wo16);
    cudaGetSymbolAddress((void**)&q16h, g_q16h); cudaGetSymbolAddress((void**)&q16l, g_q16l);
    cudaGetSymbolAddress((void**)&k16,  g_k16);
    cudaGetSymbolAddress((void**)&v16,  g_v16);
    cudaGetSymbolAddress((void**)&o16,  g_o16);

    cudaFuncSetAttribute(qkv_gemm,
                         cudaFuncAttributeMaxDynamicSharedMemorySize, GS_SMEM);
    cudaFuncSetAttribute(o_gemm,
                         cudaFuncAttributeMaxDynamicSharedMemorySize, GS_SMEM);
    cudaFuncSetAttribute(flash_mma,
                         cudaFuncAttributeMaxDynamicSharedMemorySize, FLASH_SMEM);

    split_all<<<dim3(NELEM / 4 / 256, 5), 256>>>(x, wq, wk, wv, wo,
        x16, wq16, wk16, wv16, wo16);

    adapter_gemv<<<128, 256>>>(adapter, wk, aKp);
    adapter_gemv<<<128, 256>>>(adapter, wv, aVp);

    qkv_gemm<<<dim3(DIM_ / 128, MROWS / 128, 3), 256, GS_SMEM>>>(
        x16, wq16, wk16, wv16,
        q16h, q16l, k16, v16, fcos, fsin);

    flash_mma<<<dim3(S_ / 64, H_, B_), 128, FLASH_SMEM>>>(
        q16h, q16l, k16, v16, aKp, aVp, gate, o16);

    o_gemm<<<dim3(DIM_ / 128, MROWS / 128), 256, GS_SMEM>>>(
        o16, wo16, out);
}

// round 17
// speedup vs baseline: 2.7381x; 1.0649x over previous
#include <cuda_runtime.h>
#include <cuda_bf16.h>
#include <cuda_fp16.h>
#include <math.h>
#include <stdint.h>

// ---------------------------------------------------------------- constants
#define B_    2
#define S_    2048
#define H_    32
#define D_    128
#define DIM_  4096
#define ADL_  10
#define MROWS (B_ * S_)
#define NELEM ((size_t)MROWS * DIM_)

// ---------------------------------------------------------------- scratch
__device__ float g_aK[ADL_ * DIM_];
__device__ float g_aV[ADL_ * DIM_];

__device__ __half g_x16[NELEM];
__device__ __half g_wq16[NELEM], g_wk16[NELEM];
__device__ __half g_wv16[NELEM], g_wo16[NELEM];
__device__ __half g_q16[NELEM], g_k16[NELEM];
__device__ __half g_v16[NELEM];
__device__ __half g_o16[NELEM];

// ---------------------------------------------------------------- PTX utils
__device__ __forceinline__ uint32_t smem_u32(const void* p) {
    uint32_t a;
    asm("{ .reg .u64 t; cvta.to.shared.u64 t, %1; cvt.u32.u64 %0, t; }"
        : "=r"(a) : "l"(p));
    return a;
}
#define CP_ASYNC16(dst, src) \
    asm volatile("cp.async.cg.shared.global [%0], [%1], 16;" \
                 :: "r"(dst), "l"(src) : "memory")
#define CP_COMMIT() asm volatile("cp.async.commit_group;" ::: "memory")
#define CP_WAIT(n)  asm volatile("cp.async.wait_group %0;" :: "n"(n) : "memory")

#define LDSM_X4(r0, r1, r2, r3, addr) \
    asm volatile("ldmatrix.sync.aligned.m8n8.x4.shared.b16 {%0,%1,%2,%3}, [%4];" \
                 : "=r"(r0), "=r"(r1), "=r"(r2), "=r"(r3) : "r"(addr))
#define LDSM_X4_T(r0, r1, r2, r3, addr) \
    asm volatile("ldmatrix.sync.aligned.m8n8.x4.trans.shared.b16 {%0,%1,%2,%3}, [%4];" \
                 : "=r"(r0), "=r"(r1), "=r"(r2), "=r"(r3) : "r"(addr))

#define MMAH16816(c, a, b) \
    asm volatile("mma.sync.aligned.m16n8k16.row.col.f32.f16.f16.f32 " \
                 "{%0,%1,%2,%3}, {%4,%5,%6,%7}, {%8,%9}, {%0,%1,%2,%3};" \
                 : "+f"((c)[0]), "+f"((c)[1]), "+f"((c)[2]), "+f"((c)[3]) \
                 : "r"((a)[0]), "r"((a)[1]), "r"((a)[2]), "r"((a)[3]), \
                   "r"((b)[0]), "r"((b)[1]))

__device__ __forceinline__ uint32_t pack_h2(float lo, float hi) {
    __half2 t = __floats2half2_rn(lo, hi);
    return *(uint32_t*)&t;
}

// ============================================================================
// 1-pass fp16 GEMM core (A single, B single): 128x128 tile, BK=32,
// 2-tile stage, 2-stage pipeline, 2 CTA/SM.
// ============================================================================
#define GK_BK      32
#define GK_TILE_B  10240
#define GK_NIT     (DIM_ / GK_BK)
#define GS_STAGE_B (2 * GK_TILE_B)
#define GS_SMEM    (2 * GS_STAGE_B)     // 40960

__device__ __forceinline__ void gs_fill(uint32_t sbase,
    const __half* __restrict__ A, const __half* __restrict__ Bs,
    int rowBase, int colBase, int k0)
{
    const int tid = threadIdx.x;
#pragma unroll
    for (int i = 0; i < 4; i++) {
        int idx = tid + i * 256;
        int arr = idx >> 9;
        int rem = idx & 511;
        int row = rem >> 2;
        int ch  = rem & 3;
        uint32_t dst = sbase + (uint32_t)(arr * GK_TILE_B + row * 80 + ch * 16);
        const __half* src = (arr == 0) ? A : Bs;
        int grow = (arr == 0) ? (rowBase + row) : (colBase + row);
        CP_ASYNC16(dst, src + (size_t)grow * DIM_ + k0 + ch * 8);
    }
}

#define GS_MAINLOOP(A, Bs)                                                     \
    gs_fill(base, A, Bs, rowBase, colBase, 0);                                 \
    CP_COMMIT();                                                               \
    const uint32_t aRow = (uint32_t)(wm + (lane & 15));                        \
    const uint32_t bRow = (uint32_t)(wn + (lane & 15));                        \
    const uint32_t kHalf = (uint32_t)((lane >> 4) * 16);                       \
    for (int it = 0; it < GK_NIT; it++) {                                      \
        CP_WAIT(0);                                                            \
        __syncthreads();                                                       \
        if (it + 1 < GK_NIT)                                                   \
            gs_fill(base + (uint32_t)((it + 1) & 1) * GS_STAGE_B,              \
                    A, Bs, rowBase, colBase, (it + 1) * GK_BK);                \
        CP_COMMIT();                                                           \
        const uint32_t sb = base + (uint32_t)(it & 1) * GS_STAGE_B;            \
        _Pragma("unroll")                                                      \
        for (int ks = 0; ks < 2; ks++) {                                       \
            const uint32_t kcol = (uint32_t)(ks * 32) + kHalf;                 \
            uint32_t ah[4][4], bb[4][2];                                       \
            _Pragma("unroll")                                                  \
            for (int mi = 0; mi < 4; mi++) {                                   \
                uint32_t off = (aRow + mi * 16) * 80 + kcol;                   \
                LDSM_X4(ah[mi][0], ah[mi][1], ah[mi][2], ah[mi][3], sb + off); \
            }                                                                  \
            _Pragma("unroll")                                                  \
            for (int np = 0; np < 2; np++) {                                   \
                uint32_t off = GK_TILE_B + (bRow + np * 16) * 80 + kcol;       \
                uint32_t r0, r1, r2, r3;                                       \
                LDSM_X4(r0, r1, r2, r3, sb + off);                             \
                bb[2 * np][0] = r0; bb[2 * np][1] = r2;                        \
                bb[2 * np + 1][0] = r1; bb[2 * np + 1][1] = r3;                \
            }                                                                  \
            _Pragma("unroll")                                                  \
            for (int mi = 0; mi < 4; mi++)                                     \
                _Pragma("unroll")                                              \
                for (int ni = 0; ni < 4; ni++)                                 \
                    MMAH16816(acc[mi][ni], ah[mi], bb[ni]);                    \
        }                                                                      \
    }

// --------- QKV GEMM (1-pass): z=0 Q, z=1 K (rope, single fp16),
// ---------                    z=2 V (single fp16, no rope)
__global__ __launch_bounds__(256, 2)
void qkv_gemm(const __half* __restrict__ X,
              const __half* __restrict__ Bq, const __half* __restrict__ Bk,
              const __half* __restrict__ Bv,
              __half* __restrict__ Q, __half* __restrict__ K,
              __half* __restrict__ V,
              const float* __restrict__ fcos, const float* __restrict__ fsin)
{
    extern __shared__ char sm[];
    const uint32_t base = smem_u32(sm);
    const int lane = threadIdx.x & 31;
    const int wid  = threadIdx.x >> 5;
    const int rowBase = blockIdx.y * 128;
    const int colBase = blockIdx.x * 128;
    const int wm = (wid & 1) * 64;
    const int wn = (wid >> 1) * 32;
    const int z = blockIdx.z;

    const __half* Bs = (z == 0) ? Bq : (z == 1) ? Bk : Bv;
    __half* Out = (z == 0) ? Q : (z == 1) ? K : V;
    const bool dorope = (z < 2);

    float acc[4][4][4];
#pragma unroll
    for (int mi = 0; mi < 4; mi++)
#pragma unroll
        for (int ni = 0; ni < 4; ni++)
#pragma unroll
            for (int q = 0; q < 4; q++) acc[mi][ni][q] = 0.f;

    GS_MAINLOOP(X, Bs)

    const int r0 = rowBase + wm + (lane >> 2);
    const int c0 = colBase + wn + (lane & 3) * 2;
#pragma unroll
    for (int mi = 0; mi < 4; mi++) {
        int r  = r0 + mi * 16;
        int s1 = r & (S_ - 1);
        int s2 = (r + 8) & (S_ - 1);
#pragma unroll
        for (int ni = 0; ni < 4; ni++) {
            int c = c0 + ni * 8;
            float v0 = acc[mi][ni][0], v1 = acc[mi][ni][1];
            float v2 = acc[mi][ni][2], v3 = acc[mi][ni][3];
            if (dorope) {
                int i = (c & (D_ - 1)) >> 1;
                float c1 = fcos[s1 * 64 + i], n1 = fsin[s1 * 64 + i];
                float c2 = fcos[s2 * 64 + i], n2 = fsin[s2 * 64 + i];
                float t;
                t = v0 * c1 - v1 * n1; v1 = v0 * n1 + v1 * c1; v0 = t;
                t = v2 * c2 - v3 * n2; v3 = v2 * n2 + v3 * c2; v2 = t;
            }
            *(__half2*)(Out + (size_t)r * DIM_ + c) = __floats2half2_rn(v0, v1);
            *(__half2*)(Out + (size_t)(r + 8) * DIM_ + c) = __floats2half2_rn(v2, v3);
        }
    }
}

// --------- out GEMM (1-pass): fp32 C ---------
__global__ __launch_bounds__(256, 2)
void o_gemm(const __half* __restrict__ A, const __half* __restrict__ Bs,
            float* __restrict__ C)
{
    extern __shared__ char sm[];
    const uint32_t base = smem_u32(sm);
    const int lane = threadIdx.x & 31;
    const int wid  = threadIdx.x >> 5;
    const int rowBase = blockIdx.y * 128;
    const int colBase = blockIdx.x * 128;
    const int wm = (wid & 1) * 64;
    const int wn = (wid >> 1) * 32;

    float acc[4][4][4];
#pragma unroll
    for (int mi = 0; mi < 4; mi++)
#pragma unroll
        for (int ni = 0; ni < 4; ni++)
#pragma unroll
            for (int q = 0; q < 4; q++) acc[mi][ni][q] = 0.f;

    GS_MAINLOOP(A, Bs)

    const int r0 = rowBase + wm + (lane >> 2);
    const int c0 = colBase + wn + (lane & 3) * 2;
#pragma unroll
    for (int mi = 0; mi < 4; mi++)
#pragma unroll
        for (int ni = 0; ni < 4; ni++) {
            float* p = C + (size_t)(r0 + mi * 16) * DIM_ + c0 + ni * 8;
            *(float2*)p = make_float2(acc[mi][ni][0], acc[mi][ni][1]);
            *(float2*)(p + 8 * DIM_) = make_float2(acc[mi][ni][2], acc[mi][ni][3]);
        }
}

// ============================================================================
// split_all: y=0..4 -> single fp16 (x, wq, wk, wv, wo)
// ============================================================================
__global__ void split_all(const float* __restrict__ x,  const float* __restrict__ wq,
                          const float* __restrict__ wk, const float* __restrict__ wv,
                          const float* __restrict__ wo,
                          __half* x16, __half* wq16, __half* wk16,
                          __half* wv16, __half* wo16)
{
    size_t i = (size_t)blockIdx.x * blockDim.x + threadIdx.x;
    const int y = blockIdx.y;
    const float* src = (y == 0) ? x : (y == 1) ? wq : (y == 2) ? wk
                     : (y == 3) ? wv : wo;
    __half* dst = (y == 0) ? x16 : (y == 1) ? wq16 : (y == 2) ? wk16
                : (y == 3) ? wv16 : wo16;
    float4 v = ((const float4*)src)[i];
    ((__half2*)dst)[2 * i]     = __floats2half2_rn(v.x, v.y);
    ((__half2*)dst)[2 * i + 1] = __floats2half2_rn(v.z, v.w);
}

// ============================================================================
// adapter GEMV (fp32)
// ============================================================================
__global__ __launch_bounds__(256)
void adapter_gemv(const float* __restrict__ A, const float* __restrict__ W,
                  float* __restrict__ out)
{
    int warp = (blockIdx.x * blockDim.x + threadIdx.x) >> 5;
    int lane = threadIdx.x & 31;
    int e0 = warp * 4;

    float acc[ADL_][4];
#pragma unroll
    for (int l = 0; l < ADL_; l++)
#pragma unroll
        for (int j = 0; j < 4; j++) acc[l][j] = 0.f;

    for (int d = lane * 4; d < DIM_; d += 128) {
        float4 w4[4];
#pragma unroll
        for (int j = 0; j < 4; j++)
            w4[j] = *(const float4*)(W + (size_t)(e0 + j) * DIM_ + d);
#pragma unroll
        for (int l = 0; l < ADL_; l++) {
            float4 a4 = *(const float4*)(A + (size_t)l * DIM_ + d);
#pragma unroll
            for (int j = 0; j < 4; j++) {
                acc[l][j] = fmaf(a4.x, w4[j].x, acc[l][j]);
                acc[l][j] = fmaf(a4.y, w4[j].y, acc[l][j]);
                acc[l][j] = fmaf(a4.z, w4[j].z, acc[l][j]);
                acc[l][j] = fmaf(a4.w, w4[j].w, acc[l][j]);
            }
        }
    }
#pragma unroll
    for (int l = 0; l < ADL_; l++)
#pragma unroll
        for (int j = 0; j < 4; j++) {
            float v = acc[l][j];
#pragma unroll
            for (int off = 16; off; off >>= 1)
                v += __shfl_xor_sync(0xffffffffu, v, off);
            if (lane == 0) out[l * DIM_ + e0 + j] = v;
        }
}

// ============================================================================
// Flash attention: all-fp16 (Q, K, V, P single), QK 1 pass, PV 1 pass.
// 64 q-rows/CTA, 128 threads, double-buffered KV, 2 CTA/SM.
// ============================================================================
#define FRSTR   272
#define FQ_TILE (64 * FRSTR)             // 17408
#define FK_TILE (64 * FRSTR)
#define FSTAGE  (2 * FK_TILE)            // 34816 (K, V)
#define FLASH_SMEM (FQ_TILE + 2 * FSTAGE)    // 87040

__device__ __forceinline__ void fkv_fill(uint32_t sdst,
    const __half* __restrict__ K, const __half* __restrict__ V,
    int b, int h, int kv0)
{
    const int tid = threadIdx.x;
    const size_t gbase = ((size_t)(b * S_) + kv0) * DIM_ + h * D_;
#pragma unroll
    for (int i = 0; i < 16; i++) {
        int idx = tid + i * 128;
        int arr = idx >> 10;
        int rem = idx & 1023;
        int row = rem >> 4;
        int ch  = rem & 15;
        uint32_t dst = sdst + arr * FK_TILE + row * FRSTR + ch * 16;
        size_t src = gbase + (size_t)row * DIM_ + ch * 8;
        if (arr == 0) CP_ASYNC16(dst, K + src);
        else          CP_ASYNC16(dst, V + src);
    }
}

__global__ __launch_bounds__(128, 2)
void flash_mma(const __half* __restrict__ Q_g,
               const __half* __restrict__ K_g, const __half* __restrict__ V_g,
               const float* __restrict__ aK, const float* __restrict__ aV,
               const float* __restrict__ gate,
               __half* __restrict__ O)
{
    extern __shared__ char sm[];
    const uint32_t base = smem_u32(sm);
    const int tid  = threadIdx.x;
    const int wid  = tid >> 5;
    const int lane = tid & 31;
    const int qt = (int)gridDim.x - 1 - (int)blockIdx.x;
    const int h = blockIdx.y, b = blockIdx.z;
    const int nkt = qt + 1;

    const uint32_t sQ  = base;
    const uint32_t sKV = base + FQ_TILE;

    {
        size_t gq = ((size_t)(b * S_) + qt * 64) * DIM_ + h * D_;
#pragma unroll
        for (int i = 0; i < 8; i++) {
            int idx = tid + i * 128;
            int row = idx >> 4, ch = idx & 15;
            CP_ASYNC16(sQ + row * FRSTR + ch * 16,
                       Q_g + gq + (size_t)row * DIM_ + ch * 8);
        }
    }
    fkv_fill(sKV, K_g, V_g, b, h, 0);
    CP_COMMIT();

    const int q0  = qt * 64 + wid * 16;
    const int qg0 = q0 + (lane >> 2);
    const int qg1 = qg0 + 8;
    const float scl = 0.08838834764831845f;

    float m0 = -1e30f, m1 = -1e30f, l0 = 0.f, l1 = 0.f;
    float o[16][4];
#pragma unroll
    for (int d = 0; d < 16; d++)
#pragma unroll
        for (int q = 0; q < 4; q++) o[d][q] = 0.f;

    const uint32_t kh16 = (uint32_t)((lane >> 4) * 16);

    for (int kt = 0; kt < nkt; kt++) {
        if (kt + 1 < nkt) {
            fkv_fill(sKV + (uint32_t)((kt + 1) & 1) * FSTAGE,
                     K_g, V_g, b, h, (kt + 1) * 64);
        }
        CP_COMMIT();
        CP_WAIT(1);
        __syncthreads();

        const uint32_t st = sKV + (uint32_t)(kt & 1) * FSTAGE;
        const int kv0 = kt * 64;

        // ---- S = Q K^T (1 pass) ----
        float sa[8][4];
#pragma unroll
        for (int n8 = 0; n8 < 8; n8++)
#pragma unroll
            for (int q = 0; q < 4; q++) sa[n8][q] = 0.f;

        const uint32_t qrow = (uint32_t)(wid * 16 + (lane & 15));
        const uint32_t klrow = (uint32_t)(lane & 15);

#pragma unroll
        for (int ch = 0; ch < 8; ch++) {
            uint32_t qa = sQ + qrow * FRSTR + ch * 32 + kh16;
            uint32_t qh[4];
            LDSM_X4(qh[0], qh[1], qh[2], qh[3], qa);
            uint32_t kb[8][2];
#pragma unroll
            for (int nb = 0; nb < 4; nb++) {
                uint32_t ka = st + (klrow + nb * 16) * FRSTR + ch * 32 + kh16;
                uint32_t r0, r1, r2, r3;
                LDSM_X4(r0, r1, r2, r3, ka);
                kb[2 * nb][0] = r0; kb[2 * nb][1] = r2;
                kb[2 * nb + 1][0] = r1; kb[2 * nb + 1][1] = r3;
            }
#pragma unroll
            for (int n8 = 0; n8 < 8; n8++) MMAH16816(sa[n8], qh, kb[n8]);
        }

        // ---- mask + online softmax ----
        float rmax0 = -1e30f, rmax1 = -1e30f;
        const int kvb = kv0 + (lane & 3) * 2;
#pragma unroll
        for (int n8 = 0; n8 < 8; n8++) {
            int kvc = kvb + n8 * 8;
            float s0 = sa[n8][0] * scl, s1 = sa[n8][1] * scl;
            float s2 = sa[n8][2] * scl, s3 = sa[n8][3] * scl;
            if (kvc     > qg0) s0 = -1e30f;
            if (kvc + 1 > qg0) s1 = -1e30f;
            if (kvc     > qg1) s2 = -1e30f;
            if (kvc + 1 > qg1) s3 = -1e30f;
            sa[n8][0] = s0; sa[n8][1] = s1; sa[n8][2] = s2; sa[n8][3] = s3;
            rmax0 = fmaxf(rmax0, fmaxf(s0, s1));
            rmax1 = fmaxf(rmax1, fmaxf(s2, s3));
        }
        rmax0 = fmaxf(rmax0, __shfl_xor_sync(0xffffffffu, rmax0, 1));
        rmax0 = fmaxf(rmax0, __shfl_xor_sync(0xffffffffu, rmax0, 2));
        rmax1 = fmaxf(rmax1, __shfl_xor_sync(0xffffffffu, rmax1, 1));
        rmax1 = fmaxf(rmax1, __shfl_xor_sync(0xffffffffu, rmax1, 2));

        float mn0 = fmaxf(m0, rmax0), mn1 = fmaxf(m1, rmax1);
        float sc0 = __expf(m0 - mn0), sc1 = __expf(m1 - mn1);
        m0 = mn0; m1 = mn1;

        uint32_t ph[16];
        float rs0 = 0.f, rs1 = 0.f;
#pragma unroll
        for (int n8 = 0; n8 < 8; n8++) {
            float p0 = __expf(sa[n8][0] - mn0);
            float p1 = __expf(sa[n8][1] - mn0);
            float p2 = __expf(sa[n8][2] - mn1);
            float p3 = __expf(sa[n8][3] - mn1);
            rs0 += p0 + p1; rs1 += p2 + p3;
            ph[2 * n8]     = pack_h2(p0, p1);
            ph[2 * n8 + 1] = pack_h2(p2, p3);
        }
        rs0 += __shfl_xor_sync(0xffffffffu, rs0, 1);
        rs0 += __shfl_xor_sync(0xffffffffu, rs0, 2);
        rs1 += __shfl_xor_sync(0xffffffffu, rs1, 1);
        rs1 += __shfl_xor_sync(0xffffffffu, rs1, 2);
        l0 = l0 * sc0 + rs0;
        l1 = l1 * sc1 + rs1;

#pragma unroll
        for (int d = 0; d < 16; d++) {
            o[d][0] *= sc0; o[d][1] *= sc0;
            o[d][2] *= sc1; o[d][3] *= sc1;
        }

        // ---- O += P V (1 pass) ----
#pragma unroll
        for (int j = 0; j < 4; j++) {
            uint32_t ah[4] = {ph[4*j], ph[4*j+1], ph[4*j+2], ph[4*j+3]};
#pragma unroll
            for (int half = 0; half < 2; half++) {
                uint32_t vv[8][2];
#pragma unroll
                for (int k = 0; k < 4; k++) {
                    int nb = half * 4 + k;
                    uint32_t va = st + FK_TILE +
                                  (uint32_t)(j * 16 + (lane & 15)) * FRSTR +
                                  nb * 32 + kh16;
                    uint32_t r0, r1, r2, r3;
                    LDSM_X4_T(r0, r1, r2, r3, va);
                    vv[2 * k][0] = r0; vv[2 * k][1] = r1;
                    vv[2 * k + 1][0] = r2; vv[2 * k + 1][1] = r3;
                }
                const int ob = half * 8;
#pragma unroll
                for (int n = 0; n < 8; n++) MMAH16816(o[ob + n], ah, vv[n]);
            }
        }
        __syncthreads();
    }

    // ---- epilogue: adapter attention, single-fp16 output ----
    float* aKs = (float*)(sm + FQ_TILE);
    float* aVs = aKs + ADL_ * D_;
    for (int idx = tid; idx < ADL_ * D_; idx += 128) {
        int t = idx >> 7, cc = idx & (D_ - 1);
        aKs[idx] = aK[t * DIM_ + h * D_ + cc];
        aVs[idx] = aV[t * DIM_ + h * D_ + cc];
    }
    __syncthreads();

    const float g = tanhf(gate[h]);
    const float inv0 = 1.0f / l0, inv1 = 1.0f / l1;
    const int ccb = (lane & 3) * 2;

#pragma unroll
    for (int rr = 0; rr < 2; rr++) {
        const int lr = wid * 16 + (lane >> 2) + rr * 8;
        const float inv = rr ? inv1 : inv0;
        const size_t rowg = (size_t)(b * S_) + qt * 64 + lr;

        float qv[32];
#pragma unroll
        for (int d = 0; d < 16; d++) {
            int cc = d * 8 + ccb;
            __half2 hh = *(__half2*)(sm + lr * FRSTR + cc * 2);
            qv[2 * d]     = __half2float(hh.x);
            qv[2 * d + 1] = __half2float(hh.y);
        }
        float sc[ADL_];
#pragma unroll
        for (int t = 0; t < ADL_; t++) {
            float p = 0.f;
#pragma unroll
            for (int d = 0; d < 16; d++) {
                int cc = d * 8 + ccb;
                p = fmaf(qv[2 * d],     aKs[t * D_ + cc],     p);
                p = fmaf(qv[2 * d + 1], aKs[t * D_ + cc + 1], p);
            }
            p += __shfl_xor_sync(0xffffffffu, p, 1);
            p += __shfl_xor_sync(0xffffffffu, p, 2);
            sc[t] = p * scl;
        }
        float mx = sc[0];
#pragma unroll
        for (int t = 1; t < ADL_; t++) mx = fmaxf(mx, sc[t]);
        float sum = 0.f;
#pragma unroll
        for (int t = 0; t < ADL_; t++) { sc[t] = __expf(sc[t] - mx); sum += sc[t]; }
        float isum = g / sum;
#pragma unroll
        for (int t = 0; t < ADL_; t++) sc[t] *= isum;

#pragma unroll
        for (int d = 0; d < 16; d++) {
            int cc = d * 8 + ccb;
            float a0 = 0.f, a1 = 0.f;
#pragma unroll
            for (int t = 0; t < ADL_; t++) {
                a0 = fmaf(sc[t], aVs[t * D_ + cc],     a0);
                a1 = fmaf(sc[t], aVs[t * D_ + cc + 1], a1);
            }
            float o0 = o[d][rr * 2]     * inv + a0;
            float o1 = o[d][rr * 2 + 1] * inv + a1;
            *(__half2*)(O + rowg * DIM_ + h * D_ + cc) =
                __floats2half2_rn(o0, o1);
        }
    }
}

// ============================================================================
// launch
// ============================================================================
extern "C" void kernel_launch(void* const* d_in, const int* in_sizes, int n_in,
                              void* d_out, int out_size)
{
    const float* x       = (const float*)d_in[0];
    const float* wq      = (const float*)d_in[1];
    const float* wk      = (const float*)d_in[2];
    const float* wv      = (const float*)d_in[3];
    const float* wo      = (const float*)d_in[4];
    const float* gate    = (const float*)d_in[5];
    const float* adapter = (const float*)d_in[6];
    const float* fcos    = (const float*)d_in[7];
    const float* fsin    = (const float*)d_in[8];
    float* out = (float*)d_out;

    float *aKp, *aVp;
    cudaGetSymbolAddress((void**)&aKp, g_aK);
    cudaGetSymbolAddress((void**)&aVp, g_aV);

    __half *x16, *wq16, *wk16, *wv16, *wo16;
    __half *q16, *k16, *v16, *o16;
    cudaGetSymbolAddress((void**)&x16,  g_x16);
    cudaGetSymbolAddress((void**)&wq16, g_wq16); cudaGetSymbolAddress((void**)&wk16, g_wk16);
    cudaGetSymbolAddress((void**)&wv16, g_wv16); cudaGetSymbolAddress((void**)&wo16, g_wo16);
    cudaGetSymbolAddress((void**)&q16,  g_q16);  cudaGetSymbolAddress((void**)&k16,  g_k16);
    cudaGetSymbolAddress((void**)&v16,  g_v16);
    cudaGetSymbolAddress((void**)&o16,  g_o16);

    cudaFuncSetAttribute(qkv_gemm,
                         cudaFuncAttributeMaxDynamicSharedMemorySize, GS_SMEM);
    cudaFuncSetAttribute(o_gemm,
                         cudaFuncAttributeMaxDynamicSharedMemorySize, GS_SMEM);
    cudaFuncSetAttribute(flash_mma,
                         cudaFuncAttributeMaxDynamicSharedMemorySize, FLASH_SMEM);

    split_all<<<dim3(NELEM / 4 / 256, 5), 256>>>(x, wq, wk, wv, wo,
        x16, wq16, wk16, wv16, wo16);

    adapter_gemv<<<128, 256>>>(adapter, wk, aKp);
    adapter_gemv<<<128, 256>>>(adapter, wv, aVp);

    qkv_gemm<<<dim3(DIM_ / 128, MROWS / 128, 3), 256, GS_SMEM>>>(
        x16, wq16, wk16, wv16, q16, k16, v16, fcos, fsin);

    flash_mma<<<dim3(S_ / 64, H_, B_), 128, FLASH_SMEM>>>(
        q16, k16, v16, aKp, aVp, gate, o16);

    o_gemm<<<dim3(DIM_ / 128, MROWS / 128), 256, GS_SMEM>>>(
        o16, wo16, out);
}